// round 3
// baseline (speedup 1.0000x reference)
#include <cuda_runtime.h>
#include <math.h>

// ---------------- problem constants ----------------
#define BATCH   32
#define IMGSZ   224
#define PATCH   16
#define CC      384
#define DD      12
#define TT      8
#define HIDN    1536
#define NCLS    1000
#define GRIDW   14
#define NTOK    (BATCH*GRIDW*GRIDW)   // 6272
#define KI2C    (PATCH*PATCH*3)       // 768

// ---------------- scratch (no allocations allowed) ----------------
__device__ float g_h   [(size_t)NTOK*CC];     // residual stream
__device__ float g_z   [(size_t)NTOK*CC];     // LN output
__device__ float g_u   [(size_t)NTOK*CC];     // input proj
__device__ float g_gate[(size_t)NTOK*CC];     // sigmoid gate
__device__ float g_hid [(size_t)NTOK*HIDN];   // MLP hidden
__device__ float g_i2c [(size_t)NTOK*KI2C];   // im2col patches
__device__ float g_pool[(size_t)BATCH*CC];    // pooled features

// ---------------- helpers ----------------
__device__ __forceinline__ float gelu_f(float x) {
    float x3 = x * x * x;
    float t  = tanhf(0.7978845608028654f * (x + 0.044715f * x3));
    return 0.5f * x * (1.0f + t);
}
__device__ __forceinline__ float sigmoid_f(float x) {
    return 1.0f / (1.0f + expf(-x));
}

// ---------------- im2col for patch embed ----------------
__global__ void im2col_kernel(const float* __restrict__ x) {
    int token = blockIdx.x;                 // 0..6271
    int b  = token / (GRIDW*GRIDW);
    int p  = token % (GRIDW*GRIDW);
    int gy = p / GRIDW, gx = p % GRIDW;
    for (int k = threadIdx.x; k < KI2C; k += blockDim.x) {
        int py = k / 48;          // patch row
        int r  = k % 48;          // px*3 + ci
        size_t src = ((size_t)(b*IMGSZ + gy*PATCH + py) * IMGSZ + gx*PATCH) * 3 + r;
        g_i2c[(size_t)token*KI2C + k] = x[src];
    }
}

// ---------------- SGEMM: C[N,M] = epi(A[N,K] @ W[K,M] + bias) ----------------
// BM=128 (token rows), BN=64 (out cols), BK=16, 256 threads, 8x4 microtile.
// EPI: 0 = +bias, 1 = sigmoid, 2 = gelu, 3 = residual add into C, 4 = +bias+pos
template<int EPI>
__global__ __launch_bounds__(256)
void sgemm_kernel(const float* __restrict__ A, const float* __restrict__ W,
                  const float* __restrict__ bias, float* __restrict__ C,
                  int K, int M, const float* __restrict__ extra) {
    __shared__ float As[16][132];   // [k][row], padded (132*4 % 16 == 0)
    __shared__ float Bs[16][64];    // [k][col]

    const int tid = threadIdx.x;
    const int tx = tid % 16;        // col group (4 cols)
    const int ty = tid / 16;        // row group (8 rows)
    const int bn = blockIdx.x;      // M tile
    const int bm = blockIdx.y;      // N tile

    const float* Ab = A + (size_t)bm * 128 * K;
    const float* Wb = W + (size_t)bn * 64;

    const int a_row = tid >> 2;           // 0..63
    const int a_col = (tid & 3) * 4;      // 0,4,8,12
    const int b_row = tid >> 4;           // 0..15
    const int b_col = (tid & 15) * 4;     // 0..60

    float acc[8][4];
    #pragma unroll
    for (int i = 0; i < 8; i++)
        #pragma unroll
        for (int j = 0; j < 4; j++) acc[i][j] = 0.0f;

    for (int k0 = 0; k0 < K; k0 += 16) {
        #pragma unroll
        for (int h = 0; h < 2; h++) {
            int r = a_row + h * 64;
            float4 v = *reinterpret_cast<const float4*>(Ab + (size_t)r * K + k0 + a_col);
            As[a_col + 0][r] = v.x;
            As[a_col + 1][r] = v.y;
            As[a_col + 2][r] = v.z;
            As[a_col + 3][r] = v.w;
        }
        float4 w4 = *reinterpret_cast<const float4*>(Wb + (size_t)(k0 + b_row) * M + b_col);
        *reinterpret_cast<float4*>(&Bs[b_row][b_col]) = w4;
        __syncthreads();

        #pragma unroll
        for (int kk = 0; kk < 16; kk++) {
            float a[8], bfr[4];
            const float4* ap = reinterpret_cast<const float4*>(&As[kk][ty * 8]);
            float4 a0 = ap[0], a1 = ap[1];
            a[0]=a0.x; a[1]=a0.y; a[2]=a0.z; a[3]=a0.w;
            a[4]=a1.x; a[5]=a1.y; a[6]=a1.z; a[7]=a1.w;
            float4 b0 = *reinterpret_cast<const float4*>(&Bs[kk][tx * 4]);
            bfr[0]=b0.x; bfr[1]=b0.y; bfr[2]=b0.z; bfr[3]=b0.w;
            #pragma unroll
            for (int i = 0; i < 8; i++)
                #pragma unroll
                for (int j = 0; j < 4; j++)
                    acc[i][j] += a[i] * bfr[j];
        }
        __syncthreads();
    }

    const int col0 = bn * 64 + tx * 4;
    float4 bv = *reinterpret_cast<const float4*>(bias + col0);
    #pragma unroll
    for (int i = 0; i < 8; i++) {
        int row = bm * 128 + ty * 8 + i;
        float4 o;
        o.x = acc[i][0] + bv.x;
        o.y = acc[i][1] + bv.y;
        o.z = acc[i][2] + bv.z;
        o.w = acc[i][3] + bv.w;
        float* cp = C + (size_t)row * M + col0;
        if (EPI == 1) { o.x = sigmoid_f(o.x); o.y = sigmoid_f(o.y); o.z = sigmoid_f(o.z); o.w = sigmoid_f(o.w); }
        if (EPI == 2) { o.x = gelu_f(o.x);    o.y = gelu_f(o.y);    o.z = gelu_f(o.z);    o.w = gelu_f(o.w); }
        if (EPI == 3) {
            float4 r = *reinterpret_cast<const float4*>(cp);
            o.x += r.x; o.y += r.y; o.z += r.z; o.w += r.w;
        }
        if (EPI == 4) {
            int p = row % (GRIDW*GRIDW);
            float4 pv = *reinterpret_cast<const float4*>(extra + (size_t)p * CC + col0);
            o.x += pv.x; o.y += pv.y; o.z += pv.z; o.w += pv.w;
        }
        *reinterpret_cast<float4*>(cp) = o;
    }
}

// ---------------- LayerNorm: g_h -> g_z ----------------
__global__ __launch_bounds__(128)
void ln_kernel(const float* __restrict__ gamma, const float* __restrict__ beta) {
    int row = blockIdx.x;
    int t = threadIdx.x;
    const float* xr = g_h + (size_t)row * CC;
    float v0 = xr[t], v1 = xr[t + 128], v2 = xr[t + 256];
    float s = v0 + v1 + v2;
    float q = v0 * v0 + v1 * v1 + v2 * v2;
    #pragma unroll
    for (int o = 16; o; o >>= 1) {
        s += __shfl_down_sync(0xffffffffu, s, o);
        q += __shfl_down_sync(0xffffffffu, q, o);
    }
    __shared__ float ss[4], sq[4];
    __shared__ float mean_s, rs_s;
    if ((t & 31) == 0) { ss[t >> 5] = s; sq[t >> 5] = q; }
    __syncthreads();
    if (t == 0) {
        float S = ss[0] + ss[1] + ss[2] + ss[3];
        float Q = sq[0] + sq[1] + sq[2] + sq[3];
        float m = S * (1.0f / CC);
        float var = Q * (1.0f / CC) - m * m;
        mean_s = m;
        rs_s = rsqrtf(var + 1e-6f);
    }
    __syncthreads();
    float m = mean_s, r = rs_s;
    float* yr = g_z + (size_t)row * CC;
    yr[t]       = (v0 - m) * r * gamma[t]       + beta[t];
    yr[t + 128] = (v1 - m) * r * gamma[t + 128] + beta[t + 128];
    yr[t + 256] = (v2 - m) * r * gamma[t + 256] + beta[t + 256];
}

// ---------------- gated depthwise-conv recurrence ----------------
// grid: BATCH * (CC/32) blocks; 196 threads (one per spatial position).
// s_1 = (1-g)*u ; then 7 steps of s = g*dwconv3x3(s) + (1-g)*u ; h += s.
__global__ __launch_bounds__(196)
void recur_kernel(const float* __restrict__ KD) {
    __shared__ float s[32][256];    // 16x16 halo layout per channel
    __shared__ float kds[9][32];

    int blk = blockIdx.x;
    int b  = blk / (CC / 32);
    int cg = blk % (CC / 32);
    int tid = threadIdx.x;          // 0..195
    int y = tid / GRIDW, x = tid % GRIDW;

    for (int i = tid; i < 32 * 256; i += 196) ((float*)s)[i] = 0.0f;
    for (int i = tid; i < 288; i += 196)      // FIX: 288 > blockDim, must grid-stride
        ((float*)kds)[i] = KD[(i >> 5) * CC + cg * 32 + (i & 31)];

    size_t base = ((size_t)(b * (GRIDW*GRIDW) + tid)) * CC + cg * 32;
    float gg[32], u1[32], ns[32];
    #pragma unroll
    for (int c = 0; c < 32; c += 4) {
        float4 gv = *reinterpret_cast<const float4*>(g_gate + base + c);
        float4 uv = *reinterpret_cast<const float4*>(g_u + base + c);
        gg[c+0]=gv.x; gg[c+1]=gv.y; gg[c+2]=gv.z; gg[c+3]=gv.w;
        u1[c+0]=(1.0f-gv.x)*uv.x; u1[c+1]=(1.0f-gv.y)*uv.y;
        u1[c+2]=(1.0f-gv.z)*uv.z; u1[c+3]=(1.0f-gv.w)*uv.w;
    }
    __syncthreads();

    const int ip = (y + 1) * 16 + (x + 1);
    #pragma unroll
    for (int c = 0; c < 32; c++) s[c][ip] = u1[c];
    __syncthreads();

    for (int step = 0; step < TT - 1; step++) {
        #pragma unroll
        for (int c = 0; c < 32; c++) {
            const float* sc = s[c];
            float acc = kds[0][c]*sc[ip-17] + kds[1][c]*sc[ip-16] + kds[2][c]*sc[ip-15]
                      + kds[3][c]*sc[ip-1]  + kds[4][c]*sc[ip]    + kds[5][c]*sc[ip+1]
                      + kds[6][c]*sc[ip+15] + kds[7][c]*sc[ip+16] + kds[8][c]*sc[ip+17];
            ns[c] = gg[c] * acc + u1[c];
        }
        __syncthreads();
        #pragma unroll
        for (int c = 0; c < 32; c++) s[c][ip] = ns[c];
        __syncthreads();
    }

    #pragma unroll
    for (int c = 0; c < 32; c++) g_h[base + c] += s[c][ip];
}

// ---------------- final max pool over spatial ----------------
__global__ void maxpool_kernel() {
    int b = blockIdx.x, c = threadIdx.x;
    const float* zb = g_z + (size_t)b * (GRIDW*GRIDW) * CC + c;
    float m = -INFINITY;
    #pragma unroll 4
    for (int p = 0; p < GRIDW*GRIDW; p++) m = fmaxf(m, zb[(size_t)p * CC]);
    g_pool[b * CC + c] = m;
}

// ---------------- classification head ----------------
__global__ void head_kernel(const float* __restrict__ HW, const float* __restrict__ HB,
                            float* __restrict__ out) {
    int idx = blockIdx.x * blockDim.x + threadIdx.x;
    if (idx >= BATCH * NCLS) return;
    int b = idx / NCLS, cls = idx % NCLS;
    const float* pb = g_pool + b * CC;
    float acc = HB[cls];
    #pragma unroll 4
    for (int k = 0; k < CC; k++) acc += pb[k] * HW[(size_t)k * NCLS + cls];
    out[idx] = acc;
}

// ---------------- host orchestration ----------------
extern "C" void kernel_launch(void* const* d_in, const int* in_sizes, int n_in,
                              void* d_out, int out_size) {
    const float* x       = (const float*)d_in[0];
    const float* patch_w = (const float*)d_in[1];
    const float* patch_b = (const float*)d_in[2];
    const float* pos     = (const float*)d_in[3];
    const float* ln1_s   = (const float*)d_in[4];
    const float* ln1_b   = (const float*)d_in[5];
    const float* w_in    = (const float*)d_in[6];
    const float* b_in    = (const float*)d_in[7];
    const float* w_g     = (const float*)d_in[8];
    const float* b_g     = (const float*)d_in[9];
    const float* k_dw    = (const float*)d_in[10];
    const float* ln2_s   = (const float*)d_in[11];
    const float* ln2_b   = (const float*)d_in[12];
    const float* w1      = (const float*)d_in[13];
    const float* b1      = (const float*)d_in[14];
    const float* w2      = (const float*)d_in[15];
    const float* b2      = (const float*)d_in[16];
    const float* lnf_s   = (const float*)d_in[17];
    const float* lnf_b   = (const float*)d_in[18];
    const float* head_w  = (const float*)d_in[19];
    const float* head_b  = (const float*)d_in[20];
    float* out = (float*)d_out;

    float *ph, *pz, *pu, *pg, *phid, *pi2c;
    cudaGetSymbolAddress((void**)&ph,   g_h);
    cudaGetSymbolAddress((void**)&pz,   g_z);
    cudaGetSymbolAddress((void**)&pu,   g_u);
    cudaGetSymbolAddress((void**)&pg,   g_gate);
    cudaGetSymbolAddress((void**)&phid, g_hid);
    cudaGetSymbolAddress((void**)&pi2c, g_i2c);

    const dim3 gemm_blk(256);
    const int NT = NTOK / 128;      // 49

    // patch embed: im2col + GEMM(+bias+pos) -> g_h
    im2col_kernel<<<NTOK, 256>>>(x);
    sgemm_kernel<4><<<dim3(CC/64, NT), gemm_blk>>>(pi2c, patch_w, patch_b, ph, KI2C, CC, pos);

    for (int d = 0; d < DD; d++) {
        // LN1: h -> z
        ln_kernel<<<NTOK, 128>>>(ln1_s + d*CC, ln1_b + d*CC);
        // u = z@Wi + bi ; g = sigmoid(z@Wg + bg)
        sgemm_kernel<0><<<dim3(CC/64, NT), gemm_blk>>>(pz, w_in + (size_t)d*CC*CC, b_in + d*CC, pu, CC, CC, nullptr);
        sgemm_kernel<1><<<dim3(CC/64, NT), gemm_blk>>>(pz, w_g  + (size_t)d*CC*CC, b_g  + d*CC, pg, CC, CC, nullptr);
        // gated recurrence; h += s
        recur_kernel<<<BATCH * (CC/32), 196>>>(k_dw + (size_t)d*9*CC);
        // LN2: h -> z
        ln_kernel<<<NTOK, 128>>>(ln2_s + d*CC, ln2_b + d*CC);
        // MLP: hid = gelu(z@W1+b1) ; h += hid@W2+b2
        sgemm_kernel<2><<<dim3(HIDN/64, NT), gemm_blk>>>(pz,   w1 + (size_t)d*CC*HIDN, b1 + d*HIDN, phid, CC,   HIDN, nullptr);
        sgemm_kernel<3><<<dim3(CC/64,   NT), gemm_blk>>>(phid, w2 + (size_t)d*HIDN*CC, b2 + d*CC,   ph,   HIDN, CC,   nullptr);
    }

    // final LN -> z, max pool, head
    ln_kernel<<<NTOK, 128>>>(lnf_s, lnf_b);
    maxpool_kernel<<<BATCH, CC>>>();
    head_kernel<<<(BATCH*NCLS + 255) / 256, 256>>>(head_w, head_b, out);
}

// round 6
// speedup vs baseline: 1.6684x; 1.6684x over previous
#include <cuda_runtime.h>
#include <cuda_bf16.h>
#include <math.h>
#include <stdint.h>

// ---------------- problem constants ----------------
#define BATCH   32
#define IMGSZ   224
#define PATCH   16
#define CC      384
#define DD      12
#define TT      8
#define HIDN    1536
#define NCLS    1000
#define GRIDW   14
#define NTOK    (BATCH*GRIDW*GRIDW)   // 6272
#define KI2C    (PATCH*PATCH*3)       // 768

// weight scratch offsets (transposed [M,K] bf16 hi/lo)
#define OFF_PATCH   0
#define LEN_PATCH   (384*768)
#define OFF_BLK0    LEN_PATCH
#define LEN_CXC     (CC*CC)            // 147456
#define LEN_W1      (HIDN*CC)          // 589824
#define PER_BLK     (2*LEN_CXC + 2*LEN_W1)   // 1474560
#define WT_TOTAL    (OFF_BLK0 + DD*PER_BLK)  // 17989632

// ---------------- scratch (no allocations allowed) ----------------
__device__ float g_h   [(size_t)NTOK*CC];
__device__ float g_z   [(size_t)NTOK*CC];
__device__ float g_u   [(size_t)NTOK*CC];
__device__ float g_gate[(size_t)NTOK*CC];
__device__ float g_pool[(size_t)BATCH*CC];
__device__ __nv_bfloat16 g_za_hi [(size_t)NTOK*KI2C];
__device__ __nv_bfloat16 g_za_lo [(size_t)NTOK*KI2C];
__device__ __nv_bfloat16 g_hid_hi[(size_t)NTOK*HIDN];
__device__ __nv_bfloat16 g_hid_lo[(size_t)NTOK*HIDN];
__device__ __nv_bfloat16 g_wt_hi [(size_t)WT_TOTAL];
__device__ __nv_bfloat16 g_wt_lo [(size_t)WT_TOTAL];

// ---------------- small helpers ----------------
__device__ __forceinline__ float gelu_f(float x) {
    float x3 = x * x * x;
    float t  = tanhf(0.7978845608028654f * (x + 0.044715f * x3));
    return 0.5f * x * (1.0f + t);
}
__device__ __forceinline__ float sigmoid_f(float x) { return 1.0f / (1.0f + expf(-x)); }

__device__ __forceinline__ uint32_t smem_u32(const void* p) {
    uint32_t a;
    asm("{ .reg .u64 t; cvta.to.shared.u64 t, %1; cvt.u32.u64 %0, t; }" : "=r"(a) : "l"(p));
    return a;
}
__device__ __forceinline__ uint32_t pack_bf2(float a, float b) {
    uint32_t u; asm("cvt.rn.bf16x2.f32 %0, %1, %2;" : "=r"(u) : "f"(b), "f"(a)); return u;
}
__device__ __forceinline__ void split_bf(float v, __nv_bfloat16& hi, __nv_bfloat16& lo) {
    hi = __float2bfloat16(v);
    lo = __float2bfloat16(v - __bfloat162float(hi));
}

#define CP16(dst, src)      asm volatile("cp.async.cg.shared.global [%0], [%1], 16;" :: "r"(dst), "l"(src))
#define CP_COMMIT()         asm volatile("cp.async.commit_group;" ::: "memory")

__device__ __forceinline__ void ldm4(uint32_t* r, uint32_t addr) {
    asm volatile("ldmatrix.sync.aligned.m8n8.x4.shared.b16 {%0,%1,%2,%3}, [%4];"
                 : "=r"(r[0]), "=r"(r[1]), "=r"(r[2]), "=r"(r[3]) : "r"(addr));
}
__device__ __forceinline__ void mma16816(float* c, const uint32_t* a, const uint32_t* b) {
    asm volatile("mma.sync.aligned.m16n8k16.row.col.f32.bf16.bf16.f32 "
                 "{%0,%1,%2,%3}, {%4,%5,%6,%7}, {%8,%9}, {%0,%1,%2,%3};"
                 : "+f"(c[0]), "+f"(c[1]), "+f"(c[2]), "+f"(c[3])
                 : "r"(a[0]), "r"(a[1]), "r"(a[2]), "r"(a[3]), "r"(b[0]), "r"(b[1]));
}

// ---------------- weight convert+transpose: fp32 [K,M] -> bf16 hi/lo [M,K] ----------------
__global__ void convert_w_kernel(const float* __restrict__ patch_w,
                                 const float* __restrict__ w_in, const float* __restrict__ w_g,
                                 const float* __restrict__ w1, const float* __restrict__ w2) {
    int id = blockIdx.y;
    const float* src; int K, M; size_t dst;
    if (id == 0) { src = patch_w; K = KI2C; M = CC; dst = OFF_PATCH; }
    else {
        int d = (id - 1) >> 2, kind = (id - 1) & 3;
        size_t base = OFF_BLK0 + (size_t)d * PER_BLK;
        if      (kind == 0) { src = w_in + (size_t)d*CC*CC;   K = CC;   M = CC;   dst = base; }
        else if (kind == 1) { src = w_g  + (size_t)d*CC*CC;   K = CC;   M = CC;   dst = base + LEN_CXC; }
        else if (kind == 2) { src = w1   + (size_t)d*CC*HIDN; K = CC;   M = HIDN; dst = base + 2*LEN_CXC; }
        else                { src = w2   + (size_t)d*HIDN*CC; K = HIDN; M = CC;   dst = base + 2*LEN_CXC + LEN_W1; }
    }
    int total = K * M;
    for (int e = blockIdx.x * blockDim.x + threadIdx.x; e < total; e += gridDim.x * blockDim.x) {
        int m = e / K, k = e % K;
        float v = src[(size_t)k * M + m];
        __nv_bfloat16 hi, lo;
        split_bf(v, hi, lo);
        g_wt_hi[dst + e] = hi;
        g_wt_lo[dst + e] = lo;
    }
}

// ---------------- im2col -> bf16 hi/lo pairs ----------------
__global__ void im2col_kernel(const float* __restrict__ x) {
    int token = blockIdx.x;
    int b  = token / (GRIDW*GRIDW);
    int p  = token % (GRIDW*GRIDW);
    int gy = p / GRIDW, gx = p % GRIDW;
    for (int k = threadIdx.x; k < KI2C; k += blockDim.x) {
        int py = k / 48;
        int r  = k % 48;
        size_t src = ((size_t)(b*IMGSZ + gy*PATCH + py) * IMGSZ + gx*PATCH) * 3 + r;
        float v = x[src];
        __nv_bfloat16 hi, lo;
        split_bf(v, hi, lo);
        g_za_hi[(size_t)token*KI2C + k] = hi;
        g_za_lo[(size_t)token*KI2C + k] = lo;
    }
}

// ---------------- mma.sync GEMM: C[NTOK, M] = epi(A @ W^T + bias) ----------------
// A bf16 hi/lo [rows, K]; W bf16 hi/lo [M, K]. CTA tile 128x128, BK=32,
// 8 warps (2m x 4n), warp tile 64x32, m16n8k16, 3-pass hi/lo split.
// SMEM tile: 128 rows x 80B (32 bf16 data + 16B pad) -> conflict-free ldmatrix.
// EPI: 0 +bias ; 1 sigmoid ; 2 gelu->g_hid pairs ; 3 residual add ; 4 +bias+pos
#define ROWB        80
#define TILEB       (128*ROWB)         // 10240
#define STAGEB      (4*TILEB)          // 40960
#define GEMM_SMEM   (2*STAGEB)         // 81920

template<int EPI>
__global__ __launch_bounds__(256, 2)
void tgemm_kernel(const __nv_bfloat16* __restrict__ Ah, const __nv_bfloat16* __restrict__ Al,
                  const __nv_bfloat16* __restrict__ Bh, const __nv_bfloat16* __restrict__ Bl,
                  const float* __restrict__ bias, float* __restrict__ Cout,
                  int K, int M, const float* __restrict__ extra) {
    extern __shared__ char smem[];
    const uint32_t sb = smem_u32(smem);
    const int tid = threadIdx.x, wid = tid >> 5, lid = tid & 31;
    const int bn = blockIdx.x, bm = blockIdx.y;
    const int NC = K >> 5;                       // 32-wide k chunks
    const int wm = wid & 1, wn = wid >> 1;       // warp 64x32 tile coords

    // loader: 4 tiles (Ah, Al, Bh, Bl), each thread 2x16B per tile
    const int lrow = tid >> 1;
    const int lc0  = (tid & 1) * 2;
    auto load_chunk = [&](int c, int stage) {
        const int k0 = c * 32;
        const uint32_t sbase = sb + stage * STAGEB;
        #pragma unroll
        for (int t = 0; t < 4; t++) {
            const __nv_bfloat16* basep = (t == 0) ? Ah : (t == 1) ? Al : (t == 2) ? Bh : Bl;
            const size_t rbase = (t < 2) ? ((size_t)bm * 128) : ((size_t)bn * 128);
            #pragma unroll
            for (int j = 0; j < 2; j++) {
                int cc = lc0 + j;
                const __nv_bfloat16* src = basep + (rbase + lrow) * K + k0 + cc * 8;
                CP16(sbase + t * TILEB + lrow * ROWB + cc * 16, src);
            }
        }
        CP_COMMIT();
    };

    load_chunk(0, 0);
    if (NC > 1) load_chunk(1, 1);

    float acc[4][4][4];
    #pragma unroll
    for (int i = 0; i < 4; i++)
        #pragma unroll
        for (int j = 0; j < 4; j++)
            #pragma unroll
            for (int q = 0; q < 4; q++) acc[i][j][q] = 0.0f;

    // ldmatrix lane address components
    const uint32_t arow = (uint32_t)(lid & 15);          // A: row within 16
    const uint32_t asel = (uint32_t)(lid >> 4);          // A: k-half
    const uint32_t brow = (uint32_t)((lid & 7) + ((lid & 16) ? 8 : 0));  // B: n within 16
    const uint32_t bsel = (uint32_t)((lid >> 3) & 1);    // B: k-half

    for (int c = 0; c < NC; c++) {
        if (c + 1 < NC) asm volatile("cp.async.wait_group 1;" ::: "memory");
        else            asm volatile("cp.async.wait_group 0;" ::: "memory");
        __syncthreads();

        const uint32_t st  = sb + (c & 1) * STAGEB;
        const uint32_t tAh = st;
        const uint32_t tAl = st + TILEB;
        const uint32_t tBh = st + 2 * TILEB;
        const uint32_t tBl = st + 3 * TILEB;

        #pragma unroll
        for (int ks = 0; ks < 2; ks++) {
            uint32_t a[4][4], b[4][2], b2[4][2];
            // A hi
            #pragma unroll
            for (int mf = 0; mf < 4; mf++)
                ldm4(a[mf], tAh + (wm*64 + mf*16 + arow) * ROWB + (ks*2 + asel) * 16);
            // B hi
            #pragma unroll
            for (int ng = 0; ng < 2; ng++) {
                uint32_t r[4];
                ldm4(r, tBh + (wn*32 + ng*16 + brow) * ROWB + (ks*2 + bsel) * 16);
                b[ng*2+0][0] = r[0]; b[ng*2+0][1] = r[1];
                b[ng*2+1][0] = r[2]; b[ng*2+1][1] = r[3];
            }
            #pragma unroll
            for (int mf = 0; mf < 4; mf++)
                #pragma unroll
                for (int nf = 0; nf < 4; nf++)
                    mma16816(acc[mf][nf], a[mf], b[nf]);
            // B lo : Ah x Bl
            #pragma unroll
            for (int ng = 0; ng < 2; ng++) {
                uint32_t r[4];
                ldm4(r, tBl + (wn*32 + ng*16 + brow) * ROWB + (ks*2 + bsel) * 16);
                b2[ng*2+0][0] = r[0]; b2[ng*2+0][1] = r[1];
                b2[ng*2+1][0] = r[2]; b2[ng*2+1][1] = r[3];
            }
            #pragma unroll
            for (int mf = 0; mf < 4; mf++)
                #pragma unroll
                for (int nf = 0; nf < 4; nf++)
                    mma16816(acc[mf][nf], a[mf], b2[nf]);
            // A lo : Al x Bh (reuse a regs)
            #pragma unroll
            for (int mf = 0; mf < 4; mf++)
                ldm4(a[mf], tAl + (wm*64 + mf*16 + arow) * ROWB + (ks*2 + asel) * 16);
            #pragma unroll
            for (int mf = 0; mf < 4; mf++)
                #pragma unroll
                for (int nf = 0; nf < 4; nf++)
                    mma16816(acc[mf][nf], a[mf], b[nf]);
        }
        __syncthreads();
        if (c + 2 < NC) load_chunk(c + 2, c & 1);
    }

    // epilogue
    const int gr = lid >> 2, gc = lid & 3;
    #pragma unroll
    for (int mf = 0; mf < 4; mf++) {
        #pragma unroll
        for (int nf = 0; nf < 4; nf++) {
            const int col  = bn * 128 + wn * 32 + nf * 8 + gc * 2;
            const float2 bv = *reinterpret_cast<const float2*>(bias + col);
            #pragma unroll
            for (int half = 0; half < 2; half++) {
                const int row = bm * 128 + wm * 64 + mf * 16 + gr + half * 8;
                float v0 = acc[mf][nf][half*2+0] + bv.x;
                float v1 = acc[mf][nf][half*2+1] + bv.y;
                if (EPI == 1) { v0 = sigmoid_f(v0); v1 = sigmoid_f(v1); }
                if (EPI == 2) {
                    v0 = gelu_f(v0); v1 = gelu_f(v1);
                    __nv_bfloat16 h0, l0, h1, l1;
                    split_bf(v0, h0, l0); split_bf(v1, h1, l1);
                    size_t ob = (size_t)row * M + col;
                    *reinterpret_cast<uint32_t*>(&g_hid_hi[ob]) =
                        pack_bf2(__bfloat162float(h0), __bfloat162float(h1));
                    *reinterpret_cast<uint32_t*>(&g_hid_lo[ob]) =
                        pack_bf2(__bfloat162float(l0), __bfloat162float(l1));
                    continue;
                }
                if (EPI == 4) {
                    int p = row % (GRIDW*GRIDW);
                    float2 pv = *reinterpret_cast<const float2*>(extra + (size_t)p * CC + col);
                    v0 += pv.x; v1 += pv.y;
                }
                float* cp = Cout + (size_t)row * M + col;
                if (EPI == 3) {
                    float2 rr = *reinterpret_cast<const float2*>(cp);
                    v0 += rr.x; v1 += rr.y;
                }
                float2 o; o.x = v0; o.y = v1;
                *reinterpret_cast<float2*>(cp) = o;
            }
        }
    }
}

// ---------------- LayerNorm: g_h -> (bf16 pairs) or (fp32 g_z) ----------------
template<bool PAIR>
__global__ __launch_bounds__(128)
void ln_kernel(const float* __restrict__ gamma, const float* __restrict__ beta) {
    int row = blockIdx.x;
    int t = threadIdx.x;
    const float* xr = g_h + (size_t)row * CC;
    float v0 = xr[t], v1 = xr[t + 128], v2 = xr[t + 256];
    float s = v0 + v1 + v2;
    float q = v0 * v0 + v1 * v1 + v2 * v2;
    #pragma unroll
    for (int o = 16; o; o >>= 1) {
        s += __shfl_down_sync(0xffffffffu, s, o);
        q += __shfl_down_sync(0xffffffffu, q, o);
    }
    __shared__ float ss[4], sq[4];
    __shared__ float mean_s, rs_s;
    if ((t & 31) == 0) { ss[t >> 5] = s; sq[t >> 5] = q; }
    __syncthreads();
    if (t == 0) {
        float S = ss[0] + ss[1] + ss[2] + ss[3];
        float Q = sq[0] + sq[1] + sq[2] + sq[3];
        float m = S * (1.0f / CC);
        float var = Q * (1.0f / CC) - m * m;
        mean_s = m;
        rs_s = rsqrtf(var + 1e-6f);
    }
    __syncthreads();
    float m = mean_s, r = rs_s;
    #pragma unroll
    for (int i = 0; i < 3; i++) {
        int c = t + i * 128;
        float v = (i == 0) ? v0 : (i == 1) ? v1 : v2;
        float y = (v - m) * r * gamma[c] + beta[c];
        if (PAIR) {
            __nv_bfloat16 hi, lo;
            split_bf(y, hi, lo);
            g_za_hi[(size_t)row * CC + c] = hi;
            g_za_lo[(size_t)row * CC + c] = lo;
        } else {
            g_z[(size_t)row * CC + c] = y;
        }
    }
}

// ---------------- gated depthwise-conv recurrence ----------------
__global__ __launch_bounds__(196)
void recur_kernel(const float* __restrict__ KD) {
    __shared__ float s[32][256];
    __shared__ float kds[9][32];

    int blk = blockIdx.x;
    int b  = blk / (CC / 32);
    int cg = blk % (CC / 32);
    int tid = threadIdx.x;
    int y = tid / GRIDW, x = tid % GRIDW;

    for (int i = tid; i < 32 * 256; i += 196) ((float*)s)[i] = 0.0f;
    for (int i = tid; i < 288; i += 196)
        ((float*)kds)[i] = KD[(i >> 5) * CC + cg * 32 + (i & 31)];

    size_t base = ((size_t)(b * (GRIDW*GRIDW) + tid)) * CC + cg * 32;
    float gg[32], u1[32], ns[32];
    #pragma unroll
    for (int c = 0; c < 32; c += 4) {
        float4 gv = *reinterpret_cast<const float4*>(g_gate + base + c);
        float4 uv = *reinterpret_cast<const float4*>(g_u + base + c);
        gg[c+0]=gv.x; gg[c+1]=gv.y; gg[c+2]=gv.z; gg[c+3]=gv.w;
        u1[c+0]=(1.0f-gv.x)*uv.x; u1[c+1]=(1.0f-gv.y)*uv.y;
        u1[c+2]=(1.0f-gv.z)*uv.z; u1[c+3]=(1.0f-gv.w)*uv.w;
    }
    __syncthreads();

    const int ip = (y + 1) * 16 + (x + 1);
    #pragma unroll
    for (int c = 0; c < 32; c++) s[c][ip] = u1[c];
    __syncthreads();

    for (int step = 0; step < TT - 1; step++) {
        #pragma unroll
        for (int c = 0; c < 32; c++) {
            const float* sc = s[c];
            float acc = kds[0][c]*sc[ip-17] + kds[1][c]*sc[ip-16] + kds[2][c]*sc[ip-15]
                      + kds[3][c]*sc[ip-1]  + kds[4][c]*sc[ip]    + kds[5][c]*sc[ip+1]
                      + kds[6][c]*sc[ip+15] + kds[7][c]*sc[ip+16] + kds[8][c]*sc[ip+17];
            ns[c] = gg[c] * acc + u1[c];
        }
        __syncthreads();
        #pragma unroll
        for (int c = 0; c < 32; c++) s[c][ip] = ns[c];
        __syncthreads();
    }

    #pragma unroll
    for (int c = 0; c < 32; c++) g_h[base + c] += s[c][ip];
}

// ---------------- final max pool over spatial ----------------
__global__ void maxpool_kernel() {
    int b = blockIdx.x, c = threadIdx.x;
    const float* zb = g_z + (size_t)b * (GRIDW*GRIDW) * CC + c;
    float m = -INFINITY;
    #pragma unroll 4
    for (int p = 0; p < GRIDW*GRIDW; p++) m = fmaxf(m, zb[(size_t)p * CC]);
    g_pool[b * CC + c] = m;
}

// ---------------- classification head ----------------
__global__ void head_kernel(const float* __restrict__ HW, const float* __restrict__ HB,
                            float* __restrict__ out) {
    int idx = blockIdx.x * blockDim.x + threadIdx.x;
    if (idx >= BATCH * NCLS) return;
    int b = idx / NCLS, cls = idx % NCLS;
    const float* pb = g_pool + b * CC;
    float acc = HB[cls];
    #pragma unroll 4
    for (int k = 0; k < CC; k++) acc += pb[k] * HW[(size_t)k * NCLS + cls];
    out[idx] = acc;
}

// ---------------- host orchestration ----------------
extern "C" void kernel_launch(void* const* d_in, const int* in_sizes, int n_in,
                              void* d_out, int out_size) {
    const float* x       = (const float*)d_in[0];
    const float* patch_w = (const float*)d_in[1];
    const float* patch_b = (const float*)d_in[2];
    const float* pos     = (const float*)d_in[3];
    const float* ln1_s   = (const float*)d_in[4];
    const float* ln1_b   = (const float*)d_in[5];
    const float* w_in    = (const float*)d_in[6];
    const float* b_in    = (const float*)d_in[7];
    const float* w_g     = (const float*)d_in[8];
    const float* b_g     = (const float*)d_in[9];
    const float* k_dw    = (const float*)d_in[10];
    const float* ln2_s   = (const float*)d_in[11];
    const float* ln2_b   = (const float*)d_in[12];
    const float* w1      = (const float*)d_in[13];
    const float* b1      = (const float*)d_in[14];
    const float* w2      = (const float*)d_in[15];
    const float* b2      = (const float*)d_in[16];
    const float* lnf_s   = (const float*)d_in[17];
    const float* lnf_b   = (const float*)d_in[18];
    const float* head_w  = (const float*)d_in[19];
    const float* head_b  = (const float*)d_in[20];
    float* out = (float*)d_out;

    float *ph, *pu, *pg;
    __nv_bfloat16 *zah, *zal, *hidh, *hidl, *wth, *wtl;
    cudaGetSymbolAddress((void**)&ph,   g_h);
    cudaGetSymbolAddress((void**)&pu,   g_u);
    cudaGetSymbolAddress((void**)&pg,   g_gate);
    cudaGetSymbolAddress((void**)&zah,  g_za_hi);
    cudaGetSymbolAddress((void**)&zal,  g_za_lo);
    cudaGetSymbolAddress((void**)&hidh, g_hid_hi);
    cudaGetSymbolAddress((void**)&hidl, g_hid_lo);
    cudaGetSymbolAddress((void**)&wth,  g_wt_hi);
    cudaGetSymbolAddress((void**)&wtl,  g_wt_lo);

    cudaFuncSetAttribute(tgemm_kernel<0>, cudaFuncAttributeMaxDynamicSharedMemorySize, GEMM_SMEM);
    cudaFuncSetAttribute(tgemm_kernel<1>, cudaFuncAttributeMaxDynamicSharedMemorySize, GEMM_SMEM);
    cudaFuncSetAttribute(tgemm_kernel<2>, cudaFuncAttributeMaxDynamicSharedMemorySize, GEMM_SMEM);
    cudaFuncSetAttribute(tgemm_kernel<3>, cudaFuncAttributeMaxDynamicSharedMemorySize, GEMM_SMEM);
    cudaFuncSetAttribute(tgemm_kernel<4>, cudaFuncAttributeMaxDynamicSharedMemorySize, GEMM_SMEM);

    const int NT = NTOK / 128;   // 49

    // weights -> transposed bf16 hi/lo
    convert_w_kernel<<<dim3(288, 1 + 4*DD), 256>>>(patch_w, w_in, w_g, w1, w2);

    // patch embed
    im2col_kernel<<<NTOK, 256>>>(x);
    tgemm_kernel<4><<<dim3(CC/128, NT), 256, GEMM_SMEM>>>(
        zah, zal, wth + OFF_PATCH, wtl + OFF_PATCH, patch_b, ph, KI2C, CC, pos);

    for (int d = 0; d < DD; d++) {
        size_t wb = OFF_BLK0 + (size_t)d * PER_BLK;
        ln_kernel<true><<<NTOK, 128>>>(ln1_s + d*CC, ln1_b + d*CC);
        tgemm_kernel<0><<<dim3(CC/128, NT), 256, GEMM_SMEM>>>(
            zah, zal, wth + wb, wtl + wb, b_in + d*CC, pu, CC, CC, nullptr);
        tgemm_kernel<1><<<dim3(CC/128, NT), 256, GEMM_SMEM>>>(
            zah, zal, wth + wb + LEN_CXC, wtl + wb + LEN_CXC, b_g + d*CC, pg, CC, CC, nullptr);
        recur_kernel<<<BATCH * (CC/32), 196>>>(k_dw + (size_t)d*9*CC);
        ln_kernel<true><<<NTOK, 128>>>(ln2_s + d*CC, ln2_b + d*CC);
        tgemm_kernel<2><<<dim3(HIDN/128, NT), 256, GEMM_SMEM>>>(
            zah, zal, wth + wb + 2*LEN_CXC, wtl + wb + 2*LEN_CXC, b1 + d*HIDN, nullptr, CC, HIDN, nullptr);
        tgemm_kernel<3><<<dim3(CC/128, NT), 256, GEMM_SMEM>>>(
            hidh, hidl, wth + wb + 2*LEN_CXC + LEN_W1, wtl + wb + 2*LEN_CXC + LEN_W1,
            b2 + d*CC, ph, HIDN, CC, nullptr);
    }

    ln_kernel<false><<<NTOK, 128>>>(lnf_s, lnf_b);
    maxpool_kernel<<<BATCH, CC>>>();
    head_kernel<<<(BATCH*NCLS + 255) / 256, 256>>>(head_w, head_b, out);
}

// round 7
// speedup vs baseline: 1.6972x; 1.0173x over previous
#include <cuda_runtime.h>
#include <cuda_bf16.h>
#include <math.h>
#include <stdint.h>

// ---------------- problem constants ----------------
#define BATCH   32
#define IMGSZ   224
#define PATCH   16
#define CC      384
#define DD      12
#define TT      8
#define HIDN    1536
#define NCLS    1000
#define GRIDW   14
#define NTOK    (BATCH*GRIDW*GRIDW)   // 6272
#define KI2C    (PATCH*PATCH*3)       // 768

// weight scratch offsets (transposed [M,K] bf16 hi/lo)
#define OFF_PATCH   0
#define LEN_PATCH   (384*768)
#define OFF_BLK0    LEN_PATCH
#define LEN_CXC     (CC*CC)            // 147456
#define LEN_W1      (HIDN*CC)          // 589824
#define PER_BLK     (2*LEN_CXC + 2*LEN_W1)   // 1474560
#define WT_TOTAL    (OFF_BLK0 + DD*PER_BLK)  // 17989632

// ---------------- scratch (no allocations allowed) ----------------
__device__ float g_h   [(size_t)NTOK*CC];
__device__ float g_z   [(size_t)NTOK*CC];
__device__ float g_u   [(size_t)NTOK*CC];
__device__ float g_gate[(size_t)NTOK*CC];
__device__ float g_pool[(size_t)BATCH*CC];
__device__ __nv_bfloat16 g_za_hi [(size_t)NTOK*KI2C];
__device__ __nv_bfloat16 g_za_lo [(size_t)NTOK*KI2C];
__device__ __nv_bfloat16 g_hid_hi[(size_t)NTOK*HIDN];
__device__ __nv_bfloat16 g_hid_lo[(size_t)NTOK*HIDN];
__device__ __nv_bfloat16 g_wt_hi [(size_t)WT_TOTAL];
__device__ __nv_bfloat16 g_wt_lo [(size_t)WT_TOTAL];

// ---------------- small helpers ----------------
__device__ __forceinline__ float gelu_f(float x) {
    float x3 = x * x * x;
    float t  = tanhf(0.7978845608028654f * (x + 0.044715f * x3));
    return 0.5f * x * (1.0f + t);
}
__device__ __forceinline__ float sigmoid_f(float x) { return 1.0f / (1.0f + expf(-x)); }

__device__ __forceinline__ uint32_t smem_u32(const void* p) {
    uint32_t a;
    asm("{ .reg .u64 t; cvta.to.shared.u64 t, %1; cvt.u32.u64 %0, t; }" : "=r"(a) : "l"(p));
    return a;
}
__device__ __forceinline__ uint32_t pack_bf2(float a, float b) {
    uint32_t u; asm("cvt.rn.bf16x2.f32 %0, %1, %2;" : "=r"(u) : "f"(b), "f"(a)); return u;
}
__device__ __forceinline__ void split_bf(float v, __nv_bfloat16& hi, __nv_bfloat16& lo) {
    hi = __float2bfloat16(v);
    lo = __float2bfloat16(v - __bfloat162float(hi));
}

#define CP16(dst, src)      asm volatile("cp.async.cg.shared.global [%0], [%1], 16;" :: "r"(dst), "l"(src))
#define CP_COMMIT()         asm volatile("cp.async.commit_group;" ::: "memory")

__device__ __forceinline__ void ldm4(uint32_t* r, uint32_t addr) {
    asm volatile("ldmatrix.sync.aligned.m8n8.x4.shared.b16 {%0,%1,%2,%3}, [%4];"
                 : "=r"(r[0]), "=r"(r[1]), "=r"(r[2]), "=r"(r[3]) : "r"(addr));
}
__device__ __forceinline__ void mma16816(float* c, const uint32_t* a, const uint32_t* b) {
    asm volatile("mma.sync.aligned.m16n8k16.row.col.f32.bf16.bf16.f32 "
                 "{%0,%1,%2,%3}, {%4,%5,%6,%7}, {%8,%9}, {%0,%1,%2,%3};"
                 : "+f"(c[0]), "+f"(c[1]), "+f"(c[2]), "+f"(c[3])
                 : "r"(a[0]), "r"(a[1]), "r"(a[2]), "r"(a[3]), "r"(b[0]), "r"(b[1]));
}

// ---------------- weight convert+transpose: fp32 [K,M] -> bf16 hi/lo [M,K] ----------------
__global__ void convert_w_kernel(const float* __restrict__ patch_w,
                                 const float* __restrict__ w_in, const float* __restrict__ w_g,
                                 const float* __restrict__ w1, const float* __restrict__ w2) {
    int id = blockIdx.y;
    const float* src; int K, M; size_t dst;
    if (id == 0) { src = patch_w; K = KI2C; M = CC; dst = OFF_PATCH; }
    else {
        int d = (id - 1) >> 2, kind = (id - 1) & 3;
        size_t base = OFF_BLK0 + (size_t)d * PER_BLK;
        if      (kind == 0) { src = w_in + (size_t)d*CC*CC;   K = CC;   M = CC;   dst = base; }
        else if (kind == 1) { src = w_g  + (size_t)d*CC*CC;   K = CC;   M = CC;   dst = base + LEN_CXC; }
        else if (kind == 2) { src = w1   + (size_t)d*CC*HIDN; K = CC;   M = HIDN; dst = base + 2*LEN_CXC; }
        else                { src = w2   + (size_t)d*HIDN*CC; K = HIDN; M = CC;   dst = base + 2*LEN_CXC + LEN_W1; }
    }
    int total = K * M;
    for (int e = blockIdx.x * blockDim.x + threadIdx.x; e < total; e += gridDim.x * blockDim.x) {
        int m = e / K, k = e % K;
        float v = src[(size_t)k * M + m];
        __nv_bfloat16 hi, lo;
        split_bf(v, hi, lo);
        g_wt_hi[dst + e] = hi;
        g_wt_lo[dst + e] = lo;
    }
}

// ---------------- im2col -> bf16 hi/lo pairs ----------------
__global__ void im2col_kernel(const float* __restrict__ x) {
    int token = blockIdx.x;
    int b  = token / (GRIDW*GRIDW);
    int p  = token % (GRIDW*GRIDW);
    int gy = p / GRIDW, gx = p % GRIDW;
    for (int k = threadIdx.x; k < KI2C; k += blockDim.x) {
        int py = k / 48;
        int r  = k % 48;
        size_t src = ((size_t)(b*IMGSZ + gy*PATCH + py) * IMGSZ + gx*PATCH) * 3 + r;
        float v = x[src];
        __nv_bfloat16 hi, lo;
        split_bf(v, hi, lo);
        g_za_hi[(size_t)token*KI2C + k] = hi;
        g_za_lo[(size_t)token*KI2C + k] = lo;
    }
}

// ---------------- mma.sync GEMM: C[NTOK, M] = epi(A @ W^T + bias) ----------------
// CTA tile 64x128, BK=32, 8 warps (2m x 4n), warp tile 32x32, 3-pass hi/lo split.
// SMEM rows 80B (32 bf16 + 16B pad) -> conflict-free ldmatrix, no swizzle.
// EPI: 2 gelu->g_hid pairs ; 3 residual add ; 4 +bias+pos ; 5 fused u/gate
#define ROWB        80
#define A_TILEB     (64*ROWB)          // 5120
#define B_TILEB     (128*ROWB)         // 10240
#define STAGEB      (2*A_TILEB + 2*B_TILEB)  // 30720
#define GEMM_SMEM   (2*STAGEB)               // 61440
#define OFF_AL      A_TILEB
#define OFF_BH      (2*A_TILEB)
#define OFF_BL      (2*A_TILEB + B_TILEB)

template<int EPI>
__global__ __launch_bounds__(256, 2)
void tgemm_kernel(const __nv_bfloat16* __restrict__ Ah, const __nv_bfloat16* __restrict__ Al,
                  const __nv_bfloat16* __restrict__ Bh, const __nv_bfloat16* __restrict__ Bl,
                  const float* __restrict__ bias, float* __restrict__ Cout,
                  int K, int M, const float* __restrict__ extra) {
    extern __shared__ char smem[];
    const uint32_t sb = smem_u32(smem);
    const int tid = threadIdx.x, wid = tid >> 5, lid = tid & 31;
    const int bn = blockIdx.x, bm = blockIdx.y;
    const int NC = K >> 5;
    const int wm = wid & 1, wn = wid >> 1;       // warp 32x32 tile coords

    const int arowi = tid >> 2;     // 0..63  (A row per cp16)
    const int aseg  = tid & 3;      // 16B segment
    auto load_chunk = [&](int c, int stage) {
        const int k0 = c * 32;
        const uint32_t sbase = sb + stage * STAGEB;
        // A hi / lo : 64 rows x 4 segs, one per thread
        {
            const size_t gr = (size_t)(bm * 64 + arowi) * K + k0 + aseg * 8;
            CP16(sbase + arowi * ROWB + aseg * 16,          Ah + gr);
            CP16(sbase + OFF_AL + arowi * ROWB + aseg * 16, Al + gr);
        }
        // B hi / lo : 128 rows x 4 segs, two per thread
        #pragma unroll
        for (int j = 0; j < 2; j++) {
            int idx = tid + j * 256;
            int row = idx >> 2, seg = idx & 3;
            const size_t gr = (size_t)(bn * 128 + row) * K + k0 + seg * 8;
            CP16(sbase + OFF_BH + row * ROWB + seg * 16, Bh + gr);
            CP16(sbase + OFF_BL + row * ROWB + seg * 16, Bl + gr);
        }
        CP_COMMIT();
    };

    load_chunk(0, 0);
    if (NC > 1) load_chunk(1, 1);

    float acc[2][4][4];
    #pragma unroll
    for (int i = 0; i < 2; i++)
        #pragma unroll
        for (int j = 0; j < 4; j++)
            #pragma unroll
            for (int q = 0; q < 4; q++) acc[i][j][q] = 0.0f;

    const uint32_t arow = (uint32_t)(lid & 15);
    const uint32_t asel = (uint32_t)(lid >> 4);
    const uint32_t brow = (uint32_t)((lid & 7) + ((lid & 16) ? 8 : 0));
    const uint32_t bsel = (uint32_t)((lid >> 3) & 1);

    for (int c = 0; c < NC; c++) {
        if (c + 1 < NC) asm volatile("cp.async.wait_group 1;" ::: "memory");
        else            asm volatile("cp.async.wait_group 0;" ::: "memory");
        __syncthreads();

        const uint32_t st  = sb + (c & 1) * STAGEB;
        #pragma unroll
        for (int ks = 0; ks < 2; ks++) {
            uint32_t a[2][4], al[2][4], b[4][2], b2[4][2];
            #pragma unroll
            for (int mf = 0; mf < 2; mf++) {
                uint32_t ra = st + (wm*32 + mf*16 + arow) * ROWB + (ks*2 + asel) * 16;
                ldm4(a[mf],  ra);
                ldm4(al[mf], ra + OFF_AL);
            }
            #pragma unroll
            for (int ng = 0; ng < 2; ng++) {
                uint32_t rb = st + (wn*32 + ng*16 + brow) * ROWB + (ks*2 + bsel) * 16;
                uint32_t r[4], r2[4];
                ldm4(r,  rb + OFF_BH);
                ldm4(r2, rb + OFF_BL);
                b[ng*2+0][0]  = r[0];  b[ng*2+0][1]  = r[1];
                b[ng*2+1][0]  = r[2];  b[ng*2+1][1]  = r[3];
                b2[ng*2+0][0] = r2[0]; b2[ng*2+0][1] = r2[1];
                b2[ng*2+1][0] = r2[2]; b2[ng*2+1][1] = r2[3];
            }
            #pragma unroll
            for (int mf = 0; mf < 2; mf++)
                #pragma unroll
                for (int nf = 0; nf < 4; nf++) {
                    mma16816(acc[mf][nf], a[mf],  b[nf]);
                    mma16816(acc[mf][nf], a[mf],  b2[nf]);
                    mma16816(acc[mf][nf], al[mf], b[nf]);
                }
        }
        __syncthreads();
        if (c + 2 < NC) load_chunk(c + 2, c & 1);
    }

    // epilogue
    const int gr = lid >> 2, gc = lid & 3;
    #pragma unroll
    for (int mf = 0; mf < 2; mf++) {
        #pragma unroll
        for (int nf = 0; nf < 4; nf++) {
            const int col = bn * 128 + wn * 32 + nf * 8 + gc * 2;
            #pragma unroll
            for (int half = 0; half < 2; half++) {
                const int row = bm * 64 + wm * 32 + mf * 16 + gr + half * 8;
                float v0 = acc[mf][nf][half*2+0];
                float v1 = acc[mf][nf][half*2+1];
                if (EPI == 5) {
                    // fused u/gate: cols [0,384) -> u (+b_in), [384,768) -> sigmoid gate (+b_g)
                    if (col < CC) {
                        float2 bv = *reinterpret_cast<const float2*>(bias + col);
                        v0 += bv.x; v1 += bv.y;
                        float2 o; o.x = v0; o.y = v1;
                        *reinterpret_cast<float2*>(&g_u[(size_t)row * CC + col]) = o;
                    } else {
                        int cg = col - CC;
                        float2 bv = *reinterpret_cast<const float2*>(extra + cg);
                        v0 = sigmoid_f(v0 + bv.x); v1 = sigmoid_f(v1 + bv.y);
                        float2 o; o.x = v0; o.y = v1;
                        *reinterpret_cast<float2*>(&g_gate[(size_t)row * CC + cg]) = o;
                    }
                    continue;
                }
                {
                    float2 bv = *reinterpret_cast<const float2*>(bias + col);
                    v0 += bv.x; v1 += bv.y;
                }
                if (EPI == 2) {
                    v0 = gelu_f(v0); v1 = gelu_f(v1);
                    __nv_bfloat16 h0, l0, h1, l1;
                    split_bf(v0, h0, l0); split_bf(v1, h1, l1);
                    size_t ob = (size_t)row * M + col;
                    *reinterpret_cast<uint32_t*>(&g_hid_hi[ob]) =
                        pack_bf2(__bfloat162float(h0), __bfloat162float(h1));
                    *reinterpret_cast<uint32_t*>(&g_hid_lo[ob]) =
                        pack_bf2(__bfloat162float(l0), __bfloat162float(l1));
                    continue;
                }
                if (EPI == 4) {
                    int p = row % (GRIDW*GRIDW);
                    float2 pv = *reinterpret_cast<const float2*>(extra + (size_t)p * CC + col);
                    v0 += pv.x; v1 += pv.y;
                }
                float* cp = Cout + (size_t)row * M + col;
                if (EPI == 3) {
                    float2 rr = *reinterpret_cast<const float2*>(cp);
                    v0 += rr.x; v1 += rr.y;
                }
                float2 o; o.x = v0; o.y = v1;
                *reinterpret_cast<float2*>(cp) = o;
            }
        }
    }
}

// ---------------- LayerNorm: g_h -> (bf16 pairs) or (fp32 g_z) ----------------
template<bool PAIR>
__global__ __launch_bounds__(128)
void ln_kernel(const float* __restrict__ gamma, const float* __restrict__ beta) {
    int row = blockIdx.x;
    int t = threadIdx.x;
    const float* xr = g_h + (size_t)row * CC;
    float v0 = xr[t], v1 = xr[t + 128], v2 = xr[t + 256];
    float s = v0 + v1 + v2;
    float q = v0 * v0 + v1 * v1 + v2 * v2;
    #pragma unroll
    for (int o = 16; o; o >>= 1) {
        s += __shfl_down_sync(0xffffffffu, s, o);
        q += __shfl_down_sync(0xffffffffu, q, o);
    }
    __shared__ float ss[4], sq[4];
    __shared__ float mean_s, rs_s;
    if ((t & 31) == 0) { ss[t >> 5] = s; sq[t >> 5] = q; }
    __syncthreads();
    if (t == 0) {
        float S = ss[0] + ss[1] + ss[2] + ss[3];
        float Q = sq[0] + sq[1] + sq[2] + sq[3];
        float m = S * (1.0f / CC);
        float var = Q * (1.0f / CC) - m * m;
        mean_s = m;
        rs_s = rsqrtf(var + 1e-6f);
    }
    __syncthreads();
    float m = mean_s, r = rs_s;
    #pragma unroll
    for (int i = 0; i < 3; i++) {
        int c = t + i * 128;
        float v = (i == 0) ? v0 : (i == 1) ? v1 : v2;
        float y = (v - m) * r * gamma[c] + beta[c];
        if (PAIR) {
            __nv_bfloat16 hi, lo;
            split_bf(y, hi, lo);
            g_za_hi[(size_t)row * CC + c] = hi;
            g_za_lo[(size_t)row * CC + c] = lo;
        } else {
            g_z[(size_t)row * CC + c] = y;
        }
    }
}

// ---------------- gated depthwise-conv recurrence ----------------
__global__ __launch_bounds__(196)
void recur_kernel(const float* __restrict__ KD) {
    __shared__ float s[32][256];
    __shared__ float kds[9][32];

    int blk = blockIdx.x;
    int b  = blk / (CC / 32);
    int cg = blk % (CC / 32);
    int tid = threadIdx.x;
    int y = tid / GRIDW, x = tid % GRIDW;

    for (int i = tid; i < 32 * 256; i += 196) ((float*)s)[i] = 0.0f;
    for (int i = tid; i < 288; i += 196)
        ((float*)kds)[i] = KD[(i >> 5) * CC + cg * 32 + (i & 31)];

    size_t base = ((size_t)(b * (GRIDW*GRIDW) + tid)) * CC + cg * 32;
    float gg[32], u1[32], ns[32];
    #pragma unroll
    for (int c = 0; c < 32; c += 4) {
        float4 gv = *reinterpret_cast<const float4*>(g_gate + base + c);
        float4 uv = *reinterpret_cast<const float4*>(g_u + base + c);
        gg[c+0]=gv.x; gg[c+1]=gv.y; gg[c+2]=gv.z; gg[c+3]=gv.w;
        u1[c+0]=(1.0f-gv.x)*uv.x; u1[c+1]=(1.0f-gv.y)*uv.y;
        u1[c+2]=(1.0f-gv.z)*uv.z; u1[c+3]=(1.0f-gv.w)*uv.w;
    }
    __syncthreads();

    const int ip = (y + 1) * 16 + (x + 1);
    #pragma unroll
    for (int c = 0; c < 32; c++) s[c][ip] = u1[c];
    __syncthreads();

    for (int step = 0; step < TT - 1; step++) {
        #pragma unroll
        for (int c = 0; c < 32; c++) {
            const float* sc = s[c];
            float acc = kds[0][c]*sc[ip-17] + kds[1][c]*sc[ip-16] + kds[2][c]*sc[ip-15]
                      + kds[3][c]*sc[ip-1]  + kds[4][c]*sc[ip]    + kds[5][c]*sc[ip+1]
                      + kds[6][c]*sc[ip+15] + kds[7][c]*sc[ip+16] + kds[8][c]*sc[ip+17];
            ns[c] = gg[c] * acc + u1[c];
        }
        __syncthreads();
        #pragma unroll
        for (int c = 0; c < 32; c++) s[c][ip] = ns[c];
        __syncthreads();
    }

    #pragma unroll
    for (int c = 0; c < 32; c++) g_h[base + c] += s[c][ip];
}

// ---------------- final max pool over spatial ----------------
__global__ void maxpool_kernel() {
    int b = blockIdx.x, c = threadIdx.x;
    const float* zb = g_z + (size_t)b * (GRIDW*GRIDW) * CC + c;
    float m = -INFINITY;
    #pragma unroll 4
    for (int p = 0; p < GRIDW*GRIDW; p++) m = fmaxf(m, zb[(size_t)p * CC]);
    g_pool[b * CC + c] = m;
}

// ---------------- classification head ----------------
__global__ void head_kernel(const float* __restrict__ HW, const float* __restrict__ HB,
                            float* __restrict__ out) {
    int idx = blockIdx.x * blockDim.x + threadIdx.x;
    if (idx >= BATCH * NCLS) return;
    int b = idx / NCLS, cls = idx % NCLS;
    const float* pb = g_pool + b * CC;
    float acc = HB[cls];
    #pragma unroll 4
    for (int k = 0; k < CC; k++) acc += pb[k] * HW[(size_t)k * NCLS + cls];
    out[idx] = acc;
}

// ---------------- host orchestration ----------------
extern "C" void kernel_launch(void* const* d_in, const int* in_sizes, int n_in,
                              void* d_out, int out_size) {
    const float* x       = (const float*)d_in[0];
    const float* patch_w = (const float*)d_in[1];
    const float* patch_b = (const float*)d_in[2];
    const float* pos     = (const float*)d_in[3];
    const float* ln1_s   = (const float*)d_in[4];
    const float* ln1_b   = (const float*)d_in[5];
    const float* w_in    = (const float*)d_in[6];
    const float* b_in    = (const float*)d_in[7];
    const float* w_g     = (const float*)d_in[8];
    const float* b_g     = (const float*)d_in[9];
    const float* k_dw    = (const float*)d_in[10];
    const float* ln2_s   = (const float*)d_in[11];
    const float* ln2_b   = (const float*)d_in[12];
    const float* w1      = (const float*)d_in[13];
    const float* b1      = (const float*)d_in[14];
    const float* w2      = (const float*)d_in[15];
    const float* b2      = (const float*)d_in[16];
    const float* lnf_s   = (const float*)d_in[17];
    const float* lnf_b   = (const float*)d_in[18];
    const float* head_w  = (const float*)d_in[19];
    const float* head_b  = (const float*)d_in[20];
    float* out = (float*)d_out;

    float *ph;
    __nv_bfloat16 *zah, *zal, *hidh, *hidl, *wth, *wtl;
    cudaGetSymbolAddress((void**)&ph,   g_h);
    cudaGetSymbolAddress((void**)&zah,  g_za_hi);
    cudaGetSymbolAddress((void**)&zal,  g_za_lo);
    cudaGetSymbolAddress((void**)&hidh, g_hid_hi);
    cudaGetSymbolAddress((void**)&hidl, g_hid_lo);
    cudaGetSymbolAddress((void**)&wth,  g_wt_hi);
    cudaGetSymbolAddress((void**)&wtl,  g_wt_lo);

    cudaFuncSetAttribute(tgemm_kernel<2>, cudaFuncAttributeMaxDynamicSharedMemorySize, GEMM_SMEM);
    cudaFuncSetAttribute(tgemm_kernel<3>, cudaFuncAttributeMaxDynamicSharedMemorySize, GEMM_SMEM);
    cudaFuncSetAttribute(tgemm_kernel<4>, cudaFuncAttributeMaxDynamicSharedMemorySize, GEMM_SMEM);
    cudaFuncSetAttribute(tgemm_kernel<5>, cudaFuncAttributeMaxDynamicSharedMemorySize, GEMM_SMEM);

    const int NT = NTOK / 64;    // 98

    // weights -> transposed bf16 hi/lo
    convert_w_kernel<<<dim3(288, 1 + 4*DD), 256>>>(patch_w, w_in, w_g, w1, w2);

    // patch embed
    im2col_kernel<<<NTOK, 256>>>(x);
    tgemm_kernel<4><<<dim3(CC/128, NT), 256, GEMM_SMEM>>>(
        zah, zal, wth + OFF_PATCH, wtl + OFF_PATCH, patch_b, ph, KI2C, CC, pos);

    for (int d = 0; d < DD; d++) {
        size_t wb = OFF_BLK0 + (size_t)d * PER_BLK;
        ln_kernel<true><<<NTOK, 128>>>(ln1_s + d*CC, ln1_b + d*CC);
        // fused u + gate GEMM over combined [768, 384] weight (w_in^T ++ w_g^T contiguous)
        tgemm_kernel<5><<<dim3((2*CC)/128, NT), 256, GEMM_SMEM>>>(
            zah, zal, wth + wb, wtl + wb, b_in + d*CC, nullptr, CC, 2*CC, b_g + d*CC);
        recur_kernel<<<BATCH * (CC/32), 196>>>(k_dw + (size_t)d*9*CC);
        ln_kernel<true><<<NTOK, 128>>>(ln2_s + d*CC, ln2_b + d*CC);
        tgemm_kernel<2><<<dim3(HIDN/128, NT), 256, GEMM_SMEM>>>(
            zah, zal, wth + wb + 2*LEN_CXC, wtl + wb + 2*LEN_CXC, b1 + d*HIDN, nullptr, CC, HIDN, nullptr);
        tgemm_kernel<3><<<dim3(CC/128, NT), 256, GEMM_SMEM>>>(
            hidh, hidl, wth + wb + 2*LEN_CXC + LEN_W1, wtl + wb + 2*LEN_CXC + LEN_W1,
            b2 + d*CC, ph, HIDN, CC, nullptr);
    }

    ln_kernel<false><<<NTOK, 128>>>(lnf_s, lnf_b);
    maxpool_kernel<<<BATCH, CC>>>();
    head_kernel<<<(BATCH*NCLS + 255) / 256, 256>>>(head_w, head_b, out);
}

// round 8
// speedup vs baseline: 2.1301x; 1.2550x over previous
#include <cuda_runtime.h>
#include <cuda_fp16.h>
#include <math.h>
#include <stdint.h>

// ---------------- problem constants ----------------
#define BATCH   32
#define IMGSZ   224
#define PATCH   16
#define CC      384
#define DD      12
#define TT      8
#define HIDN    1536
#define NCLS    1000
#define GRIDW   14
#define NTOK    (BATCH*GRIDW*GRIDW)   // 6272
#define KI2C    (PATCH*PATCH*3)       // 768

// weight scratch offsets (transposed [M,K] fp16)
#define OFF_PATCH   0
#define LEN_PATCH   (384*768)
#define OFF_BLK0    LEN_PATCH
#define LEN_CXC     (CC*CC)            // 147456
#define LEN_W1      (HIDN*CC)          // 589824
#define PER_BLK     (2*LEN_CXC + 2*LEN_W1)   // 1474560
#define WT_TOTAL    (OFF_BLK0 + DD*PER_BLK)  // 17989632

// ---------------- scratch (no allocations allowed) ----------------
__device__ float g_h   [(size_t)NTOK*CC];
__device__ float g_z   [(size_t)NTOK*CC];
__device__ float g_u   [(size_t)NTOK*CC];
__device__ float g_gate[(size_t)NTOK*CC];
__device__ float g_pool[(size_t)BATCH*CC];
__device__ __half g_za_hi [(size_t)NTOK*KI2C];
__device__ __half g_za_lo [(size_t)NTOK*KI2C];
__device__ __half g_hid_hi[(size_t)NTOK*HIDN];
__device__ __half g_hid_lo[(size_t)NTOK*HIDN];
__device__ __half g_wt    [(size_t)WT_TOTAL];

// ---------------- small helpers ----------------
__device__ __forceinline__ float gelu_f(float x) {
    float x3 = x * x * x;
    float t  = tanhf(0.7978845608028654f * (x + 0.044715f * x3));
    return 0.5f * x * (1.0f + t);
}
__device__ __forceinline__ float sigmoid_f(float x) { return 1.0f / (1.0f + expf(-x)); }

__device__ __forceinline__ uint32_t smem_u32(const void* p) {
    uint32_t a;
    asm("{ .reg .u64 t; cvta.to.shared.u64 t, %1; cvt.u32.u64 %0, t; }" : "=r"(a) : "l"(p));
    return a;
}
__device__ __forceinline__ void split_h(float v, __half& hi, __half& lo) {
    hi = __float2half_rn(v);
    lo = __float2half_rn(v - __half2float(hi));
}

#define CP16(dst, src)      asm volatile("cp.async.cg.shared.global [%0], [%1], 16;" :: "r"(dst), "l"(src))
#define CP_COMMIT()         asm volatile("cp.async.commit_group;" ::: "memory")

__device__ __forceinline__ void ldm4(uint32_t* r, uint32_t addr) {
    asm volatile("ldmatrix.sync.aligned.m8n8.x4.shared.b16 {%0,%1,%2,%3}, [%4];"
                 : "=r"(r[0]), "=r"(r[1]), "=r"(r[2]), "=r"(r[3]) : "r"(addr));
}
__device__ __forceinline__ void mma16816(float* c, const uint32_t* a, const uint32_t* b) {
    asm volatile("mma.sync.aligned.m16n8k16.row.col.f32.f16.f16.f32 "
                 "{%0,%1,%2,%3}, {%4,%5,%6,%7}, {%8,%9}, {%0,%1,%2,%3};"
                 : "+f"(c[0]), "+f"(c[1]), "+f"(c[2]), "+f"(c[3])
                 : "r"(a[0]), "r"(a[1]), "r"(a[2]), "r"(a[3]), "r"(b[0]), "r"(b[1]));
}

// ---------------- weight convert+transpose: fp32 [K,M] -> fp16 [M,K] ----------------
__global__ void convert_w_kernel(const float* __restrict__ patch_w,
                                 const float* __restrict__ w_in, const float* __restrict__ w_g,
                                 const float* __restrict__ w1, const float* __restrict__ w2) {
    int id = blockIdx.y;
    const float* src; int K, M; size_t dst;
    if (id == 0) { src = patch_w; K = KI2C; M = CC; dst = OFF_PATCH; }
    else {
        int d = (id - 1) >> 2, kind = (id - 1) & 3;
        size_t base = OFF_BLK0 + (size_t)d * PER_BLK;
        if      (kind == 0) { src = w_in + (size_t)d*CC*CC;   K = CC;   M = CC;   dst = base; }
        else if (kind == 1) { src = w_g  + (size_t)d*CC*CC;   K = CC;   M = CC;   dst = base + LEN_CXC; }
        else if (kind == 2) { src = w1   + (size_t)d*CC*HIDN; K = CC;   M = HIDN; dst = base + 2*LEN_CXC; }
        else                { src = w2   + (size_t)d*HIDN*CC; K = HIDN; M = CC;   dst = base + 2*LEN_CXC + LEN_W1; }
    }
    int total = K * M;
    for (int e = blockIdx.x * blockDim.x + threadIdx.x; e < total; e += gridDim.x * blockDim.x) {
        int m = e / K, k = e % K;
        g_wt[dst + e] = __float2half_rn(src[(size_t)k * M + m]);
    }
}

// ---------------- im2col -> fp16 hi/lo pairs ----------------
__global__ void im2col_kernel(const float* __restrict__ x) {
    int token = blockIdx.x;
    int b  = token / (GRIDW*GRIDW);
    int p  = token % (GRIDW*GRIDW);
    int gy = p / GRIDW, gx = p % GRIDW;
    for (int k = threadIdx.x; k < KI2C; k += blockDim.x) {
        int py = k / 48;
        int r  = k % 48;
        size_t src = ((size_t)(b*IMGSZ + gy*PATCH + py) * IMGSZ + gx*PATCH) * 3 + r;
        __half hi, lo;
        split_h(x[src], hi, lo);
        g_za_hi[(size_t)token*KI2C + k] = hi;
        g_za_lo[(size_t)token*KI2C + k] = lo;
    }
}

// ---------------- mma.sync GEMM: C[NTOK, M] = epi(A @ W^T + bias) ----------------
// A fp16 hi/lo [rows,K]; W fp16 [M,K]. CTA 128x128, BK=32, 8 warps (2m x 4n),
// warp tile 64x32, 2-pass (Ah*B + Al*B), 3-stage cp.async pipeline.
// SMEM rows 80B (32 fp16 + 16B pad) -> conflict-free ldmatrix.
// EPI: 2 gelu->g_hid pairs ; 3 residual add ; 4 +bias+pos ; 5 fused u/gate
#define ROWB        80
#define TILEB       (128*ROWB)         // 10240
#define STAGEB      (3*TILEB)          // 30720 (Ah, Al, B)
#define NSTAGE      3
#define GEMM_SMEM   (NSTAGE*STAGEB)    // 92160
#define OFF_AL      TILEB
#define OFF_B       (2*TILEB)

template<int EPI>
__global__ __launch_bounds__(256, 2)
void tgemm_kernel(const __half* __restrict__ Ah, const __half* __restrict__ Al,
                  const __half* __restrict__ Bw,
                  const float* __restrict__ bias, float* __restrict__ Cout,
                  int K, int M, const float* __restrict__ extra) {
    extern __shared__ char smem[];
    const uint32_t sb = smem_u32(smem);
    const int tid = threadIdx.x, wid = tid >> 5, lid = tid & 31;
    const int bn = blockIdx.x, bm = blockIdx.y;
    const int NC = K >> 5;
    const int wm = wid & 1, wn = wid >> 1;       // warp 64x32 tile coords

    auto load_chunk = [&](int c, int stage) {
        const int k0 = c * 32;
        const uint32_t sbase = sb + stage * STAGEB;
        #pragma unroll
        for (int j = 0; j < 2; j++) {
            int idx = tid + j * 256;
            int row = idx >> 2, seg = idx & 3;
            const size_t gra = (size_t)(bm * 128 + row) * K + k0 + seg * 8;
            const size_t grb = (size_t)(bn * 128 + row) * K + k0 + seg * 8;
            uint32_t so = row * ROWB + seg * 16;
            CP16(sbase + so,          Ah + gra);
            CP16(sbase + OFF_AL + so, Al + gra);
            CP16(sbase + OFF_B  + so, Bw + grb);
        }
        CP_COMMIT();
    };

    load_chunk(0, 0);
    if (NC > 1) load_chunk(1, 1);

    float acc[4][4][4];
    #pragma unroll
    for (int i = 0; i < 4; i++)
        #pragma unroll
        for (int j = 0; j < 4; j++)
            #pragma unroll
            for (int q = 0; q < 4; q++) acc[i][j][q] = 0.0f;

    const uint32_t arow = (uint32_t)(lid & 15);
    const uint32_t asel = (uint32_t)(lid >> 4);
    const uint32_t brow = (uint32_t)((lid & 7) + ((lid & 16) ? 8 : 0));
    const uint32_t bsel = (uint32_t)((lid >> 3) & 1);

    for (int c = 0; c < NC; c++) {
        if (c + 1 < NC) asm volatile("cp.async.wait_group 1;" ::: "memory");
        else            asm volatile("cp.async.wait_group 0;" ::: "memory");
        __syncthreads();
        if (c + 2 < NC) load_chunk(c + 2, (c + 2) % NSTAGE);

        const uint32_t st = sb + (c % NSTAGE) * STAGEB;
        #pragma unroll
        for (int ks = 0; ks < 2; ks++) {
            uint32_t b[4][2];
            #pragma unroll
            for (int ng = 0; ng < 2; ng++) {
                uint32_t r[4];
                ldm4(r, st + OFF_B + (wn*32 + ng*16 + brow) * ROWB + (ks*2 + bsel) * 16);
                b[ng*2+0][0] = r[0]; b[ng*2+0][1] = r[1];
                b[ng*2+1][0] = r[2]; b[ng*2+1][1] = r[3];
            }
            #pragma unroll
            for (int mf = 0; mf < 4; mf++) {
                uint32_t a[4], al[4];
                uint32_t ra = st + (wm*64 + mf*16 + arow) * ROWB + (ks*2 + asel) * 16;
                ldm4(a,  ra);
                ldm4(al, ra + OFF_AL);
                #pragma unroll
                for (int nf = 0; nf < 4; nf++) {
                    mma16816(acc[mf][nf], a,  b[nf]);
                    mma16816(acc[mf][nf], al, b[nf]);
                }
            }
        }
    }

    // epilogue
    const int gr = lid >> 2, gc = lid & 3;
    #pragma unroll
    for (int mf = 0; mf < 4; mf++) {
        #pragma unroll
        for (int nf = 0; nf < 4; nf++) {
            const int col = bn * 128 + wn * 32 + nf * 8 + gc * 2;
            #pragma unroll
            for (int half = 0; half < 2; half++) {
                const int row = bm * 128 + wm * 64 + mf * 16 + gr + half * 8;
                float v0 = acc[mf][nf][half*2+0];
                float v1 = acc[mf][nf][half*2+1];
                if (EPI == 5) {
                    // fused u/gate: cols [0,384) -> u (+b_in), [384,768) -> sigmoid gate (+b_g)
                    if (col < CC) {
                        float2 bv = *reinterpret_cast<const float2*>(bias + col);
                        float2 o; o.x = v0 + bv.x; o.y = v1 + bv.y;
                        *reinterpret_cast<float2*>(&g_u[(size_t)row * CC + col]) = o;
                    } else {
                        int cg = col - CC;
                        float2 bv = *reinterpret_cast<const float2*>(extra + cg);
                        float2 o; o.x = sigmoid_f(v0 + bv.x); o.y = sigmoid_f(v1 + bv.y);
                        *reinterpret_cast<float2*>(&g_gate[(size_t)row * CC + cg]) = o;
                    }
                    continue;
                }
                {
                    float2 bv = *reinterpret_cast<const float2*>(bias + col);
                    v0 += bv.x; v1 += bv.y;
                }
                if (EPI == 2) {
                    v0 = gelu_f(v0); v1 = gelu_f(v1);
                    __half h0, l0, h1, l1;
                    split_h(v0, h0, l0); split_h(v1, h1, l1);
                    size_t ob = (size_t)row * M + col;
                    *reinterpret_cast<__half2*>(&g_hid_hi[ob]) = __halves2half2(h0, h1);
                    *reinterpret_cast<__half2*>(&g_hid_lo[ob]) = __halves2half2(l0, l1);
                    continue;
                }
                if (EPI == 4) {
                    int p = row % (GRIDW*GRIDW);
                    float2 pv = *reinterpret_cast<const float2*>(extra + (size_t)p * CC + col);
                    v0 += pv.x; v1 += pv.y;
                }
                float* cp = Cout + (size_t)row * M + col;
                if (EPI == 3) {
                    float2 rr = *reinterpret_cast<const float2*>(cp);
                    v0 += rr.x; v1 += rr.y;
                }
                float2 o; o.x = v0; o.y = v1;
                *reinterpret_cast<float2*>(cp) = o;
            }
        }
    }
}

// ---------------- LayerNorm: g_h -> (fp16 pairs) or (fp32 g_z) ----------------
template<bool PAIR>
__global__ __launch_bounds__(128)
void ln_kernel(const float* __restrict__ gamma, const float* __restrict__ beta) {
    int row = blockIdx.x;
    int t = threadIdx.x;
    const float* xr = g_h + (size_t)row * CC;
    float v0 = xr[t], v1 = xr[t + 128], v2 = xr[t + 256];
    float s = v0 + v1 + v2;
    float q = v0 * v0 + v1 * v1 + v2 * v2;
    #pragma unroll
    for (int o = 16; o; o >>= 1) {
        s += __shfl_down_sync(0xffffffffu, s, o);
        q += __shfl_down_sync(0xffffffffu, q, o);
    }
    __shared__ float ss[4], sq[4];
    __shared__ float mean_s, rs_s;
    if ((t & 31) == 0) { ss[t >> 5] = s; sq[t >> 5] = q; }
    __syncthreads();
    if (t == 0) {
        float S = ss[0] + ss[1] + ss[2] + ss[3];
        float Q = sq[0] + sq[1] + sq[2] + sq[3];
        float m = S * (1.0f / CC);
        float var = Q * (1.0f / CC) - m * m;
        mean_s = m;
        rs_s = rsqrtf(var + 1e-6f);
    }
    __syncthreads();
    float m = mean_s, r = rs_s;
    #pragma unroll
    for (int i = 0; i < 3; i++) {
        int c = t + i * 128;
        float v = (i == 0) ? v0 : (i == 1) ? v1 : v2;
        float y = (v - m) * r * gamma[c] + beta[c];
        if (PAIR) {
            __half hi, lo;
            split_h(y, hi, lo);
            g_za_hi[(size_t)row * CC + c] = hi;
            g_za_lo[(size_t)row * CC + c] = lo;
        } else {
            g_z[(size_t)row * CC + c] = y;
        }
    }
}

// ---------------- gated depthwise-conv recurrence ----------------
__global__ __launch_bounds__(196)
void recur_kernel(const float* __restrict__ KD) {
    __shared__ float s[32][256];
    __shared__ float kds[9][32];

    int blk = blockIdx.x;
    int b  = blk / (CC / 32);
    int cg = blk % (CC / 32);
    int tid = threadIdx.x;
    int y = tid / GRIDW, x = tid % GRIDW;

    for (int i = tid; i < 32 * 256; i += 196) ((float*)s)[i] = 0.0f;
    for (int i = tid; i < 288; i += 196)
        ((float*)kds)[i] = KD[(i >> 5) * CC + cg * 32 + (i & 31)];

    size_t base = ((size_t)(b * (GRIDW*GRIDW) + tid)) * CC + cg * 32;
    float gg[32], u1[32], ns[32];
    #pragma unroll
    for (int c = 0; c < 32; c += 4) {
        float4 gv = *reinterpret_cast<const float4*>(g_gate + base + c);
        float4 uv = *reinterpret_cast<const float4*>(g_u + base + c);
        gg[c+0]=gv.x; gg[c+1]=gv.y; gg[c+2]=gv.z; gg[c+3]=gv.w;
        u1[c+0]=(1.0f-gv.x)*uv.x; u1[c+1]=(1.0f-gv.y)*uv.y;
        u1[c+2]=(1.0f-gv.z)*uv.z; u1[c+3]=(1.0f-gv.w)*uv.w;
    }
    __syncthreads();

    const int ip = (y + 1) * 16 + (x + 1);
    #pragma unroll
    for (int c = 0; c < 32; c++) s[c][ip] = u1[c];
    __syncthreads();

    for (int step = 0; step < TT - 1; step++) {
        #pragma unroll
        for (int c = 0; c < 32; c++) {
            const float* sc = s[c];
            float acc = kds[0][c]*sc[ip-17] + kds[1][c]*sc[ip-16] + kds[2][c]*sc[ip-15]
                      + kds[3][c]*sc[ip-1]  + kds[4][c]*sc[ip]    + kds[5][c]*sc[ip+1]
                      + kds[6][c]*sc[ip+15] + kds[7][c]*sc[ip+16] + kds[8][c]*sc[ip+17];
            ns[c] = gg[c] * acc + u1[c];
        }
        __syncthreads();
        #pragma unroll
        for (int c = 0; c < 32; c++) s[c][ip] = ns[c];
        __syncthreads();
    }

    #pragma unroll
    for (int c = 0; c < 32; c++) g_h[base + c] += s[c][ip];
}

// ---------------- final max pool over spatial ----------------
__global__ void maxpool_kernel() {
    int b = blockIdx.x, c = threadIdx.x;
    const float* zb = g_z + (size_t)b * (GRIDW*GRIDW) * CC + c;
    float m = -INFINITY;
    #pragma unroll 4
    for (int p = 0; p < GRIDW*GRIDW; p++) m = fmaxf(m, zb[(size_t)p * CC]);
    g_pool[b * CC + c] = m;
}

// ---------------- classification head ----------------
__global__ void head_kernel(const float* __restrict__ HW, const float* __restrict__ HB,
                            float* __restrict__ out) {
    int idx = blockIdx.x * blockDim.x + threadIdx.x;
    if (idx >= BATCH * NCLS) return;
    int b = idx / NCLS, cls = idx % NCLS;
    const float* pb = g_pool + b * CC;
    float acc = HB[cls];
    #pragma unroll 4
    for (int k = 0; k < CC; k++) acc += pb[k] * HW[(size_t)k * NCLS + cls];
    out[idx] = acc;
}

// ---------------- host orchestration ----------------
extern "C" void kernel_launch(void* const* d_in, const int* in_sizes, int n_in,
                              void* d_out, int out_size) {
    const float* x       = (const float*)d_in[0];
    const float* patch_w = (const float*)d_in[1];
    const float* patch_b = (const float*)d_in[2];
    const float* pos     = (const float*)d_in[3];
    const float* ln1_s   = (const float*)d_in[4];
    const float* ln1_b   = (const float*)d_in[5];
    const float* w_in    = (const float*)d_in[6];
    const float* b_in    = (const float*)d_in[7];
    const float* w_g     = (const float*)d_in[8];
    const float* b_g     = (const float*)d_in[9];
    const float* k_dw    = (const float*)d_in[10];
    const float* ln2_s   = (const float*)d_in[11];
    const float* ln2_b   = (const float*)d_in[12];
    const float* w1      = (const float*)d_in[13];
    const float* b1      = (const float*)d_in[14];
    const float* w2      = (const float*)d_in[15];
    const float* b2      = (const float*)d_in[16];
    const float* lnf_s   = (const float*)d_in[17];
    const float* lnf_b   = (const float*)d_in[18];
    const float* head_w  = (const float*)d_in[19];
    const float* head_b  = (const float*)d_in[20];
    float* out = (float*)d_out;

    float *ph;
    __half *zah, *zal, *hidh, *hidl, *wt;
    cudaGetSymbolAddress((void**)&ph,   g_h);
    cudaGetSymbolAddress((void**)&zah,  g_za_hi);
    cudaGetSymbolAddress((void**)&zal,  g_za_lo);
    cudaGetSymbolAddress((void**)&hidh, g_hid_hi);
    cudaGetSymbolAddress((void**)&hidl, g_hid_lo);
    cudaGetSymbolAddress((void**)&wt,   g_wt);

    cudaFuncSetAttribute(tgemm_kernel<2>, cudaFuncAttributeMaxDynamicSharedMemorySize, GEMM_SMEM);
    cudaFuncSetAttribute(tgemm_kernel<3>, cudaFuncAttributeMaxDynamicSharedMemorySize, GEMM_SMEM);
    cudaFuncSetAttribute(tgemm_kernel<4>, cudaFuncAttributeMaxDynamicSharedMemorySize, GEMM_SMEM);
    cudaFuncSetAttribute(tgemm_kernel<5>, cudaFuncAttributeMaxDynamicSharedMemorySize, GEMM_SMEM);

    const int NT = NTOK / 128;   // 49

    // weights -> transposed fp16
    convert_w_kernel<<<dim3(288, 1 + 4*DD), 256>>>(patch_w, w_in, w_g, w1, w2);

    // patch embed
    im2col_kernel<<<NTOK, 256>>>(x);
    tgemm_kernel<4><<<dim3(CC/128, NT), 256, GEMM_SMEM>>>(
        zah, zal, wt + OFF_PATCH, patch_b, ph, KI2C, CC, pos);

    for (int d = 0; d < DD; d++) {
        size_t wb = OFF_BLK0 + (size_t)d * PER_BLK;
        ln_kernel<true><<<NTOK, 128>>>(ln1_s + d*CC, ln1_b + d*CC);
        // fused u + gate GEMM over combined [768, 384] weight (w_in^T ++ w_g^T contiguous)
        tgemm_kernel<5><<<dim3((2*CC)/128, NT), 256, GEMM_SMEM>>>(
            zah, zal, wt + wb, b_in + d*CC, nullptr, CC, 2*CC, b_g + d*CC);
        recur_kernel<<<BATCH * (CC/32), 196>>>(k_dw + (size_t)d*9*CC);
        ln_kernel<true><<<NTOK, 128>>>(ln2_s + d*CC, ln2_b + d*CC);
        tgemm_kernel<2><<<dim3(HIDN/128, NT), 256, GEMM_SMEM>>>(
            zah, zal, wt + wb + 2*LEN_CXC, b1 + d*HIDN, nullptr, CC, HIDN, nullptr);
        tgemm_kernel<3><<<dim3(CC/128, NT), 256, GEMM_SMEM>>>(
            hidh, hidl, wt + wb + 2*LEN_CXC + LEN_W1, b2 + d*CC, ph, HIDN, CC, nullptr);
    }

    ln_kernel<false><<<NTOK, 128>>>(lnf_s, lnf_b);
    maxpool_kernel<<<BATCH, CC>>>();
    head_kernel<<<(BATCH*NCLS + 255) / 256, 256>>>(head_w, head_b, out);
}

// round 9
// speedup vs baseline: 2.6466x; 1.2425x over previous
#include <cuda_runtime.h>
#include <cuda_fp16.h>
#include <math.h>
#include <stdint.h>

// ---------------- problem constants ----------------
#define BATCH   32
#define IMGSZ   224
#define PATCH   16
#define CC      384
#define DD      12
#define TT      8
#define HIDN    1536
#define NCLS    1000
#define GRIDW   14
#define NTOK    (BATCH*GRIDW*GRIDW)   // 6272
#define KI2C    (PATCH*PATCH*3)       // 768

// weight scratch offsets (transposed [M,K] fp16)
#define OFF_PATCH   0
#define LEN_PATCH   (384*768)
#define OFF_BLK0    LEN_PATCH
#define LEN_CXC     (CC*CC)            // 147456
#define LEN_W1      (HIDN*CC)          // 589824
#define PER_BLK     (2*LEN_CXC + 2*LEN_W1)   // 1474560
#define WT_TOTAL    (OFF_BLK0 + DD*PER_BLK)  // 17989632

// ---------------- scratch (no allocations allowed) ----------------
__device__ float g_h   [(size_t)NTOK*CC];
__device__ float g_z   [(size_t)NTOK*CC];
__device__ float g_u   [(size_t)NTOK*CC];
__device__ float g_gate[(size_t)NTOK*CC];
__device__ float g_pool[(size_t)BATCH*CC];
__device__ __half g_za [(size_t)NTOK*KI2C];    // A operand (LN output / im2col)
__device__ __half g_hid[(size_t)NTOK*HIDN];    // MLP hidden
__device__ __half g_wt [(size_t)WT_TOTAL];     // transposed weights

// ---------------- small helpers ----------------
__device__ __forceinline__ float gelu_f(float x) {
    float x3 = x * x * x;
    float t  = tanhf(0.7978845608028654f * (x + 0.044715f * x3));
    return 0.5f * x * (1.0f + t);
}
__device__ __forceinline__ float sigmoid_f(float x) { return 1.0f / (1.0f + expf(-x)); }

__device__ __forceinline__ uint32_t smem_u32(const void* p) {
    uint32_t a;
    asm("{ .reg .u64 t; cvta.to.shared.u64 t, %1; cvt.u32.u64 %0, t; }" : "=r"(a) : "l"(p));
    return a;
}

#define CP16(dst, src)      asm volatile("cp.async.cg.shared.global [%0], [%1], 16;" :: "r"(dst), "l"(src))
#define CP_COMMIT()         asm volatile("cp.async.commit_group;" ::: "memory")

__device__ __forceinline__ void ldm4(uint32_t* r, uint32_t addr) {
    asm volatile("ldmatrix.sync.aligned.m8n8.x4.shared.b16 {%0,%1,%2,%3}, [%4];"
                 : "=r"(r[0]), "=r"(r[1]), "=r"(r[2]), "=r"(r[3]) : "r"(addr));
}
__device__ __forceinline__ void mma16816(float* c, const uint32_t* a, const uint32_t* b) {
    asm volatile("mma.sync.aligned.m16n8k16.row.col.f32.f16.f16.f32 "
                 "{%0,%1,%2,%3}, {%4,%5,%6,%7}, {%8,%9}, {%0,%1,%2,%3};"
                 : "+f"(c[0]), "+f"(c[1]), "+f"(c[2]), "+f"(c[3])
                 : "r"(a[0]), "r"(a[1]), "r"(a[2]), "r"(a[3]), "r"(b[0]), "r"(b[1]));
}

// ---------------- weight convert+transpose: fp32 [K,M] -> fp16 [M,K] ----------------
__global__ void convert_w_kernel(const float* __restrict__ patch_w,
                                 const float* __restrict__ w_in, const float* __restrict__ w_g,
                                 const float* __restrict__ w1, const float* __restrict__ w2) {
    int id = blockIdx.y;
    const float* src; int K, M; size_t dst;
    if (id == 0) { src = patch_w; K = KI2C; M = CC; dst = OFF_PATCH; }
    else {
        int d = (id - 1) >> 2, kind = (id - 1) & 3;
        size_t base = OFF_BLK0 + (size_t)d * PER_BLK;
        if      (kind == 0) { src = w_in + (size_t)d*CC*CC;   K = CC;   M = CC;   dst = base; }
        else if (kind == 1) { src = w_g  + (size_t)d*CC*CC;   K = CC;   M = CC;   dst = base + LEN_CXC; }
        else if (kind == 2) { src = w1   + (size_t)d*CC*HIDN; K = CC;   M = HIDN; dst = base + 2*LEN_CXC; }
        else                { src = w2   + (size_t)d*HIDN*CC; K = HIDN; M = CC;   dst = base + 2*LEN_CXC + LEN_W1; }
    }
    int total = K * M;
    for (int e = blockIdx.x * blockDim.x + threadIdx.x; e < total; e += gridDim.x * blockDim.x) {
        int m = e / K, k = e % K;
        g_wt[dst + e] = __float2half_rn(src[(size_t)k * M + m]);
    }
}

// ---------------- im2col -> fp16 ----------------
__global__ void im2col_kernel(const float* __restrict__ x) {
    int token = blockIdx.x;
    int b  = token / (GRIDW*GRIDW);
    int p  = token % (GRIDW*GRIDW);
    int gy = p / GRIDW, gx = p % GRIDW;
    for (int k = threadIdx.x; k < KI2C; k += blockDim.x) {
        int py = k / 48;
        int r  = k % 48;
        size_t src = ((size_t)(b*IMGSZ + gy*PATCH + py) * IMGSZ + gx*PATCH) * 3 + r;
        g_za[(size_t)token*KI2C + k] = __float2half_rn(x[src]);
    }
}

// ---------------- mma.sync GEMM: C[NTOK, M] = epi(A @ W^T + bias) ----------------
// A fp16 [rows,K]; W fp16 [M,K]. CTA 128x128, BK=32, 8 warps (2m x 4n),
// warp tile 64x32, single pass, 3-stage cp.async pipeline.
// SMEM rows 80B (32 fp16 + 16B pad) -> conflict-free ldmatrix.
// EPI: 2 gelu->g_hid ; 3 residual add ; 4 +bias+pos ; 5 fused u/gate
#define ROWB        80
#define TILEB       (128*ROWB)         // 10240
#define STAGEB      (2*TILEB)          // 20480 (A, B)
#define NSTAGE      3
#define GEMM_SMEM   (NSTAGE*STAGEB)    // 61440
#define OFF_B       TILEB

template<int EPI>
__global__ __launch_bounds__(256, 2)
void tgemm_kernel(const __half* __restrict__ Ah, const __half* __restrict__ Bw,
                  const float* __restrict__ bias, float* __restrict__ Cout,
                  int K, int M, const float* __restrict__ extra) {
    extern __shared__ char smem[];
    const uint32_t sb = smem_u32(smem);
    const int tid = threadIdx.x, wid = tid >> 5, lid = tid & 31;
    const int bn = blockIdx.x, bm = blockIdx.y;
    const int NC = K >> 5;
    const int wm = wid & 1, wn = wid >> 1;       // warp 64x32 tile coords

    auto load_chunk = [&](int c, int stage) {
        const int k0 = c * 32;
        const uint32_t sbase = sb + stage * STAGEB;
        #pragma unroll
        for (int j = 0; j < 2; j++) {
            int idx = tid + j * 256;
            int row = idx >> 2, seg = idx & 3;
            const size_t gra = (size_t)(bm * 128 + row) * K + k0 + seg * 8;
            const size_t grb = (size_t)(bn * 128 + row) * K + k0 + seg * 8;
            uint32_t so = row * ROWB + seg * 16;
            CP16(sbase + so,         Ah + gra);
            CP16(sbase + OFF_B + so, Bw + grb);
        }
        CP_COMMIT();
    };

    load_chunk(0, 0);
    if (NC > 1) load_chunk(1, 1);

    float acc[4][4][4];
    #pragma unroll
    for (int i = 0; i < 4; i++)
        #pragma unroll
        for (int j = 0; j < 4; j++)
            #pragma unroll
            for (int q = 0; q < 4; q++) acc[i][j][q] = 0.0f;

    const uint32_t arow = (uint32_t)(lid & 15);
    const uint32_t asel = (uint32_t)(lid >> 4);
    const uint32_t brow = (uint32_t)((lid & 7) + ((lid & 16) ? 8 : 0));
    const uint32_t bsel = (uint32_t)((lid >> 3) & 1);

    for (int c = 0; c < NC; c++) {
        if (c + 1 < NC) asm volatile("cp.async.wait_group 1;" ::: "memory");
        else            asm volatile("cp.async.wait_group 0;" ::: "memory");
        __syncthreads();
        if (c + 2 < NC) load_chunk(c + 2, (c + 2) % NSTAGE);

        const uint32_t st = sb + (c % NSTAGE) * STAGEB;
        #pragma unroll
        for (int ks = 0; ks < 2; ks++) {
            uint32_t b[4][2];
            #pragma unroll
            for (int ng = 0; ng < 2; ng++) {
                uint32_t r[4];
                ldm4(r, st + OFF_B + (wn*32 + ng*16 + brow) * ROWB + (ks*2 + bsel) * 16);
                b[ng*2+0][0] = r[0]; b[ng*2+0][1] = r[1];
                b[ng*2+1][0] = r[2]; b[ng*2+1][1] = r[3];
            }
            #pragma unroll
            for (int mf = 0; mf < 4; mf++) {
                uint32_t a[4];
                ldm4(a, st + (wm*64 + mf*16 + arow) * ROWB + (ks*2 + asel) * 16);
                #pragma unroll
                for (int nf = 0; nf < 4; nf++)
                    mma16816(acc[mf][nf], a, b[nf]);
            }
        }
    }

    // epilogue
    const int gr = lid >> 2, gc = lid & 3;
    #pragma unroll
    for (int mf = 0; mf < 4; mf++) {
        #pragma unroll
        for (int nf = 0; nf < 4; nf++) {
            const int col = bn * 128 + wn * 32 + nf * 8 + gc * 2;
            #pragma unroll
            for (int half = 0; half < 2; half++) {
                const int row = bm * 128 + wm * 64 + mf * 16 + gr + half * 8;
                float v0 = acc[mf][nf][half*2+0];
                float v1 = acc[mf][nf][half*2+1];
                if (EPI == 5) {
                    // fused u/gate: cols [0,384) -> u (+b_in), [384,768) -> sigmoid gate (+b_g)
                    if (col < CC) {
                        float2 bv = *reinterpret_cast<const float2*>(bias + col);
                        float2 o; o.x = v0 + bv.x; o.y = v1 + bv.y;
                        *reinterpret_cast<float2*>(&g_u[(size_t)row * CC + col]) = o;
                    } else {
                        int cg = col - CC;
                        float2 bv = *reinterpret_cast<const float2*>(extra + cg);
                        float2 o; o.x = sigmoid_f(v0 + bv.x); o.y = sigmoid_f(v1 + bv.y);
                        *reinterpret_cast<float2*>(&g_gate[(size_t)row * CC + cg]) = o;
                    }
                    continue;
                }
                {
                    float2 bv = *reinterpret_cast<const float2*>(bias + col);
                    v0 += bv.x; v1 += bv.y;
                }
                if (EPI == 2) {
                    v0 = gelu_f(v0); v1 = gelu_f(v1);
                    size_t ob = (size_t)row * M + col;
                    *reinterpret_cast<__half2*>(&g_hid[ob]) =
                        __halves2half2(__float2half_rn(v0), __float2half_rn(v1));
                    continue;
                }
                if (EPI == 4) {
                    int p = row % (GRIDW*GRIDW);
                    float2 pv = *reinterpret_cast<const float2*>(extra + (size_t)p * CC + col);
                    v0 += pv.x; v1 += pv.y;
                }
                float* cp = Cout + (size_t)row * M + col;
                if (EPI == 3) {
                    float2 rr = *reinterpret_cast<const float2*>(cp);
                    v0 += rr.x; v1 += rr.y;
                }
                float2 o; o.x = v0; o.y = v1;
                *reinterpret_cast<float2*>(cp) = o;
            }
        }
    }
}

// ---------------- LayerNorm: g_h -> (fp16 g_za) or (fp32 g_z) ----------------
template<bool PAIR>
__global__ __launch_bounds__(128)
void ln_kernel(const float* __restrict__ gamma, const float* __restrict__ beta) {
    int row = blockIdx.x;
    int t = threadIdx.x;
    const float* xr = g_h + (size_t)row * CC;
    float v0 = xr[t], v1 = xr[t + 128], v2 = xr[t + 256];
    float s = v0 + v1 + v2;
    float q = v0 * v0 + v1 * v1 + v2 * v2;
    #pragma unroll
    for (int o = 16; o; o >>= 1) {
        s += __shfl_down_sync(0xffffffffu, s, o);
        q += __shfl_down_sync(0xffffffffu, q, o);
    }
    __shared__ float ss[4], sq[4];
    __shared__ float mean_s, rs_s;
    if ((t & 31) == 0) { ss[t >> 5] = s; sq[t >> 5] = q; }
    __syncthreads();
    if (t == 0) {
        float S = ss[0] + ss[1] + ss[2] + ss[3];
        float Q = sq[0] + sq[1] + sq[2] + sq[3];
        float m = S * (1.0f / CC);
        float var = Q * (1.0f / CC) - m * m;
        mean_s = m;
        rs_s = rsqrtf(var + 1e-6f);
    }
    __syncthreads();
    float m = mean_s, r = rs_s;
    #pragma unroll
    for (int i = 0; i < 3; i++) {
        int c = t + i * 128;
        float v = (i == 0) ? v0 : (i == 1) ? v1 : v2;
        float y = (v - m) * r * gamma[c] + beta[c];
        if (PAIR) {
            g_za[(size_t)row * CC + c] = __float2half_rn(y);
        } else {
            g_z[(size_t)row * CC + c] = y;
        }
    }
}

// ---------------- gated depthwise-conv recurrence ----------------
__global__ __launch_bounds__(196)
void recur_kernel(const float* __restrict__ KD) {
    __shared__ float s[32][256];
    __shared__ float kds[9][32];

    int blk = blockIdx.x;
    int b  = blk / (CC / 32);
    int cg = blk % (CC / 32);
    int tid = threadIdx.x;
    int y = tid / GRIDW, x = tid % GRIDW;

    for (int i = tid; i < 32 * 256; i += 196) ((float*)s)[i] = 0.0f;
    for (int i = tid; i < 288; i += 196)
        ((float*)kds)[i] = KD[(i >> 5) * CC + cg * 32 + (i & 31)];

    size_t base = ((size_t)(b * (GRIDW*GRIDW) + tid)) * CC + cg * 32;
    float gg[32], u1[32], ns[32];
    #pragma unroll
    for (int c = 0; c < 32; c += 4) {
        float4 gv = *reinterpret_cast<const float4*>(g_gate + base + c);
        float4 uv = *reinterpret_cast<const float4*>(g_u + base + c);
        gg[c+0]=gv.x; gg[c+1]=gv.y; gg[c+2]=gv.z; gg[c+3]=gv.w;
        u1[c+0]=(1.0f-gv.x)*uv.x; u1[c+1]=(1.0f-gv.y)*uv.y;
        u1[c+2]=(1.0f-gv.z)*uv.z; u1[c+3]=(1.0f-gv.w)*uv.w;
    }
    __syncthreads();

    const int ip = (y + 1) * 16 + (x + 1);
    #pragma unroll
    for (int c = 0; c < 32; c++) s[c][ip] = u1[c];
    __syncthreads();

    for (int step = 0; step < TT - 1; step++) {
        #pragma unroll
        for (int c = 0; c < 32; c++) {
            const float* sc = s[c];
            float acc = kds[0][c]*sc[ip-17] + kds[1][c]*sc[ip-16] + kds[2][c]*sc[ip-15]
                      + kds[3][c]*sc[ip-1]  + kds[4][c]*sc[ip]    + kds[5][c]*sc[ip+1]
                      + kds[6][c]*sc[ip+15] + kds[7][c]*sc[ip+16] + kds[8][c]*sc[ip+17];
            ns[c] = gg[c] * acc + u1[c];
        }
        __syncthreads();
        #pragma unroll
        for (int c = 0; c < 32; c++) s[c][ip] = ns[c];
        __syncthreads();
    }

    #pragma unroll
    for (int c = 0; c < 32; c++) g_h[base + c] += s[c][ip];
}

// ---------------- final max pool over spatial ----------------
__global__ void maxpool_kernel() {
    int b = blockIdx.x, c = threadIdx.x;
    const float* zb = g_z + (size_t)b * (GRIDW*GRIDW) * CC + c;
    float m = -INFINITY;
    #pragma unroll 4
    for (int p = 0; p < GRIDW*GRIDW; p++) m = fmaxf(m, zb[(size_t)p * CC]);
    g_pool[b * CC + c] = m;
}

// ---------------- classification head ----------------
__global__ void head_kernel(const float* __restrict__ HW, const float* __restrict__ HB,
                            float* __restrict__ out) {
    int idx = blockIdx.x * blockDim.x + threadIdx.x;
    if (idx >= BATCH * NCLS) return;
    int b = idx / NCLS, cls = idx % NCLS;
    const float* pb = g_pool + b * CC;
    float acc = HB[cls];
    #pragma unroll 4
    for (int k = 0; k < CC; k++) acc += pb[k] * HW[(size_t)k * NCLS + cls];
    out[idx] = acc;
}

// ---------------- host orchestration ----------------
extern "C" void kernel_launch(void* const* d_in, const int* in_sizes, int n_in,
                              void* d_out, int out_size) {
    const float* x       = (const float*)d_in[0];
    const float* patch_w = (const float*)d_in[1];
    const float* patch_b = (const float*)d_in[2];
    const float* pos     = (const float*)d_in[3];
    const float* ln1_s   = (const float*)d_in[4];
    const float* ln1_b   = (const float*)d_in[5];
    const float* w_in    = (const float*)d_in[6];
    const float* b_in    = (const float*)d_in[7];
    const float* w_g     = (const float*)d_in[8];
    const float* b_g     = (const float*)d_in[9];
    const float* k_dw    = (const float*)d_in[10];
    const float* ln2_s   = (const float*)d_in[11];
    const float* ln2_b   = (const float*)d_in[12];
    const float* w1      = (const float*)d_in[13];
    const float* b1      = (const float*)d_in[14];
    const float* w2      = (const float*)d_in[15];
    const float* b2      = (const float*)d_in[16];
    const float* lnf_s   = (const float*)d_in[17];
    const float* lnf_b   = (const float*)d_in[18];
    const float* head_w  = (const float*)d_in[19];
    const float* head_b  = (const float*)d_in[20];
    float* out = (float*)d_out;

    float *ph;
    __half *za, *hid, *wt;
    cudaGetSymbolAddress((void**)&ph,  g_h);
    cudaGetSymbolAddress((void**)&za,  g_za);
    cudaGetSymbolAddress((void**)&hid, g_hid);
    cudaGetSymbolAddress((void**)&wt,  g_wt);

    cudaFuncSetAttribute(tgemm_kernel<2>, cudaFuncAttributeMaxDynamicSharedMemorySize, GEMM_SMEM);
    cudaFuncSetAttribute(tgemm_kernel<3>, cudaFuncAttributeMaxDynamicSharedMemorySize, GEMM_SMEM);
    cudaFuncSetAttribute(tgemm_kernel<4>, cudaFuncAttributeMaxDynamicSharedMemorySize, GEMM_SMEM);
    cudaFuncSetAttribute(tgemm_kernel<5>, cudaFuncAttributeMaxDynamicSharedMemorySize, GEMM_SMEM);

    const int NT = NTOK / 128;   // 49

    // weights -> transposed fp16
    convert_w_kernel<<<dim3(288, 1 + 4*DD), 256>>>(patch_w, w_in, w_g, w1, w2);

    // patch embed
    im2col_kernel<<<NTOK, 256>>>(x);
    tgemm_kernel<4><<<dim3(CC/128, NT), 256, GEMM_SMEM>>>(
        za, wt + OFF_PATCH, patch_b, ph, KI2C, CC, pos);

    for (int d = 0; d < DD; d++) {
        size_t wb = OFF_BLK0 + (size_t)d * PER_BLK;
        ln_kernel<true><<<NTOK, 128>>>(ln1_s + d*CC, ln1_b + d*CC);
        // fused u + gate GEMM over combined [768, 384] weight (w_in^T ++ w_g^T contiguous)
        tgemm_kernel<5><<<dim3((2*CC)/128, NT), 256, GEMM_SMEM>>>(
            za, wt + wb, b_in + d*CC, nullptr, CC, 2*CC, b_g + d*CC);
        recur_kernel<<<BATCH * (CC/32), 196>>>(k_dw + (size_t)d*9*CC);
        ln_kernel<true><<<NTOK, 128>>>(ln2_s + d*CC, ln2_b + d*CC);
        tgemm_kernel<2><<<dim3(HIDN/128, NT), 256, GEMM_SMEM>>>(
            za, wt + wb + 2*LEN_CXC, b1 + d*HIDN, nullptr, CC, HIDN, nullptr);
        tgemm_kernel<3><<<dim3(CC/128, NT), 256, GEMM_SMEM>>>(
            hid, wt + wb + 2*LEN_CXC + LEN_W1, b2 + d*CC, ph, HIDN, CC, nullptr);
    }

    ln_kernel<false><<<NTOK, 128>>>(lnf_s, lnf_b);
    maxpool_kernel<<<BATCH, CC>>>();
    head_kernel<<<(BATCH*NCLS + 255) / 256, 256>>>(head_w, head_b, out);
}

// round 10
// speedup vs baseline: 3.0492x; 1.1521x over previous
#include <cuda_runtime.h>
#include <cuda_fp16.h>
#include <math.h>
#include <stdint.h>

// ---------------- problem constants ----------------
#define BATCH   32
#define IMGSZ   224
#define PATCH   16
#define CC      384
#define DD      12
#define TT      8
#define HIDN    1536
#define NCLS    1000
#define GRIDW   14
#define NTOK    (BATCH*GRIDW*GRIDW)   // 6272
#define KI2C    (PATCH*PATCH*3)       // 768

// weight scratch offsets (elements; chunked [M/128][K/32] 8KB blocks)
#define OFF_PATCH   0
#define LEN_PATCH   (384*768)
#define OFF_BLK0    LEN_PATCH
#define LEN_CXC     (CC*CC)            // 147456
#define LEN_W1      (HIDN*CC)          // 589824
#define PER_BLK     (2*LEN_CXC + 2*LEN_W1)   // 1474560
#define WT_TOTAL    (OFF_BLK0 + DD*PER_BLK)  // 17989632

// ---------------- scratch (no allocations allowed) ----------------
__device__ float g_h   [(size_t)NTOK*CC];
__device__ float g_z   [(size_t)NTOK*CC];
__device__ float g_u   [(size_t)NTOK*CC];
__device__ float g_gate[(size_t)NTOK*CC];
__device__ float g_pool[(size_t)BATCH*CC];
__device__ __half g_za [(size_t)NTOK*KI2C];    // A operand, chunked layout
__device__ __half g_hid[(size_t)NTOK*HIDN];    // MLP hidden, chunked layout
__device__ __half g_wt [(size_t)WT_TOTAL];     // weights, chunked layout

// ---------------- chunked layout ----------------
// chunk = 128 rows x 32 k fp16 = 8192 bytes, contiguous.
// in-chunk byte offset: row*64 + ((seg ^ ((row>>1)&3))<<4) + (k&7)*2, seg=(k>>3)&3
// -> 8 consecutive rows at fixed seg occupy 8 distinct 16B slots mod 128 (ldmatrix conflict-free)
__device__ __forceinline__ size_t coff(int row, int k, int Kdim) {
    int rk = row & 127;
    int seg = (k >> 3) & 3, col = k & 7;
    return (((size_t)((row >> 7) * (Kdim >> 5) + (k >> 5))) << 13)
         + (uint32_t)(rk * 64 + ((seg ^ ((rk >> 1) & 3)) << 4) + col * 2);
}

// ---------------- small helpers ----------------
__device__ __forceinline__ float gelu_f(float x) {
    float x3 = x * x * x;
    float t  = tanhf(0.7978845608028654f * (x + 0.044715f * x3));
    return 0.5f * x * (1.0f + t);
}
__device__ __forceinline__ float sigmoid_f(float x) { return 1.0f / (1.0f + expf(-x)); }

__device__ __forceinline__ uint32_t smem_u32(const void* p) {
    uint32_t a;
    asm("{ .reg .u64 t; cvta.to.shared.u64 t, %1; cvt.u32.u64 %0, t; }" : "=r"(a) : "l"(p));
    return a;
}
__device__ __forceinline__ uint32_t packh2(float a, float b) {
    __half2 h = __halves2half2(__float2half_rn(a), __float2half_rn(b));
    return *reinterpret_cast<uint32_t*>(&h);
}

#define MBAR_INIT(a, c)  asm volatile("mbarrier.init.shared.b64 [%0], %1;" :: "r"(a), "r"(c) : "memory")
#define MBAR_EXPECT(a, tx) asm volatile("mbarrier.arrive.expect_tx.shared.b64 _, [%0], %1;" :: "r"(a), "r"(tx) : "memory")

__device__ __forceinline__ void bulk_ld(uint32_t dst, const void* src, uint32_t bytes, uint32_t mbar) {
    asm volatile("cp.async.bulk.shared::cluster.global.mbarrier::complete_tx::bytes [%0], [%1], %2, [%3];"
                 :: "r"(dst), "l"(src), "r"(bytes), "r"(mbar) : "memory");
}

__device__ __forceinline__ void mbar_wait(uint32_t mbar, uint32_t parity) {
    uint32_t done;
    asm volatile("{\n\t.reg .pred p;\n\t"
                 "mbarrier.try_wait.parity.acquire.cta.shared::cta.b64 p, [%1], %2;\n\t"
                 "selp.b32 %0, 1, 0, p;\n\t}"
                 : "=r"(done) : "r"(mbar), "r"(parity) : "memory");
    if (!done) {
        asm volatile("{\n\t.reg .pred P1;\n\t"
                     "WL_%=:\n\t"
                     "mbarrier.try_wait.parity.acquire.cta.shared::cta.b64 P1, [%0], %1, 0x989680;\n\t"
                     "@P1 bra.uni WD_%=;\n\t"
                     "bra.uni WL_%=;\n\t"
                     "WD_%=:\n\t}" :: "r"(mbar), "r"(parity) : "memory");
    }
}

__device__ __forceinline__ void ldm4(uint32_t* r, uint32_t addr) {
    asm volatile("ldmatrix.sync.aligned.m8n8.x4.shared.b16 {%0,%1,%2,%3}, [%4];"
                 : "=r"(r[0]), "=r"(r[1]), "=r"(r[2]), "=r"(r[3]) : "r"(addr));
}
__device__ __forceinline__ void mma16816(float* c, const uint32_t* a, const uint32_t* b) {
    asm volatile("mma.sync.aligned.m16n8k16.row.col.f32.f16.f16.f32 "
                 "{%0,%1,%2,%3}, {%4,%5,%6,%7}, {%8,%9}, {%0,%1,%2,%3};"
                 : "+f"(c[0]), "+f"(c[1]), "+f"(c[2]), "+f"(c[3])
                 : "r"(a[0]), "r"(a[1]), "r"(a[2]), "r"(a[3]), "r"(b[0]), "r"(b[1]));
}

// ---------------- weight convert+transpose into chunked layout ----------------
// One block builds one 8KB chunk: reads 32 k-rows x 128 m of fp32 [K,M] (coalesced),
// stages the swizzled chunk in SMEM, writes it out linearly (coalesced).
__global__ __launch_bounds__(256)
void convert_w_kernel(const float* __restrict__ patch_w,
                      const float* __restrict__ w_in, const float* __restrict__ w_g,
                      const float* __restrict__ w1, const float* __restrict__ w2) {
    int id = blockIdx.y;
    const float* src; int K, M; size_t dstel;
    if (id == 0) { src = patch_w; K = KI2C; M = CC; dstel = OFF_PATCH; }
    else {
        int d = (id - 1) >> 2, kind = (id - 1) & 3;
        size_t base = OFF_BLK0 + (size_t)d * PER_BLK;
        if      (kind == 0) { src = w_in + (size_t)d*CC*CC;   K = CC;   M = CC;   dstel = base; }
        else if (kind == 1) { src = w_g  + (size_t)d*CC*CC;   K = CC;   M = CC;   dstel = base + LEN_CXC; }
        else if (kind == 2) { src = w1   + (size_t)d*CC*HIDN; K = CC;   M = HIDN; dstel = base + 2*LEN_CXC; }
        else                { src = w2   + (size_t)d*HIDN*CC; K = HIDN; M = CC;   dstel = base + 2*LEN_CXC + LEN_W1; }
    }
    int nch = (M >> 7) * (K >> 5);
    int ch = blockIdx.x;
    if (ch >= nch) return;
    int mt = ch / (K >> 5), kc = ch % (K >> 5);

    __shared__ __half hs[4096];
    int tid = threadIdx.x;
    #pragma unroll
    for (int it = 0; it < 16; it++) {
        int e = tid + it * 256;          // e = kk*128 + rm
        int kk = e >> 7, rm = e & 127;
        float v = src[(size_t)(kc*32 + kk) * M + mt*128 + rm];
        int seg = kk >> 3, col = kk & 7;
        hs[rm*32 + ((seg ^ ((rm >> 1) & 3)) << 3) + col] = __float2half_rn(v);
    }
    __syncthreads();
    uint4* dst = reinterpret_cast<uint4*>(reinterpret_cast<uint8_t*>(g_wt) + dstel*2 + (size_t)ch*8192);
    const uint4* s4 = reinterpret_cast<const uint4*>(hs);
    dst[tid] = s4[tid];
    dst[tid + 256] = s4[tid + 256];
}

// ---------------- im2col -> fp16 chunked ----------------
__global__ void im2col_kernel(const float* __restrict__ x) {
    int token = blockIdx.x;
    int b  = token / (GRIDW*GRIDW);
    int p  = token % (GRIDW*GRIDW);
    int gy = p / GRIDW, gx = p % GRIDW;
    uint8_t* za = reinterpret_cast<uint8_t*>(g_za);
    for (int k = threadIdx.x; k < KI2C; k += blockDim.x) {
        int py = k / 48;
        int r  = k % 48;
        size_t src = ((size_t)(b*IMGSZ + gy*PATCH + py) * IMGSZ + gx*PATCH) * 3 + r;
        *reinterpret_cast<__half*>(za + coff(token, k, KI2C)) = __float2half_rn(x[src]);
    }
}

// ---------------- bulk-copy GEMM: C[NTOK, M] = epi(A @ W^T + bias) ----------------
// A, B in chunked fp16 layout. CTA 128x128, BK=32, 8 warps (2m x 4n), warp 64x32.
// 4-stage cp.async.bulk pipeline, mbarrier completion.
// EPI: 2 gelu->g_hid(chunked) ; 3 residual add ; 4 +bias+pos ; 5 fused u/gate
#define CHUNKB  8192
#define STAGEB  (2*CHUNKB)
#define NSTAGE  4
#define GEMM_SMEM (NSTAGE*STAGEB + 64)   // 65600

template<int EPI>
__global__ __launch_bounds__(256, 2)
void tgemm_kernel(const uint8_t* __restrict__ Ab, const uint8_t* __restrict__ Bb,
                  const float* __restrict__ bias, float* __restrict__ Cout,
                  int K, int M, const float* __restrict__ extra) {
    extern __shared__ char smem[];
    const uint32_t sb  = smem_u32(smem);
    const uint32_t mb0 = sb + NSTAGE*STAGEB;
    const int tid = threadIdx.x, wid = tid >> 5, lid = tid & 31;
    const int bn = blockIdx.x, bm = blockIdx.y;
    const int NC = K >> 5;
    const int wm = wid & 1, wn = wid >> 1;

    if (tid == 0) {
        #pragma unroll
        for (int s = 0; s < NSTAGE; s++) MBAR_INIT(mb0 + s*8, 1);
    }
    __syncthreads();

    auto issue = [&](int c, int s) {
        uint32_t mb = mb0 + s*8;
        MBAR_EXPECT(mb, 2*CHUNKB);
        bulk_ld(sb + s*STAGEB,          Ab + ((size_t)bm*NC + c)*CHUNKB, CHUNKB, mb);
        bulk_ld(sb + s*STAGEB + CHUNKB, Bb + ((size_t)bn*NC + c)*CHUNKB, CHUNKB, mb);
    };
    if (tid == 0) { issue(0,0); issue(1,1); issue(2,2); }    // NC >= 12 always

    float acc[4][4][4];
    #pragma unroll
    for (int i = 0; i < 4; i++)
        #pragma unroll
        for (int j = 0; j < 4; j++)
            #pragma unroll
            for (int q = 0; q < 4; q++) acc[i][j][q] = 0.0f;

    const int arow = lid & 15;
    const int asel = lid >> 4;
    const int brow = (lid & 7) + ((lid & 16) ? 8 : 0);
    const int bsel = (lid >> 3) & 1;

    for (int c = 0; c < NC; c++) {
        const int s = c & 3;
        mbar_wait(mb0 + s*8, (uint32_t)((c >> 2) & 1));
        const uint32_t stA = sb + s*STAGEB;
        const uint32_t stB = stA + CHUNKB;

        #pragma unroll
        for (int ks = 0; ks < 2; ks++) {
            uint32_t b[4][2];
            #pragma unroll
            for (int ng = 0; ng < 2; ng++) {
                int row = wn*32 + ng*16 + brow;
                int seg = ks*2 + bsel;
                uint32_t r[4];
                ldm4(r, stB + row*64 + ((seg ^ ((row >> 1) & 3)) << 4));
                b[ng*2+0][0] = r[0]; b[ng*2+0][1] = r[1];
                b[ng*2+1][0] = r[2]; b[ng*2+1][1] = r[3];
            }
            #pragma unroll
            for (int mf = 0; mf < 4; mf++) {
                int row = wm*64 + mf*16 + arow;
                int seg = ks*2 + asel;
                uint32_t a[4];
                ldm4(a, stA + row*64 + ((seg ^ ((row >> 1) & 3)) << 4));
                #pragma unroll
                for (int nf = 0; nf < 4; nf++)
                    mma16816(acc[mf][nf], a, b[nf]);
            }
        }
        __syncthreads();
        if (tid == 0 && c + 3 < NC) issue(c + 3, (c + 3) & 3);
    }

    // epilogue
    const int gr = lid >> 2, gc = lid & 3;
    uint8_t* hidb = reinterpret_cast<uint8_t*>(g_hid);
    #pragma unroll
    for (int mf = 0; mf < 4; mf++) {
        #pragma unroll
        for (int nf = 0; nf < 4; nf++) {
            const int col = bn * 128 + wn * 32 + nf * 8 + gc * 2;
            #pragma unroll
            for (int half = 0; half < 2; half++) {
                const int row = bm * 128 + wm * 64 + mf * 16 + gr + half * 8;
                float v0 = acc[mf][nf][half*2+0];
                float v1 = acc[mf][nf][half*2+1];
                if (EPI == 5) {
                    if (col < CC) {
                        float2 bv = *reinterpret_cast<const float2*>(bias + col);
                        float2 o; o.x = v0 + bv.x; o.y = v1 + bv.y;
                        *reinterpret_cast<float2*>(&g_u[(size_t)row * CC + col]) = o;
                    } else {
                        int cg = col - CC;
                        float2 bv = *reinterpret_cast<const float2*>(extra + cg);
                        float2 o; o.x = sigmoid_f(v0 + bv.x); o.y = sigmoid_f(v1 + bv.y);
                        *reinterpret_cast<float2*>(&g_gate[(size_t)row * CC + cg]) = o;
                    }
                    continue;
                }
                {
                    float2 bv = *reinterpret_cast<const float2*>(bias + col);
                    v0 += bv.x; v1 += bv.y;
                }
                if (EPI == 2) {
                    v0 = gelu_f(v0); v1 = gelu_f(v1);
                    *reinterpret_cast<uint32_t*>(hidb + coff(row, col, HIDN)) = packh2(v0, v1);
                    continue;
                }
                if (EPI == 4) {
                    int p = row % (GRIDW*GRIDW);
                    float2 pv = *reinterpret_cast<const float2*>(extra + (size_t)p * CC + col);
                    v0 += pv.x; v1 += pv.y;
                }
                float* cp = Cout + (size_t)row * M + col;
                if (EPI == 3) {
                    float2 rr = *reinterpret_cast<const float2*>(cp);
                    v0 += rr.x; v1 += rr.y;
                }
                float2 o; o.x = v0; o.y = v1;
                *reinterpret_cast<float2*>(cp) = o;
            }
        }
    }
}

// ---------------- LayerNorm (warp per row): g_h -> chunked fp16 g_za or fp32 g_z ----------------
template<bool PAIR>
__global__ __launch_bounds__(256)
void ln_kernel(const float* __restrict__ gamma, const float* __restrict__ beta) {
    int row = blockIdx.x * 8 + (threadIdx.x >> 5);
    int lane = threadIdx.x & 31;
    const float* xr = g_h + (size_t)row * CC;
    float4 v[3];
    float s = 0.0f, q = 0.0f;
    #pragma unroll
    for (int i = 0; i < 3; i++) {
        v[i] = *reinterpret_cast<const float4*>(xr + lane*4 + i*128);
        s += v[i].x + v[i].y + v[i].z + v[i].w;
        q += v[i].x*v[i].x + v[i].y*v[i].y + v[i].z*v[i].z + v[i].w*v[i].w;
    }
    #pragma unroll
    for (int o = 16; o; o >>= 1) {
        s += __shfl_xor_sync(0xffffffffu, s, o);
        q += __shfl_xor_sync(0xffffffffu, q, o);
    }
    float m = s * (1.0f / CC);
    float r = rsqrtf(q * (1.0f / CC) - m*m + 1e-6f);
    uint8_t* za = reinterpret_cast<uint8_t*>(g_za);
    #pragma unroll
    for (int i = 0; i < 3; i++) {
        int k = lane*4 + i*128;
        float4 g4 = *reinterpret_cast<const float4*>(gamma + k);
        float4 b4 = *reinterpret_cast<const float4*>(beta + k);
        float y0 = (v[i].x - m) * r * g4.x + b4.x;
        float y1 = (v[i].y - m) * r * g4.y + b4.y;
        float y2 = (v[i].z - m) * r * g4.z + b4.z;
        float y3 = (v[i].w - m) * r * g4.w + b4.w;
        if (PAIR) {
            uint2 p; p.x = packh2(y0, y1); p.y = packh2(y2, y3);
            *reinterpret_cast<uint2*>(za + coff(row, k, CC)) = p;
        } else {
            float4 o; o.x = y0; o.y = y1; o.z = y2; o.w = y3;
            *reinterpret_cast<float4*>(g_z + (size_t)row * CC + k) = o;
        }
    }
}

// ---------------- gated depthwise-conv recurrence ----------------
__global__ __launch_bounds__(196)
void recur_kernel(const float* __restrict__ KD) {
    __shared__ float s[32][256];
    __shared__ float kds[9][32];

    int blk = blockIdx.x;
    int b  = blk / (CC / 32);
    int cg = blk % (CC / 32);
    int tid = threadIdx.x;
    int y = tid / GRIDW, x = tid % GRIDW;

    for (int i = tid; i < 32 * 256; i += 196) ((float*)s)[i] = 0.0f;
    for (int i = tid; i < 288; i += 196)
        ((float*)kds)[i] = KD[(i >> 5) * CC + cg * 32 + (i & 31)];

    size_t base = ((size_t)(b * (GRIDW*GRIDW) + tid)) * CC + cg * 32;
    float gg[32], u1[32], ns[32];
    #pragma unroll
    for (int c = 0; c < 32; c += 4) {
        float4 gv = *reinterpret_cast<const float4*>(g_gate + base + c);
        float4 uv = *reinterpret_cast<const float4*>(g_u + base + c);
        gg[c+0]=gv.x; gg[c+1]=gv.y; gg[c+2]=gv.z; gg[c+3]=gv.w;
        u1[c+0]=(1.0f-gv.x)*uv.x; u1[c+1]=(1.0f-gv.y)*uv.y;
        u1[c+2]=(1.0f-gv.z)*uv.z; u1[c+3]=(1.0f-gv.w)*uv.w;
    }
    __syncthreads();

    const int ip = (y + 1) * 16 + (x + 1);
    #pragma unroll
    for (int c = 0; c < 32; c++) s[c][ip] = u1[c];
    __syncthreads();

    for (int step = 0; step < TT - 1; step++) {
        #pragma unroll
        for (int c = 0; c < 32; c++) {
            const float* sc = s[c];
            float acc = kds[0][c]*sc[ip-17] + kds[1][c]*sc[ip-16] + kds[2][c]*sc[ip-15]
                      + kds[3][c]*sc[ip-1]  + kds[4][c]*sc[ip]    + kds[5][c]*sc[ip+1]
                      + kds[6][c]*sc[ip+15] + kds[7][c]*sc[ip+16] + kds[8][c]*sc[ip+17];
            ns[c] = gg[c] * acc + u1[c];
        }
        __syncthreads();
        #pragma unroll
        for (int c = 0; c < 32; c++) s[c][ip] = ns[c];
        __syncthreads();
    }

    #pragma unroll
    for (int c = 0; c < 32; c++) g_h[base + c] += s[c][ip];
}

// ---------------- final max pool over spatial ----------------
__global__ void maxpool_kernel() {
    int b = blockIdx.x, c = threadIdx.x;
    const float* zb = g_z + (size_t)b * (GRIDW*GRIDW) * CC + c;
    float m = -INFINITY;
    #pragma unroll 4
    for (int p = 0; p < GRIDW*GRIDW; p++) m = fmaxf(m, zb[(size_t)p * CC]);
    g_pool[b * CC + c] = m;
}

// ---------------- classification head ----------------
__global__ void head_kernel(const float* __restrict__ HW, const float* __restrict__ HB,
                            float* __restrict__ out) {
    int idx = blockIdx.x * blockDim.x + threadIdx.x;
    if (idx >= BATCH * NCLS) return;
    int b = idx / NCLS, cls = idx % NCLS;
    const float* pb = g_pool + b * CC;
    float acc = HB[cls];
    #pragma unroll 4
    for (int k = 0; k < CC; k++) acc += pb[k] * HW[(size_t)k * NCLS + cls];
    out[idx] = acc;
}

// ---------------- host orchestration ----------------
extern "C" void kernel_launch(void* const* d_in, const int* in_sizes, int n_in,
                              void* d_out, int out_size) {
    const float* x       = (const float*)d_in[0];
    const float* patch_w = (const float*)d_in[1];
    const float* patch_b = (const float*)d_in[2];
    const float* pos     = (const float*)d_in[3];
    const float* ln1_s   = (const float*)d_in[4];
    const float* ln1_b   = (const float*)d_in[5];
    const float* w_in    = (const float*)d_in[6];
    const float* b_in    = (const float*)d_in[7];
    const float* w_g     = (const float*)d_in[8];
    const float* b_g     = (const float*)d_in[9];
    const float* k_dw    = (const float*)d_in[10];
    const float* ln2_s   = (const float*)d_in[11];
    const float* ln2_b   = (const float*)d_in[12];
    const float* w1      = (const float*)d_in[13];
    const float* b1      = (const float*)d_in[14];
    const float* w2      = (const float*)d_in[15];
    const float* b2      = (const float*)d_in[16];
    const float* lnf_s   = (const float*)d_in[17];
    const float* lnf_b   = (const float*)d_in[18];
    const float* head_w  = (const float*)d_in[19];
    const float* head_b  = (const float*)d_in[20];
    float* out = (float*)d_out;

    float *ph;
    uint8_t *za, *hid, *wt;
    cudaGetSymbolAddress((void**)&ph,  g_h);
    cudaGetSymbolAddress((void**)&za,  g_za);
    cudaGetSymbolAddress((void**)&hid, g_hid);
    cudaGetSymbolAddress((void**)&wt,  g_wt);

    cudaFuncSetAttribute(tgemm_kernel<2>, cudaFuncAttributeMaxDynamicSharedMemorySize, GEMM_SMEM);
    cudaFuncSetAttribute(tgemm_kernel<3>, cudaFuncAttributeMaxDynamicSharedMemorySize, GEMM_SMEM);
    cudaFuncSetAttribute(tgemm_kernel<4>, cudaFuncAttributeMaxDynamicSharedMemorySize, GEMM_SMEM);
    cudaFuncSetAttribute(tgemm_kernel<5>, cudaFuncAttributeMaxDynamicSharedMemorySize, GEMM_SMEM);

    const int NT = NTOK / 128;   // 49

    // weights -> chunked fp16 (max chunks per weight = 144)
    convert_w_kernel<<<dim3(144, 1 + 4*DD), 256>>>(patch_w, w_in, w_g, w1, w2);

    // patch embed
    im2col_kernel<<<NTOK, 256>>>(x);
    tgemm_kernel<4><<<dim3(CC/128, NT), 256, GEMM_SMEM>>>(
        za, wt + (size_t)OFF_PATCH*2, patch_b, ph, KI2C, CC, pos);

    for (int d = 0; d < DD; d++) {
        size_t wb = ((size_t)OFF_BLK0 + (size_t)d * PER_BLK) * 2;
        ln_kernel<true><<<NTOK/8, 256>>>(ln1_s + d*CC, ln1_b + d*CC);
        // fused u + gate GEMM over combined [768, 384] chunked weight
        tgemm_kernel<5><<<dim3((2*CC)/128, NT), 256, GEMM_SMEM>>>(
            za, wt + wb, b_in + d*CC, nullptr, CC, 2*CC, b_g + d*CC);
        recur_kernel<<<BATCH * (CC/32), 196>>>(k_dw + (size_t)d*9*CC);
        ln_kernel<true><<<NTOK/8, 256>>>(ln2_s + d*CC, ln2_b + d*CC);
        tgemm_kernel<2><<<dim3(HIDN/128, NT), 256, GEMM_SMEM>>>(
            za, wt + wb + (size_t)2*LEN_CXC*2, b1 + d*HIDN, nullptr, CC, HIDN, nullptr);
        tgemm_kernel<3><<<dim3(CC/128, NT), 256, GEMM_SMEM>>>(
            hid, wt + wb + (size_t)(2*LEN_CXC + LEN_W1)*2, b2 + d*CC, ph, HIDN, CC, nullptr);
    }

    ln_kernel<false><<<NTOK/8, 256>>>(lnf_s, lnf_b);
    maxpool_kernel<<<BATCH, CC>>>();
    head_kernel<<<(BATCH*NCLS + 255) / 256, 256>>>(head_w, head_b, out);
}

// round 11
// speedup vs baseline: 3.9938x; 1.3098x over previous
#include <cuda_runtime.h>
#include <cuda_fp16.h>
#include <math.h>
#include <stdint.h>

// ---------------- problem constants ----------------
#define BATCH   32
#define IMGSZ   224
#define PATCH   16
#define CC      384
#define DD      12
#define TT      8
#define HIDN    1536
#define NCLS    1000
#define GRIDW   14
#define NTOK    (BATCH*GRIDW*GRIDW)   // 6272
#define KI2C    (PATCH*PATCH*3)       // 768

// weight scratch offsets (elements; chunked [M/128][K/32] 8KB blocks)
#define OFF_PATCH   0
#define LEN_PATCH   (384*768)
#define OFF_BLK0    LEN_PATCH
#define LEN_CXC     (CC*CC)            // 147456
#define LEN_W1      (HIDN*CC)          // 589824
#define PER_BLK     (2*LEN_CXC + 2*LEN_W1)   // 1474560
#define WT_TOTAL    (OFF_BLK0 + DD*PER_BLK)  // 17989632

// ---------------- scratch (no allocations allowed) ----------------
__device__ float g_h   [(size_t)NTOK*CC];
__device__ float g_z   [(size_t)NTOK*CC];
__device__ float g_u   [(size_t)NTOK*CC];
__device__ float g_gate[(size_t)NTOK*CC];
__device__ float g_pool[(size_t)BATCH*CC];
__device__ __half g_za [(size_t)NTOK*KI2C];    // A operand, chunked layout
__device__ __half g_hid[(size_t)NTOK*HIDN];    // MLP hidden, chunked layout
__device__ __half g_wt [(size_t)WT_TOTAL];     // weights, chunked layout

// ---------------- chunked layout ----------------
__device__ __forceinline__ size_t coff(int row, int k, int Kdim) {
    int rk = row & 127;
    int seg = (k >> 3) & 3, col = k & 7;
    return (((size_t)((row >> 7) * (Kdim >> 5) + (k >> 5))) << 13)
         + (uint32_t)(rk * 64 + ((seg ^ ((rk >> 1) & 3)) << 4) + col * 2);
}

// ---------------- small helpers ----------------
__device__ __forceinline__ float gelu_f(float x) {
    float x3 = x * x * x;
    float t  = tanhf(0.7978845608028654f * (x + 0.044715f * x3));
    return 0.5f * x * (1.0f + t);
}
__device__ __forceinline__ float sigmoid_f(float x) { return 1.0f / (1.0f + expf(-x)); }

__device__ __forceinline__ uint32_t smem_u32(const void* p) {
    uint32_t a;
    asm("{ .reg .u64 t; cvta.to.shared.u64 t, %1; cvt.u32.u64 %0, t; }" : "=r"(a) : "l"(p));
    return a;
}
__device__ __forceinline__ uint32_t packh2(float a, float b) {
    __half2 h = __halves2half2(__float2half_rn(a), __float2half_rn(b));
    return *reinterpret_cast<uint32_t*>(&h);
}
__device__ __forceinline__ float4 fma4(float4 a, float4 b, float4 c) {
    float4 r;
    r.x = fmaf(a.x, b.x, c.x); r.y = fmaf(a.y, b.y, c.y);
    r.z = fmaf(a.z, b.z, c.z); r.w = fmaf(a.w, b.w, c.w);
    return r;
}

#define MBAR_INIT(a, c)  asm volatile("mbarrier.init.shared.b64 [%0], %1;" :: "r"(a), "r"(c) : "memory")
#define MBAR_EXPECT(a, tx) asm volatile("mbarrier.arrive.expect_tx.shared.b64 _, [%0], %1;" :: "r"(a), "r"(tx) : "memory")

__device__ __forceinline__ void bulk_ld(uint32_t dst, const void* src, uint32_t bytes, uint32_t mbar) {
    asm volatile("cp.async.bulk.shared::cluster.global.mbarrier::complete_tx::bytes [%0], [%1], %2, [%3];"
                 :: "r"(dst), "l"(src), "r"(bytes), "r"(mbar) : "memory");
}

__device__ __forceinline__ void mbar_wait(uint32_t mbar, uint32_t parity) {
    uint32_t done;
    asm volatile("{\n\t.reg .pred p;\n\t"
                 "mbarrier.try_wait.parity.acquire.cta.shared::cta.b64 p, [%1], %2;\n\t"
                 "selp.b32 %0, 1, 0, p;\n\t}"
                 : "=r"(done) : "r"(mbar), "r"(parity) : "memory");
    if (!done) {
        asm volatile("{\n\t.reg .pred P1;\n\t"
                     "WL_%=:\n\t"
                     "mbarrier.try_wait.parity.acquire.cta.shared::cta.b64 P1, [%0], %1, 0x989680;\n\t"
                     "@P1 bra.uni WD_%=;\n\t"
                     "bra.uni WL_%=;\n\t"
                     "WD_%=:\n\t}" :: "r"(mbar), "r"(parity) : "memory");
    }
}

__device__ __forceinline__ void ldm4(uint32_t* r, uint32_t addr) {
    asm volatile("ldmatrix.sync.aligned.m8n8.x4.shared.b16 {%0,%1,%2,%3}, [%4];"
                 : "=r"(r[0]), "=r"(r[1]), "=r"(r[2]), "=r"(r[3]) : "r"(addr));
}
__device__ __forceinline__ void mma16816(float* c, const uint32_t* a, const uint32_t* b) {
    asm volatile("mma.sync.aligned.m16n8k16.row.col.f32.f16.f16.f32 "
                 "{%0,%1,%2,%3}, {%4,%5,%6,%7}, {%8,%9}, {%0,%1,%2,%3};"
                 : "+f"(c[0]), "+f"(c[1]), "+f"(c[2]), "+f"(c[3])
                 : "r"(a[0]), "r"(a[1]), "r"(a[2]), "r"(a[3]), "r"(b[0]), "r"(b[1]));
}

// ---------------- weight convert+transpose into chunked layout ----------------
__global__ __launch_bounds__(256)
void convert_w_kernel(const float* __restrict__ patch_w,
                      const float* __restrict__ w_in, const float* __restrict__ w_g,
                      const float* __restrict__ w1, const float* __restrict__ w2) {
    int id = blockIdx.y;
    const float* src; int K, M; size_t dstel;
    if (id == 0) { src = patch_w; K = KI2C; M = CC; dstel = OFF_PATCH; }
    else {
        int d = (id - 1) >> 2, kind = (id - 1) & 3;
        size_t base = OFF_BLK0 + (size_t)d * PER_BLK;
        if      (kind == 0) { src = w_in + (size_t)d*CC*CC;   K = CC;   M = CC;   dstel = base; }
        else if (kind == 1) { src = w_g  + (size_t)d*CC*CC;   K = CC;   M = CC;   dstel = base + LEN_CXC; }
        else if (kind == 2) { src = w1   + (size_t)d*CC*HIDN; K = CC;   M = HIDN; dstel = base + 2*LEN_CXC; }
        else                { src = w2   + (size_t)d*HIDN*CC; K = HIDN; M = CC;   dstel = base + 2*LEN_CXC + LEN_W1; }
    }
    int nch = (M >> 7) * (K >> 5);
    int ch = blockIdx.x;
    if (ch >= nch) return;
    int mt = ch / (K >> 5), kc = ch % (K >> 5);

    __shared__ __half hs[4096];
    int tid = threadIdx.x;
    #pragma unroll
    for (int it = 0; it < 16; it++) {
        int e = tid + it * 256;
        int kk = e >> 7, rm = e & 127;
        float v = src[(size_t)(kc*32 + kk) * M + mt*128 + rm];
        int seg = kk >> 3, col = kk & 7;
        hs[rm*32 + ((seg ^ ((rm >> 1) & 3)) << 3) + col] = __float2half_rn(v);
    }
    __syncthreads();
    uint4* dst = reinterpret_cast<uint4*>(reinterpret_cast<uint8_t*>(g_wt) + dstel*2 + (size_t)ch*8192);
    const uint4* s4 = reinterpret_cast<const uint4*>(hs);
    dst[tid] = s4[tid];
    dst[tid + 256] = s4[tid + 256];
}

// ---------------- im2col -> fp16 chunked ----------------
__global__ void im2col_kernel(const float* __restrict__ x) {
    int token = blockIdx.x;
    int b  = token / (GRIDW*GRIDW);
    int p  = token % (GRIDW*GRIDW);
    int gy = p / GRIDW, gx = p % GRIDW;
    uint8_t* za = reinterpret_cast<uint8_t*>(g_za);
    for (int k = threadIdx.x; k < KI2C; k += blockDim.x) {
        int py = k / 48;
        int r  = k % 48;
        size_t src = ((size_t)(b*IMGSZ + gy*PATCH + py) * IMGSZ + gx*PATCH) * 3 + r;
        *reinterpret_cast<__half*>(za + coff(token, k, KI2C)) = __float2half_rn(x[src]);
    }
}

// ---------------- bulk-copy GEMM ----------------
// EPI: 2 gelu->g_hid(chunked) ; 3 residual add ; 4 +bias+pos ; 5 fused u/gate ;
//      6 split-K atomicAdd into residual (gridDim.z = 2, +bias on z==0)
#define CHUNKB  8192
#define STAGEB  (2*CHUNKB)
#define NSTAGE  4
#define GEMM_SMEM (NSTAGE*STAGEB + 64)

template<int EPI>
__global__ __launch_bounds__(256, 2)
void tgemm_kernel(const uint8_t* __restrict__ Ab, const uint8_t* __restrict__ Bb,
                  const float* __restrict__ bias, float* __restrict__ Cout,
                  int K, int M, const float* __restrict__ extra) {
    extern __shared__ char smem[];
    const uint32_t sb  = smem_u32(smem);
    const uint32_t mb0 = sb + NSTAGE*STAGEB;
    const int tid = threadIdx.x, wid = tid >> 5, lid = tid & 31;
    const int bn = blockIdx.x, bm = blockIdx.y;
    const int NCfull = K >> 5;
    const int NC = (EPI == 6) ? (NCfull >> 1) : NCfull;
    const int cb = (EPI == 6) ? ((int)blockIdx.z * NC) : 0;
    const int wm = wid & 1, wn = wid >> 1;

    if (tid == 0) {
        #pragma unroll
        for (int s = 0; s < NSTAGE; s++) MBAR_INIT(mb0 + s*8, 1);
    }
    __syncthreads();

    auto issue = [&](int c, int s) {
        uint32_t mb = mb0 + s*8;
        MBAR_EXPECT(mb, 2*CHUNKB);
        bulk_ld(sb + s*STAGEB,          Ab + ((size_t)bm*NCfull + cb + c)*CHUNKB, CHUNKB, mb);
        bulk_ld(sb + s*STAGEB + CHUNKB, Bb + ((size_t)bn*NCfull + cb + c)*CHUNKB, CHUNKB, mb);
    };
    if (tid == 0) { issue(0,0); issue(1,1); issue(2,2); }    // NC >= 12 always

    float acc[4][4][4];
    #pragma unroll
    for (int i = 0; i < 4; i++)
        #pragma unroll
        for (int j = 0; j < 4; j++)
            #pragma unroll
            for (int q = 0; q < 4; q++) acc[i][j][q] = 0.0f;

    const int arow = lid & 15;
    const int asel = lid >> 4;
    const int brow = (lid & 7) + ((lid & 16) ? 8 : 0);
    const int bsel = (lid >> 3) & 1;

    for (int c = 0; c < NC; c++) {
        const int s = c & 3;
        mbar_wait(mb0 + s*8, (uint32_t)((c >> 2) & 1));
        const uint32_t stA = sb + s*STAGEB;
        const uint32_t stB = stA + CHUNKB;

        #pragma unroll
        for (int ks = 0; ks < 2; ks++) {
            uint32_t b[4][2];
            #pragma unroll
            for (int ng = 0; ng < 2; ng++) {
                int row = wn*32 + ng*16 + brow;
                int seg = ks*2 + bsel;
                uint32_t r[4];
                ldm4(r, stB + row*64 + ((seg ^ ((row >> 1) & 3)) << 4));
                b[ng*2+0][0] = r[0]; b[ng*2+0][1] = r[1];
                b[ng*2+1][0] = r[2]; b[ng*2+1][1] = r[3];
            }
            #pragma unroll
            for (int mf = 0; mf < 4; mf++) {
                int row = wm*64 + mf*16 + arow;
                int seg = ks*2 + asel;
                uint32_t a[4];
                ldm4(a, stA + row*64 + ((seg ^ ((row >> 1) & 3)) << 4));
                #pragma unroll
                for (int nf = 0; nf < 4; nf++)
                    mma16816(acc[mf][nf], a, b[nf]);
            }
        }
        __syncthreads();
        if (tid == 0 && c + 3 < NC) issue(c + 3, (c + 3) & 3);
    }

    // epilogue
    const int gr = lid >> 2, gc = lid & 3;
    uint8_t* hidb = reinterpret_cast<uint8_t*>(g_hid);
    #pragma unroll
    for (int mf = 0; mf < 4; mf++) {
        #pragma unroll
        for (int nf = 0; nf < 4; nf++) {
            const int col = bn * 128 + wn * 32 + nf * 8 + gc * 2;
            #pragma unroll
            for (int half = 0; half < 2; half++) {
                const int row = bm * 128 + wm * 64 + mf * 16 + gr + half * 8;
                float v0 = acc[mf][nf][half*2+0];
                float v1 = acc[mf][nf][half*2+1];
                if (EPI == 6) {
                    if (blockIdx.z == 0) {
                        float2 bv = *reinterpret_cast<const float2*>(bias + col);
                        v0 += bv.x; v1 += bv.y;
                    }
                    float* cp = Cout + (size_t)row * M + col;
                    atomicAdd(cp,     v0);
                    atomicAdd(cp + 1, v1);
                    continue;
                }
                if (EPI == 5) {
                    if (col < CC) {
                        float2 bv = *reinterpret_cast<const float2*>(bias + col);
                        float2 o; o.x = v0 + bv.x; o.y = v1 + bv.y;
                        *reinterpret_cast<float2*>(&g_u[(size_t)row * CC + col]) = o;
                    } else {
                        int cg = col - CC;
                        float2 bv = *reinterpret_cast<const float2*>(extra + cg);
                        float2 o; o.x = sigmoid_f(v0 + bv.x); o.y = sigmoid_f(v1 + bv.y);
                        *reinterpret_cast<float2*>(&g_gate[(size_t)row * CC + cg]) = o;
                    }
                    continue;
                }
                {
                    float2 bv = *reinterpret_cast<const float2*>(bias + col);
                    v0 += bv.x; v1 += bv.y;
                }
                if (EPI == 2) {
                    v0 = gelu_f(v0); v1 = gelu_f(v1);
                    *reinterpret_cast<uint32_t*>(hidb + coff(row, col, HIDN)) = packh2(v0, v1);
                    continue;
                }
                if (EPI == 4) {
                    int p = row % (GRIDW*GRIDW);
                    float2 pv = *reinterpret_cast<const float2*>(extra + (size_t)p * CC + col);
                    v0 += pv.x; v1 += pv.y;
                }
                float* cp = Cout + (size_t)row * M + col;
                if (EPI == 3) {
                    float2 rr = *reinterpret_cast<const float2*>(cp);
                    v0 += rr.x; v1 += rr.y;
                }
                float2 o; o.x = v0; o.y = v1;
                *reinterpret_cast<float2*>(cp) = o;
            }
        }
    }
}

// ---------------- LayerNorm (warp per row) ----------------
template<bool PAIR>
__global__ __launch_bounds__(256)
void ln_kernel(const float* __restrict__ gamma, const float* __restrict__ beta) {
    int row = blockIdx.x * 8 + (threadIdx.x >> 5);
    int lane = threadIdx.x & 31;
    const float* xr = g_h + (size_t)row * CC;
    float4 v[3];
    float s = 0.0f, q = 0.0f;
    #pragma unroll
    for (int i = 0; i < 3; i++) {
        v[i] = *reinterpret_cast<const float4*>(xr + lane*4 + i*128);
        s += v[i].x + v[i].y + v[i].z + v[i].w;
        q += v[i].x*v[i].x + v[i].y*v[i].y + v[i].z*v[i].z + v[i].w*v[i].w;
    }
    #pragma unroll
    for (int o = 16; o; o >>= 1) {
        s += __shfl_xor_sync(0xffffffffu, s, o);
        q += __shfl_xor_sync(0xffffffffu, q, o);
    }
    float m = s * (1.0f / CC);
    float r = rsqrtf(q * (1.0f / CC) - m*m + 1e-6f);
    uint8_t* za = reinterpret_cast<uint8_t*>(g_za);
    #pragma unroll
    for (int i = 0; i < 3; i++) {
        int k = lane*4 + i*128;
        float4 g4 = *reinterpret_cast<const float4*>(gamma + k);
        float4 b4 = *reinterpret_cast<const float4*>(beta + k);
        float y0 = (v[i].x - m) * r * g4.x + b4.x;
        float y1 = (v[i].y - m) * r * g4.y + b4.y;
        float y2 = (v[i].z - m) * r * g4.z + b4.z;
        float y3 = (v[i].w - m) * r * g4.w + b4.w;
        if (PAIR) {
            uint2 p; p.x = packh2(y0, y1); p.y = packh2(y2, y3);
            *reinterpret_cast<uint2*>(za + coff(row, k, CC)) = p;
        } else {
            float4 o; o.x = y0; o.y = y1; o.z = y2; o.w = y3;
            *reinterpret_cast<float4*>(g_z + (size_t)row * CC + k) = o;
        }
    }
}

// ---------------- gated depthwise-conv recurrence (16 ch/block, float4) ----------------
__global__ __launch_bounds__(196)
void recur_kernel(const float* __restrict__ KD) {
    __shared__ float4 s4[4][256];       // 4 channel-groups x 16x16 halo
    __shared__ float4 kd4[9][4];

    int blk = blockIdx.x;
    int b   = blk / (CC / 16);
    int cg  = blk % (CC / 16);          // 16-channel group
    int tid = threadIdx.x;
    int y = tid / GRIDW, x = tid % GRIDW;
    const int base_ch = cg * 16;

    for (int i = tid; i < 4 * 256; i += 196) {
        float4 z; z.x = z.y = z.z = z.w = 0.0f;
        ((float4*)s4)[i] = z;
    }
    if (tid < 36) {
        int tap = tid >> 2, grp = tid & 3;
        kd4[tap][grp] = *reinterpret_cast<const float4*>(KD + tap*CC + base_ch + grp*4);
    }

    size_t gbase = ((size_t)(b * (GRIDW*GRIDW) + tid)) * CC + base_ch;
    float4 gg[4], u1[4], cur[4];
    #pragma unroll
    for (int g = 0; g < 4; g++) {
        float4 gv = *reinterpret_cast<const float4*>(g_gate + gbase + g*4);
        float4 uv = *reinterpret_cast<const float4*>(g_u + gbase + g*4);
        gg[g] = gv;
        u1[g].x = (1.0f-gv.x)*uv.x; u1[g].y = (1.0f-gv.y)*uv.y;
        u1[g].z = (1.0f-gv.z)*uv.z; u1[g].w = (1.0f-gv.w)*uv.w;
        cur[g] = u1[g];
    }
    __syncthreads();

    const int ip = (y + 1) * 16 + (x + 1);
    #pragma unroll
    for (int g = 0; g < 4; g++) s4[g][ip] = cur[g];
    __syncthreads();

    for (int step = 0; step < TT - 1; step++) {
        float4 ns[4];
        #pragma unroll
        for (int g = 0; g < 4; g++) {
            float4 a;
            a.x = kd4[4][g].x * cur[g].x; a.y = kd4[4][g].y * cur[g].y;
            a.z = kd4[4][g].z * cur[g].z; a.w = kd4[4][g].w * cur[g].w;
            a = fma4(kd4[0][g], s4[g][ip-17], a);
            a = fma4(kd4[1][g], s4[g][ip-16], a);
            a = fma4(kd4[2][g], s4[g][ip-15], a);
            a = fma4(kd4[3][g], s4[g][ip-1],  a);
            a = fma4(kd4[5][g], s4[g][ip+1],  a);
            a = fma4(kd4[6][g], s4[g][ip+15], a);
            a = fma4(kd4[7][g], s4[g][ip+16], a);
            a = fma4(kd4[8][g], s4[g][ip+17], a);
            ns[g] = fma4(gg[g], a, u1[g]);
        }
        __syncthreads();
        #pragma unroll
        for (int g = 0; g < 4; g++) { cur[g] = ns[g]; s4[g][ip] = ns[g]; }
        __syncthreads();
    }

    #pragma unroll
    for (int g = 0; g < 4; g++) {
        float4 h = *reinterpret_cast<const float4*>(g_h + gbase + g*4);
        h.x += cur[g].x; h.y += cur[g].y; h.z += cur[g].z; h.w += cur[g].w;
        *reinterpret_cast<float4*>(g_h + gbase + g*4) = h;
    }
}

// ---------------- final max pool over spatial ----------------
__global__ void maxpool_kernel() {
    int b = blockIdx.x, c = threadIdx.x;
    const float* zb = g_z + (size_t)b * (GRIDW*GRIDW) * CC + c;
    float m = -INFINITY;
    #pragma unroll 4
    for (int p = 0; p < GRIDW*GRIDW; p++) m = fmaxf(m, zb[(size_t)p * CC]);
    g_pool[b * CC + c] = m;
}

// ---------------- classification head ----------------
__global__ void head_kernel(const float* __restrict__ HW, const float* __restrict__ HB,
                            float* __restrict__ out) {
    int idx = blockIdx.x * blockDim.x + threadIdx.x;
    if (idx >= BATCH * NCLS) return;
    int b = idx / NCLS, cls = idx % NCLS;
    const float* pb = g_pool + b * CC;
    float acc = HB[cls];
    #pragma unroll 4
    for (int k = 0; k < CC; k++) acc += pb[k] * HW[(size_t)k * NCLS + cls];
    out[idx] = acc;
}

// ---------------- host orchestration ----------------
extern "C" void kernel_launch(void* const* d_in, const int* in_sizes, int n_in,
                              void* d_out, int out_size) {
    const float* x       = (const float*)d_in[0];
    const float* patch_w = (const float*)d_in[1];
    const float* patch_b = (const float*)d_in[2];
    const float* pos     = (const float*)d_in[3];
    const float* ln1_s   = (const float*)d_in[4];
    const float* ln1_b   = (const float*)d_in[5];
    const float* w_in    = (const float*)d_in[6];
    const float* b_in    = (const float*)d_in[7];
    const float* w_g     = (const float*)d_in[8];
    const float* b_g     = (const float*)d_in[9];
    const float* k_dw    = (const float*)d_in[10];
    const float* ln2_s   = (const float*)d_in[11];
    const float* ln2_b   = (const float*)d_in[12];
    const float* w1      = (const float*)d_in[13];
    const float* b1      = (const float*)d_in[14];
    const float* w2      = (const float*)d_in[15];
    const float* b2      = (const float*)d_in[16];
    const float* lnf_s   = (const float*)d_in[17];
    const float* lnf_b   = (const float*)d_in[18];
    const float* head_w  = (const float*)d_in[19];
    const float* head_b  = (const float*)d_in[20];
    float* out = (float*)d_out;

    float *ph;
    uint8_t *za, *hid, *wt;
    cudaGetSymbolAddress((void**)&ph,  g_h);
    cudaGetSymbolAddress((void**)&za,  g_za);
    cudaGetSymbolAddress((void**)&hid, g_hid);
    cudaGetSymbolAddress((void**)&wt,  g_wt);

    cudaFuncSetAttribute(tgemm_kernel<2>, cudaFuncAttributeMaxDynamicSharedMemorySize, GEMM_SMEM);
    cudaFuncSetAttribute(tgemm_kernel<4>, cudaFuncAttributeMaxDynamicSharedMemorySize, GEMM_SMEM);
    cudaFuncSetAttribute(tgemm_kernel<5>, cudaFuncAttributeMaxDynamicSharedMemorySize, GEMM_SMEM);
    cudaFuncSetAttribute(tgemm_kernel<6>, cudaFuncAttributeMaxDynamicSharedMemorySize, GEMM_SMEM);

    const int NT = NTOK / 128;   // 49

    // weights -> chunked fp16
    convert_w_kernel<<<dim3(144, 1 + 4*DD), 256>>>(patch_w, w_in, w_g, w1, w2);

    // patch embed
    im2col_kernel<<<NTOK, 256>>>(x);
    tgemm_kernel<4><<<dim3(CC/128, NT), 256, GEMM_SMEM>>>(
        za, wt + (size_t)OFF_PATCH*2, patch_b, ph, KI2C, CC, pos);

    for (int d = 0; d < DD; d++) {
        size_t wb = ((size_t)OFF_BLK0 + (size_t)d * PER_BLK) * 2;
        ln_kernel<true><<<NTOK/8, 256>>>(ln1_s + d*CC, ln1_b + d*CC);
        tgemm_kernel<5><<<dim3((2*CC)/128, NT), 256, GEMM_SMEM>>>(
            za, wt + wb, b_in + d*CC, nullptr, CC, 2*CC, b_g + d*CC);
        recur_kernel<<<BATCH * (CC/16), 196>>>(k_dw + (size_t)d*9*CC);
        ln_kernel<true><<<NTOK/8, 256>>>(ln2_s + d*CC, ln2_b + d*CC);
        tgemm_kernel<2><<<dim3(HIDN/128, NT), 256, GEMM_SMEM>>>(
            za, wt + wb + (size_t)2*LEN_CXC*2, b1 + d*HIDN, nullptr, CC, HIDN, nullptr);
        // split-K x2 W2: both slices atomicAdd into residual g_h (bias on z==0)
        tgemm_kernel<6><<<dim3(CC/128, NT, 2), 256, GEMM_SMEM>>>(
            hid, wt + wb + (size_t)(2*LEN_CXC + LEN_W1)*2, b2 + d*CC, ph, HIDN, CC, nullptr);
    }

    ln_kernel<false><<<NTOK/8, 256>>>(lnf_s, lnf_b);
    maxpool_kernel<<<BATCH, CC>>>();
    head_kernel<<<(BATCH*NCLS + 255) / 256, 256>>>(head_w, head_b, out);
}

// round 12
// speedup vs baseline: 4.0392x; 1.0114x over previous
#include <cuda_runtime.h>
#include <cuda_fp16.h>
#include <math.h>
#include <stdint.h>

// ---------------- problem constants ----------------
#define BATCH   32
#define IMGSZ   224
#define PATCH   16
#define CC      384
#define DD      12
#define TT      8
#define HIDN    1536
#define NCLS    1000
#define GRIDW   14
#define NTOK    (BATCH*GRIDW*GRIDW)   // 6272
#define KI2C    (PATCH*PATCH*3)       // 768

// weight scratch offsets (elements; chunked [M/128][K/32] 8KB blocks)
#define OFF_PATCH   0
#define LEN_PATCH   (384*768)
#define OFF_BLK0    LEN_PATCH
#define LEN_CXC     (CC*CC)            // 147456
#define LEN_W1      (HIDN*CC)          // 589824
#define PER_BLK     (2*LEN_CXC + 2*LEN_W1)   // 1474560
#define WT_TOTAL    (OFF_BLK0 + DD*PER_BLK)  // 17989632

// ---------------- scratch (no allocations allowed) ----------------
__device__ float g_h   [(size_t)NTOK*CC];
__device__ float g_z   [(size_t)NTOK*CC];
__device__ float g_pool[(size_t)BATCH*CC];
__device__ __half g_uh [(size_t)NTOK*CC];      // u (fp16)
__device__ __half g_gh [(size_t)NTOK*CC];      // gate (fp16)
__device__ __half g_za [(size_t)NTOK*KI2C];    // A operand, chunked layout
__device__ __half g_hid[(size_t)NTOK*HIDN];    // MLP hidden, chunked layout
__device__ __half g_wt [(size_t)WT_TOTAL];     // weights, chunked layout

// ---------------- chunked layout ----------------
__device__ __forceinline__ size_t coff(int row, int k, int Kdim) {
    int rk = row & 127;
    int seg = (k >> 3) & 3, col = k & 7;
    return (((size_t)((row >> 7) * (Kdim >> 5) + (k >> 5))) << 13)
         + (uint32_t)(rk * 64 + ((seg ^ ((rk >> 1) & 3)) << 4) + col * 2);
}

// ---------------- small helpers ----------------
__device__ __forceinline__ float gelu_f(float x) {
    float x3 = x * x * x;
    float t  = tanhf(0.7978845608028654f * (x + 0.044715f * x3));
    return 0.5f * x * (1.0f + t);
}
__device__ __forceinline__ float sigmoid_f(float x) { return 1.0f / (1.0f + expf(-x)); }

__device__ __forceinline__ uint32_t smem_u32(const void* p) {
    uint32_t a;
    asm("{ .reg .u64 t; cvta.to.shared.u64 t, %1; cvt.u32.u64 %0, t; }" : "=r"(a) : "l"(p));
    return a;
}
__device__ __forceinline__ uint32_t packh2(float a, float b) {
    __half2 h = __halves2half2(__float2half_rn(a), __float2half_rn(b));
    return *reinterpret_cast<uint32_t*>(&h);
}
__device__ __forceinline__ float4 fma4(float4 a, float4 b, float4 c) {
    float4 r;
    r.x = fmaf(a.x, b.x, c.x); r.y = fmaf(a.y, b.y, c.y);
    r.z = fmaf(a.z, b.z, c.z); r.w = fmaf(a.w, b.w, c.w);
    return r;
}
__device__ __forceinline__ float4 h4_to_f4(uint2 p) {
    __half2 h0 = *reinterpret_cast<__half2*>(&p.x);
    __half2 h1 = *reinterpret_cast<__half2*>(&p.y);
    float2 f0 = __half22float2(h0), f1 = __half22float2(h1);
    float4 r; r.x = f0.x; r.y = f0.y; r.z = f1.x; r.w = f1.y;
    return r;
}

#define MBAR_INIT(a, c)  asm volatile("mbarrier.init.shared.b64 [%0], %1;" :: "r"(a), "r"(c) : "memory")
#define MBAR_EXPECT(a, tx) asm volatile("mbarrier.arrive.expect_tx.shared.b64 _, [%0], %1;" :: "r"(a), "r"(tx) : "memory")

__device__ __forceinline__ void bulk_ld(uint32_t dst, const void* src, uint32_t bytes, uint32_t mbar) {
    asm volatile("cp.async.bulk.shared::cluster.global.mbarrier::complete_tx::bytes [%0], [%1], %2, [%3];"
                 :: "r"(dst), "l"(src), "r"(bytes), "r"(mbar) : "memory");
}

__device__ __forceinline__ void mbar_wait(uint32_t mbar, uint32_t parity) {
    uint32_t done;
    asm volatile("{\n\t.reg .pred p;\n\t"
                 "mbarrier.try_wait.parity.acquire.cta.shared::cta.b64 p, [%1], %2;\n\t"
                 "selp.b32 %0, 1, 0, p;\n\t}"
                 : "=r"(done) : "r"(mbar), "r"(parity) : "memory");
    if (!done) {
        asm volatile("{\n\t.reg .pred P1;\n\t"
                     "WL_%=:\n\t"
                     "mbarrier.try_wait.parity.acquire.cta.shared::cta.b64 P1, [%0], %1, 0x989680;\n\t"
                     "@P1 bra.uni WD_%=;\n\t"
                     "bra.uni WL_%=;\n\t"
                     "WD_%=:\n\t}" :: "r"(mbar), "r"(parity) : "memory");
    }
}

__device__ __forceinline__ void ldm4(uint32_t* r, uint32_t addr) {
    asm volatile("ldmatrix.sync.aligned.m8n8.x4.shared.b16 {%0,%1,%2,%3}, [%4];"
                 : "=r"(r[0]), "=r"(r[1]), "=r"(r[2]), "=r"(r[3]) : "r"(addr));
}
__device__ __forceinline__ void mma16816(float* c, const uint32_t* a, const uint32_t* b) {
    asm volatile("mma.sync.aligned.m16n8k16.row.col.f32.f16.f16.f32 "
                 "{%0,%1,%2,%3}, {%4,%5,%6,%7}, {%8,%9}, {%0,%1,%2,%3};"
                 : "+f"(c[0]), "+f"(c[1]), "+f"(c[2]), "+f"(c[3])
                 : "r"(a[0]), "r"(a[1]), "r"(a[2]), "r"(a[3]), "r"(b[0]), "r"(b[1]));
}

// ---------------- weight convert+transpose into chunked layout ----------------
__global__ __launch_bounds__(256)
void convert_w_kernel(const float* __restrict__ patch_w,
                      const float* __restrict__ w_in, const float* __restrict__ w_g,
                      const float* __restrict__ w1, const float* __restrict__ w2) {
    int id = blockIdx.y;
    const float* src; int K, M; size_t dstel;
    if (id == 0) { src = patch_w; K = KI2C; M = CC; dstel = OFF_PATCH; }
    else {
        int d = (id - 1) >> 2, kind = (id - 1) & 3;
        size_t base = OFF_BLK0 + (size_t)d * PER_BLK;
        if      (kind == 0) { src = w_in + (size_t)d*CC*CC;   K = CC;   M = CC;   dstel = base; }
        else if (kind == 1) { src = w_g  + (size_t)d*CC*CC;   K = CC;   M = CC;   dstel = base + LEN_CXC; }
        else if (kind == 2) { src = w1   + (size_t)d*CC*HIDN; K = CC;   M = HIDN; dstel = base + 2*LEN_CXC; }
        else                { src = w2   + (size_t)d*HIDN*CC; K = HIDN; M = CC;   dstel = base + 2*LEN_CXC + LEN_W1; }
    }
    int nch = (M >> 7) * (K >> 5);
    int ch = blockIdx.x;
    if (ch >= nch) return;
    int mt = ch / (K >> 5), kc = ch % (K >> 5);

    __shared__ __half hs[4096];
    int tid = threadIdx.x;
    #pragma unroll
    for (int it = 0; it < 16; it++) {
        int e = tid + it * 256;
        int kk = e >> 7, rm = e & 127;
        float v = src[(size_t)(kc*32 + kk) * M + mt*128 + rm];
        int seg = kk >> 3, col = kk & 7;
        hs[rm*32 + ((seg ^ ((rm >> 1) & 3)) << 3) + col] = __float2half_rn(v);
    }
    __syncthreads();
    uint4* dst = reinterpret_cast<uint4*>(reinterpret_cast<uint8_t*>(g_wt) + dstel*2 + (size_t)ch*8192);
    const uint4* s4 = reinterpret_cast<const uint4*>(hs);
    dst[tid] = s4[tid];
    dst[tid + 256] = s4[tid + 256];
}

// ---------------- im2col -> fp16 chunked ----------------
__global__ void im2col_kernel(const float* __restrict__ x) {
    int token = blockIdx.x;
    int b  = token / (GRIDW*GRIDW);
    int p  = token % (GRIDW*GRIDW);
    int gy = p / GRIDW, gx = p % GRIDW;
    uint8_t* za = reinterpret_cast<uint8_t*>(g_za);
    for (int k = threadIdx.x; k < KI2C; k += blockDim.x) {
        int py = k / 48;
        int r  = k % 48;
        size_t src = ((size_t)(b*IMGSZ + gy*PATCH + py) * IMGSZ + gx*PATCH) * 3 + r;
        *reinterpret_cast<__half*>(za + coff(token, k, KI2C)) = __float2half_rn(x[src]);
    }
}

// ---------------- bulk-copy GEMM (BK=64 big-chunks) ----------------
// EPI: 2 gelu->g_hid(chunked) ; 4 +bias+pos ; 5 fused u/gate (fp16 out) ;
//      6 split-K atomicAdd into residual (gridDim.z = 2, +bias on z==0)
#define CHUNKB  8192
#define BIGB    (2*CHUNKB)             // 16KB: two 32-k chunks
#define STAGEB  (2*BIGB)               // A + B
#define NSTAGE  3
#define GEMM_SMEM (NSTAGE*STAGEB + 64) // 98368

template<int EPI>
__global__ __launch_bounds__(256, 2)
void tgemm_kernel(const uint8_t* __restrict__ Ab, const uint8_t* __restrict__ Bb,
                  const float* __restrict__ bias, float* __restrict__ Cout,
                  int K, int M, const float* __restrict__ extra) {
    extern __shared__ char smem[];
    const uint32_t sb  = smem_u32(smem);
    const uint32_t mb0 = sb + NSTAGE*STAGEB;
    const int tid = threadIdx.x, wid = tid >> 5, lid = tid & 31;
    const int bn = blockIdx.x, bm = blockIdx.y;
    const int NCfull = K >> 5;
    const int NCsl   = (EPI == 6) ? (NCfull >> 1) : NCfull;
    const int cb     = (EPI == 6) ? ((int)blockIdx.z * NCsl) : 0;
    const int NB     = NCsl >> 1;      // 64-wide big chunks (all K multiples of 64)
    const int wm = wid & 1, wn = wid >> 1;

    if (tid == 0) {
        #pragma unroll
        for (int s = 0; s < NSTAGE; s++) MBAR_INIT(mb0 + s*8, 1);
    }
    __syncthreads();

    auto issue = [&](int c, int s) {
        uint32_t mb = mb0 + s*8;
        MBAR_EXPECT(mb, 2*BIGB);
        bulk_ld(sb + s*STAGEB,        Ab + ((size_t)bm*NCfull + cb + 2*c)*CHUNKB, BIGB, mb);
        bulk_ld(sb + s*STAGEB + BIGB, Bb + ((size_t)bn*NCfull + cb + 2*c)*CHUNKB, BIGB, mb);
    };
    if (tid == 0) { issue(0,0); issue(1,1); issue(2,2); }    // NB >= 6 always

    float acc[4][4][4];
    #pragma unroll
    for (int i = 0; i < 4; i++)
        #pragma unroll
        for (int j = 0; j < 4; j++)
            #pragma unroll
            for (int q = 0; q < 4; q++) acc[i][j][q] = 0.0f;

    const int arow = lid & 15;
    const int asel = lid >> 4;
    const int brow = (lid & 7) + ((lid & 16) ? 8 : 0);
    const int bsel = (lid >> 3) & 1;

    for (int c = 0; c < NB; c++) {
        const int s = c % NSTAGE;
        mbar_wait(mb0 + s*8, (uint32_t)((c / NSTAGE) & 1));
        #pragma unroll
        for (int sub = 0; sub < 2; sub++) {
            const uint32_t stA = sb + s*STAGEB + sub*CHUNKB;
            const uint32_t stB = sb + s*STAGEB + BIGB + sub*CHUNKB;
            #pragma unroll
            for (int ks = 0; ks < 2; ks++) {
                uint32_t b[4][2];
                #pragma unroll
                for (int ng = 0; ng < 2; ng++) {
                    int row = wn*32 + ng*16 + brow;
                    int seg = ks*2 + bsel;
                    uint32_t r[4];
                    ldm4(r, stB + row*64 + ((seg ^ ((row >> 1) & 3)) << 4));
                    b[ng*2+0][0] = r[0]; b[ng*2+0][1] = r[1];
                    b[ng*2+1][0] = r[2]; b[ng*2+1][1] = r[3];
                }
                #pragma unroll
                for (int mf = 0; mf < 4; mf++) {
                    int row = wm*64 + mf*16 + arow;
                    int seg = ks*2 + asel;
                    uint32_t a[4];
                    ldm4(a, stA + row*64 + ((seg ^ ((row >> 1) & 3)) << 4));
                    #pragma unroll
                    for (int nf = 0; nf < 4; nf++)
                        mma16816(acc[mf][nf], a, b[nf]);
                }
            }
        }
        __syncthreads();
        if (tid == 0 && c + NSTAGE < NB) issue(c + NSTAGE, s);
    }

    // epilogue
    const int gr = lid >> 2, gc = lid & 3;
    uint8_t* hidb = reinterpret_cast<uint8_t*>(g_hid);
    #pragma unroll
    for (int mf = 0; mf < 4; mf++) {
        #pragma unroll
        for (int nf = 0; nf < 4; nf++) {
            const int col = bn * 128 + wn * 32 + nf * 8 + gc * 2;
            #pragma unroll
            for (int half = 0; half < 2; half++) {
                const int row = bm * 128 + wm * 64 + mf * 16 + gr + half * 8;
                float v0 = acc[mf][nf][half*2+0];
                float v1 = acc[mf][nf][half*2+1];
                if (EPI == 6) {
                    if (blockIdx.z == 0) {
                        float2 bv = *reinterpret_cast<const float2*>(bias + col);
                        v0 += bv.x; v1 += bv.y;
                    }
                    float* cp = Cout + (size_t)row * M + col;
                    atomicAdd(cp,     v0);
                    atomicAdd(cp + 1, v1);
                    continue;
                }
                if (EPI == 5) {
                    if (col < CC) {
                        float2 bv = *reinterpret_cast<const float2*>(bias + col);
                        *reinterpret_cast<uint32_t*>(&g_uh[(size_t)row * CC + col]) =
                            packh2(v0 + bv.x, v1 + bv.y);
                    } else {
                        int cg = col - CC;
                        float2 bv = *reinterpret_cast<const float2*>(extra + cg);
                        *reinterpret_cast<uint32_t*>(&g_gh[(size_t)row * CC + cg]) =
                            packh2(sigmoid_f(v0 + bv.x), sigmoid_f(v1 + bv.y));
                    }
                    continue;
                }
                {
                    float2 bv = *reinterpret_cast<const float2*>(bias + col);
                    v0 += bv.x; v1 += bv.y;
                }
                if (EPI == 2) {
                    v0 = gelu_f(v0); v1 = gelu_f(v1);
                    *reinterpret_cast<uint32_t*>(hidb + coff(row, col, HIDN)) = packh2(v0, v1);
                    continue;
                }
                if (EPI == 4) {
                    int p = row % (GRIDW*GRIDW);
                    float2 pv = *reinterpret_cast<const float2*>(extra + (size_t)p * CC + col);
                    v0 += pv.x; v1 += pv.y;
                }
                float* cp = Cout + (size_t)row * M + col;
                float2 o; o.x = v0; o.y = v1;
                *reinterpret_cast<float2*>(cp) = o;
            }
        }
    }
}

// ---------------- LayerNorm (warp per row) ----------------
template<bool PAIR>
__global__ __launch_bounds__(256)
void ln_kernel(const float* __restrict__ gamma, const float* __restrict__ beta) {
    int row = blockIdx.x * 8 + (threadIdx.x >> 5);
    int lane = threadIdx.x & 31;
    const float* xr = g_h + (size_t)row * CC;
    float4 v[3];
    float s = 0.0f, q = 0.0f;
    #pragma unroll
    for (int i = 0; i < 3; i++) {
        v[i] = *reinterpret_cast<const float4*>(xr + lane*4 + i*128);
        s += v[i].x + v[i].y + v[i].z + v[i].w;
        q += v[i].x*v[i].x + v[i].y*v[i].y + v[i].z*v[i].z + v[i].w*v[i].w;
    }
    #pragma unroll
    for (int o = 16; o; o >>= 1) {
        s += __shfl_xor_sync(0xffffffffu, s, o);
        q += __shfl_xor_sync(0xffffffffu, q, o);
    }
    float m = s * (1.0f / CC);
    float r = rsqrtf(q * (1.0f / CC) - m*m + 1e-6f);
    uint8_t* za = reinterpret_cast<uint8_t*>(g_za);
    #pragma unroll
    for (int i = 0; i < 3; i++) {
        int k = lane*4 + i*128;
        float4 g4 = *reinterpret_cast<const float4*>(gamma + k);
        float4 b4 = *reinterpret_cast<const float4*>(beta + k);
        float y0 = (v[i].x - m) * r * g4.x + b4.x;
        float y1 = (v[i].y - m) * r * g4.y + b4.y;
        float y2 = (v[i].z - m) * r * g4.z + b4.z;
        float y3 = (v[i].w - m) * r * g4.w + b4.w;
        if (PAIR) {
            uint2 p; p.x = packh2(y0, y1); p.y = packh2(y2, y3);
            *reinterpret_cast<uint2*>(za + coff(row, k, CC)) = p;
        } else {
            float4 o; o.x = y0; o.y = y1; o.z = y2; o.w = y3;
            *reinterpret_cast<float4*>(g_z + (size_t)row * CC + k) = o;
        }
    }
}

// ---------------- gated depthwise-conv recurrence (16 ch/block, float4) ----------------
__global__ __launch_bounds__(196)
void recur_kernel(const float* __restrict__ KD) {
    __shared__ float4 s4[4][256];       // 4 channel-groups x 16x16 halo
    __shared__ float4 kd4[9][4];

    int blk = blockIdx.x;
    int b   = blk / (CC / 16);
    int cg  = blk % (CC / 16);
    int tid = threadIdx.x;
    int y = tid / GRIDW, x = tid % GRIDW;
    const int base_ch = cg * 16;

    for (int i = tid; i < 4 * 256; i += 196) {
        float4 z; z.x = z.y = z.z = z.w = 0.0f;
        ((float4*)s4)[i] = z;
    }
    if (tid < 36) {
        int tap = tid >> 2, grp = tid & 3;
        kd4[tap][grp] = *reinterpret_cast<const float4*>(KD + tap*CC + base_ch + grp*4);
    }

    size_t gbase = ((size_t)(b * (GRIDW*GRIDW) + tid)) * CC + base_ch;
    float4 gg[4], u1[4], cur[4];
    #pragma unroll
    for (int g = 0; g < 4; g++) {
        float4 gv = h4_to_f4(*reinterpret_cast<const uint2*>(g_gh + gbase + g*4));
        float4 uv = h4_to_f4(*reinterpret_cast<const uint2*>(g_uh + gbase + g*4));
        gg[g] = gv;
        u1[g].x = (1.0f-gv.x)*uv.x; u1[g].y = (1.0f-gv.y)*uv.y;
        u1[g].z = (1.0f-gv.z)*uv.z; u1[g].w = (1.0f-gv.w)*uv.w;
        cur[g] = u1[g];
    }
    __syncthreads();

    const int ip = (y + 1) * 16 + (x + 1);
    #pragma unroll
    for (int g = 0; g < 4; g++) s4[g][ip] = cur[g];
    __syncthreads();

    for (int step = 0; step < TT - 1; step++) {
        float4 ns[4];
        #pragma unroll
        for (int g = 0; g < 4; g++) {
            float4 a;
            a.x = kd4[4][g].x * cur[g].x; a.y = kd4[4][g].y * cur[g].y;
            a.z = kd4[4][g].z * cur[g].z; a.w = kd4[4][g].w * cur[g].w;
            a = fma4(kd4[0][g], s4[g][ip-17], a);
            a = fma4(kd4[1][g], s4[g][ip-16], a);
            a = fma4(kd4[2][g], s4[g][ip-15], a);
            a = fma4(kd4[3][g], s4[g][ip-1],  a);
            a = fma4(kd4[5][g], s4[g][ip+1],  a);
            a = fma4(kd4[6][g], s4[g][ip+15], a);
            a = fma4(kd4[7][g], s4[g][ip+16], a);
            a = fma4(kd4[8][g], s4[g][ip+17], a);
            ns[g] = fma4(gg[g], a, u1[g]);
        }
        __syncthreads();
        #pragma unroll
        for (int g = 0; g < 4; g++) { cur[g] = ns[g]; s4[g][ip] = ns[g]; }
        __syncthreads();
    }

    #pragma unroll
    for (int g = 0; g < 4; g++) {
        float4 h = *reinterpret_cast<const float4*>(g_h + gbase + g*4);
        h.x += cur[g].x; h.y += cur[g].y; h.z += cur[g].z; h.w += cur[g].w;
        *reinterpret_cast<float4*>(g_h + gbase + g*4) = h;
    }
}

// ---------------- final max pool over spatial ----------------
__global__ void maxpool_kernel() {
    int b = blockIdx.x, c = threadIdx.x;
    const float* zb = g_z + (size_t)b * (GRIDW*GRIDW) * CC + c;
    float m = -INFINITY;
    #pragma unroll 4
    for (int p = 0; p < GRIDW*GRIDW; p++) m = fmaxf(m, zb[(size_t)p * CC]);
    g_pool[b * CC + c] = m;
}

// ---------------- classification head ----------------
__global__ void head_kernel(const float* __restrict__ HW, const float* __restrict__ HB,
                            float* __restrict__ out) {
    int idx = blockIdx.x * blockDim.x + threadIdx.x;
    if (idx >= BATCH * NCLS) return;
    int b = idx / NCLS, cls = idx % NCLS;
    const float* pb = g_pool + b * CC;
    float acc = HB[cls];
    #pragma unroll 4
    for (int k = 0; k < CC; k++) acc += pb[k] * HW[(size_t)k * NCLS + cls];
    out[idx] = acc;
}

// ---------------- host orchestration ----------------
extern "C" void kernel_launch(void* const* d_in, const int* in_sizes, int n_in,
                              void* d_out, int out_size) {
    const float* x       = (const float*)d_in[0];
    const float* patch_w = (const float*)d_in[1];
    const float* patch_b = (const float*)d_in[2];
    const float* pos     = (const float*)d_in[3];
    const float* ln1_s   = (const float*)d_in[4];
    const float* ln1_b   = (const float*)d_in[5];
    const float* w_in    = (const float*)d_in[6];
    const float* b_in    = (const float*)d_in[7];
    const float* w_g     = (const float*)d_in[8];
    const float* b_g     = (const float*)d_in[9];
    const float* k_dw    = (const float*)d_in[10];
    const float* ln2_s   = (const float*)d_in[11];
    const float* ln2_b   = (const float*)d_in[12];
    const float* w1      = (const float*)d_in[13];
    const float* b1      = (const float*)d_in[14];
    const float* w2      = (const float*)d_in[15];
    const float* b2      = (const float*)d_in[16];
    const float* lnf_s   = (const float*)d_in[17];
    const float* lnf_b   = (const float*)d_in[18];
    const float* head_w  = (const float*)d_in[19];
    const float* head_b  = (const float*)d_in[20];
    float* out = (float*)d_out;

    float *ph;
    uint8_t *za, *hid, *wt;
    cudaGetSymbolAddress((void**)&ph,  g_h);
    cudaGetSymbolAddress((void**)&za,  g_za);
    cudaGetSymbolAddress((void**)&hid, g_hid);
    cudaGetSymbolAddress((void**)&wt,  g_wt);

    cudaFuncSetAttribute(tgemm_kernel<2>, cudaFuncAttributeMaxDynamicSharedMemorySize, GEMM_SMEM);
    cudaFuncSetAttribute(tgemm_kernel<4>, cudaFuncAttributeMaxDynamicSharedMemorySize, GEMM_SMEM);
    cudaFuncSetAttribute(tgemm_kernel<5>, cudaFuncAttributeMaxDynamicSharedMemorySize, GEMM_SMEM);
    cudaFuncSetAttribute(tgemm_kernel<6>, cudaFuncAttributeMaxDynamicSharedMemorySize, GEMM_SMEM);

    const int NT = NTOK / 128;   // 49

    // weights -> chunked fp16
    convert_w_kernel<<<dim3(144, 1 + 4*DD), 256>>>(patch_w, w_in, w_g, w1, w2);

    // patch embed
    im2col_kernel<<<NTOK, 256>>>(x);
    tgemm_kernel<4><<<dim3(CC/128, NT), 256, GEMM_SMEM>>>(
        za, wt + (size_t)OFF_PATCH*2, patch_b, ph, KI2C, CC, pos);

    for (int d = 0; d < DD; d++) {
        size_t wb = ((size_t)OFF_BLK0 + (size_t)d * PER_BLK) * 2;
        ln_kernel<true><<<NTOK/8, 256>>>(ln1_s + d*CC, ln1_b + d*CC);
        tgemm_kernel<5><<<dim3((2*CC)/128, NT), 256, GEMM_SMEM>>>(
            za, wt + wb, b_in + d*CC, nullptr, CC, 2*CC, b_g + d*CC);
        recur_kernel<<<BATCH * (CC/16), 196>>>(k_dw + (size_t)d*9*CC);
        ln_kernel<true><<<NTOK/8, 256>>>(ln2_s + d*CC, ln2_b + d*CC);
        tgemm_kernel<2><<<dim3(HIDN/128, NT), 256, GEMM_SMEM>>>(
            za, wt + wb + (size_t)2*LEN_CXC*2, b1 + d*HIDN, nullptr, CC, HIDN, nullptr);
        tgemm_kernel<6><<<dim3(CC/128, NT, 2), 256, GEMM_SMEM>>>(
            hid, wt + wb + (size_t)(2*LEN_CXC + LEN_W1)*2, b2 + d*CC, ph, HIDN, CC, nullptr);
    }

    ln_kernel<false><<<NTOK/8, 256>>>(lnf_s, lnf_b);
    maxpool_kernel<<<BATCH, CC>>>();
    head_kernel<<<(BATCH*NCLS + 255) / 256, 256>>>(head_w, head_b, out);
}

// round 13
// speedup vs baseline: 4.0437x; 1.0011x over previous
#include <cuda_runtime.h>
#include <cuda_fp16.h>
#include <math.h>
#include <stdint.h>

// ---------------- problem constants ----------------
#define BATCH   32
#define IMGSZ   224
#define PATCH   16
#define CC      384
#define DD      12
#define TT      8
#define HIDN    1536
#define NCLS    1000
#define GRIDW   14
#define NTOK    (BATCH*GRIDW*GRIDW)   // 6272
#define KI2C    (PATCH*PATCH*3)       // 768

// weight scratch offsets (elements; chunked [M/128][K/32] 8KB blocks)
#define OFF_PATCH   0
#define LEN_PATCH   (384*768)
#define OFF_BLK0    LEN_PATCH
#define LEN_CXC     (CC*CC)            // 147456
#define LEN_W1      (HIDN*CC)          // 589824
#define PER_BLK     (2*LEN_CXC + 2*LEN_W1)   // 1474560
#define WT_TOTAL    (OFF_BLK0 + DD*PER_BLK)  // 17989632

// ---------------- scratch (no allocations allowed) ----------------
__device__ float g_h   [(size_t)NTOK*CC];
__device__ float g_z   [(size_t)NTOK*CC];
__device__ float g_pool[(size_t)BATCH*CC];
__device__ __half g_uh [(size_t)NTOK*CC];      // u (fp16)
__device__ __half g_gh [(size_t)NTOK*CC];      // gate (fp16)
__device__ __half g_za [(size_t)NTOK*KI2C];    // A operand, chunked layout
__device__ __half g_hid[(size_t)NTOK*HIDN];    // MLP hidden, chunked layout
__device__ __half g_wt [(size_t)WT_TOTAL];     // weights, chunked layout

// ---------------- chunked layout ----------------
__device__ __forceinline__ size_t coff(int row, int k, int Kdim) {
    int rk = row & 127;
    int seg = (k >> 3) & 3, col = k & 7;
    return (((size_t)((row >> 7) * (Kdim >> 5) + (k >> 5))) << 13)
         + (uint32_t)(rk * 64 + ((seg ^ ((rk >> 1) & 3)) << 4) + col * 2);
}

// ---------------- small helpers ----------------
__device__ __forceinline__ float gelu_f(float x) {
    float x3 = x * x * x;
    float t  = tanhf(0.7978845608028654f * (x + 0.044715f * x3));
    return 0.5f * x * (1.0f + t);
}
__device__ __forceinline__ float sigmoid_f(float x) { return 1.0f / (1.0f + expf(-x)); }

__device__ __forceinline__ uint32_t smem_u32(const void* p) {
    uint32_t a;
    asm("{ .reg .u64 t; cvta.to.shared.u64 t, %1; cvt.u32.u64 %0, t; }" : "=r"(a) : "l"(p));
    return a;
}
__device__ __forceinline__ uint32_t packh2(float a, float b) {
    __half2 h = __halves2half2(__float2half_rn(a), __float2half_rn(b));
    return *reinterpret_cast<uint32_t*>(&h);
}
__device__ __forceinline__ float4 fma4(float4 a, float4 b, float4 c) {
    float4 r;
    r.x = fmaf(a.x, b.x, c.x); r.y = fmaf(a.y, b.y, c.y);
    r.z = fmaf(a.z, b.z, c.z); r.w = fmaf(a.w, b.w, c.w);
    return r;
}
__device__ __forceinline__ float4 h4_to_f4(uint2 p) {
    __half2 h0 = *reinterpret_cast<__half2*>(&p.x);
    __half2 h1 = *reinterpret_cast<__half2*>(&p.y);
    float2 f0 = __half22float2(h0), f1 = __half22float2(h1);
    float4 r; r.x = f0.x; r.y = f0.y; r.z = f1.x; r.w = f1.y;
    return r;
}

#define MBAR_INIT(a, c)  asm volatile("mbarrier.init.shared.b64 [%0], %1;" :: "r"(a), "r"(c) : "memory")
#define MBAR_EXPECT(a, tx) asm volatile("mbarrier.arrive.expect_tx.shared.b64 _, [%0], %1;" :: "r"(a), "r"(tx) : "memory")

__device__ __forceinline__ void bulk_ld(uint32_t dst, const void* src, uint32_t bytes, uint32_t mbar) {
    asm volatile("cp.async.bulk.shared::cluster.global.mbarrier::complete_tx::bytes [%0], [%1], %2, [%3];"
                 :: "r"(dst), "l"(src), "r"(bytes), "r"(mbar) : "memory");
}

__device__ __forceinline__ void mbar_wait(uint32_t mbar, uint32_t parity) {
    uint32_t done;
    asm volatile("{\n\t.reg .pred p;\n\t"
                 "mbarrier.try_wait.parity.acquire.cta.shared::cta.b64 p, [%1], %2;\n\t"
                 "selp.b32 %0, 1, 0, p;\n\t}"
                 : "=r"(done) : "r"(mbar), "r"(parity) : "memory");
    if (!done) {
        asm volatile("{\n\t.reg .pred P1;\n\t"
                     "WL_%=:\n\t"
                     "mbarrier.try_wait.parity.acquire.cta.shared::cta.b64 P1, [%0], %1, 0x989680;\n\t"
                     "@P1 bra.uni WD_%=;\n\t"
                     "bra.uni WL_%=;\n\t"
                     "WD_%=:\n\t}" :: "r"(mbar), "r"(parity) : "memory");
    }
}

__device__ __forceinline__ void ldm4(uint32_t* r, uint32_t addr) {
    asm volatile("ldmatrix.sync.aligned.m8n8.x4.shared.b16 {%0,%1,%2,%3}, [%4];"
                 : "=r"(r[0]), "=r"(r[1]), "=r"(r[2]), "=r"(r[3]) : "r"(addr));
}
__device__ __forceinline__ void mma16816(float* c, const uint32_t* a, const uint32_t* b) {
    asm volatile("mma.sync.aligned.m16n8k16.row.col.f32.f16.f16.f32 "
                 "{%0,%1,%2,%3}, {%4,%5,%6,%7}, {%8,%9}, {%0,%1,%2,%3};"
                 : "+f"(c[0]), "+f"(c[1]), "+f"(c[2]), "+f"(c[3])
                 : "r"(a[0]), "r"(a[1]), "r"(a[2]), "r"(a[3]), "r"(b[0]), "r"(b[1]));
}

// ---------------- weight convert+transpose into chunked layout ----------------
__global__ __launch_bounds__(256)
void convert_w_kernel(const float* __restrict__ patch_w,
                      const float* __restrict__ w_in, const float* __restrict__ w_g,
                      const float* __restrict__ w1, const float* __restrict__ w2) {
    int id = blockIdx.y;
    const float* src; int K, M; size_t dstel;
    if (id == 0) { src = patch_w; K = KI2C; M = CC; dstel = OFF_PATCH; }
    else {
        int d = (id - 1) >> 2, kind = (id - 1) & 3;
        size_t base = OFF_BLK0 + (size_t)d * PER_BLK;
        if      (kind == 0) { src = w_in + (size_t)d*CC*CC;   K = CC;   M = CC;   dstel = base; }
        else if (kind == 1) { src = w_g  + (size_t)d*CC*CC;   K = CC;   M = CC;   dstel = base + LEN_CXC; }
        else if (kind == 2) { src = w1   + (size_t)d*CC*HIDN; K = CC;   M = HIDN; dstel = base + 2*LEN_CXC; }
        else                { src = w2   + (size_t)d*HIDN*CC; K = HIDN; M = CC;   dstel = base + 2*LEN_CXC + LEN_W1; }
    }
    int nch = (M >> 7) * (K >> 5);
    int ch = blockIdx.x;
    if (ch >= nch) return;
    int mt = ch / (K >> 5), kc = ch % (K >> 5);

    __shared__ __half hs[4096];
    int tid = threadIdx.x;
    #pragma unroll
    for (int it = 0; it < 16; it++) {
        int e = tid + it * 256;
        int kk = e >> 7, rm = e & 127;
        float v = src[(size_t)(kc*32 + kk) * M + mt*128 + rm];
        int seg = kk >> 3, col = kk & 7;
        hs[rm*32 + ((seg ^ ((rm >> 1) & 3)) << 3) + col] = __float2half_rn(v);
    }
    __syncthreads();
    uint4* dst = reinterpret_cast<uint4*>(reinterpret_cast<uint8_t*>(g_wt) + dstel*2 + (size_t)ch*8192);
    const uint4* s4 = reinterpret_cast<const uint4*>(hs);
    dst[tid] = s4[tid];
    dst[tid + 256] = s4[tid + 256];
}

// ---------------- im2col -> fp16 chunked ----------------
__global__ void im2col_kernel(const float* __restrict__ x) {
    int token = blockIdx.x;
    int b  = token / (GRIDW*GRIDW);
    int p  = token % (GRIDW*GRIDW);
    int gy = p / GRIDW, gx = p % GRIDW;
    uint8_t* za = reinterpret_cast<uint8_t*>(g_za);
    for (int k = threadIdx.x; k < KI2C; k += blockDim.x) {
        int py = k / 48;
        int r  = k % 48;
        size_t src = ((size_t)(b*IMGSZ + gy*PATCH + py) * IMGSZ + gx*PATCH) * 3 + r;
        *reinterpret_cast<__half*>(za + coff(token, k, KI2C)) = __float2half_rn(x[src]);
    }
}

// ---------------- bulk-copy GEMM (BK=64 big-chunks) ----------------
// EPI: 2 gelu->g_hid(chunked) ; 4 +bias+pos ; 5 fused u/gate (fp16 out) ;
//      6 split-K atomicAdd into residual (gridDim.z = 2, +bias on z==0)
#define CHUNKB  8192
#define BIGB    (2*CHUNKB)
#define STAGEB  (2*BIGB)
#define NSTAGE  3
#define GEMM_SMEM (NSTAGE*STAGEB + 64)

template<int EPI>
__global__ __launch_bounds__(256, 2)
void tgemm_kernel(const uint8_t* __restrict__ Ab, const uint8_t* __restrict__ Bb,
                  const float* __restrict__ bias, float* __restrict__ Cout,
                  int K, int M, const float* __restrict__ extra) {
    extern __shared__ char smem[];
    const uint32_t sb  = smem_u32(smem);
    const uint32_t mb0 = sb + NSTAGE*STAGEB;
    const int tid = threadIdx.x, wid = tid >> 5, lid = tid & 31;
    const int bn = blockIdx.x, bm = blockIdx.y;
    const int NCfull = K >> 5;
    const int NCsl   = (EPI == 6) ? (NCfull >> 1) : NCfull;
    const int cb     = (EPI == 6) ? ((int)blockIdx.z * NCsl) : 0;
    const int NB     = NCsl >> 1;
    const int wm = wid & 1, wn = wid >> 1;

    if (tid == 0) {
        #pragma unroll
        for (int s = 0; s < NSTAGE; s++) MBAR_INIT(mb0 + s*8, 1);
    }
    __syncthreads();

    auto issue = [&](int c, int s) {
        uint32_t mb = mb0 + s*8;
        MBAR_EXPECT(mb, 2*BIGB);
        bulk_ld(sb + s*STAGEB,        Ab + ((size_t)bm*NCfull + cb + 2*c)*CHUNKB, BIGB, mb);
        bulk_ld(sb + s*STAGEB + BIGB, Bb + ((size_t)bn*NCfull + cb + 2*c)*CHUNKB, BIGB, mb);
    };
    if (tid == 0) { issue(0,0); issue(1,1); issue(2,2); }

    float acc[4][4][4];
    #pragma unroll
    for (int i = 0; i < 4; i++)
        #pragma unroll
        for (int j = 0; j < 4; j++)
            #pragma unroll
            for (int q = 0; q < 4; q++) acc[i][j][q] = 0.0f;

    const int arow = lid & 15;
    const int asel = lid >> 4;
    const int brow = (lid & 7) + ((lid & 16) ? 8 : 0);
    const int bsel = (lid >> 3) & 1;

    for (int c = 0; c < NB; c++) {
        const int s = c % NSTAGE;
        mbar_wait(mb0 + s*8, (uint32_t)((c / NSTAGE) & 1));
        #pragma unroll
        for (int sub = 0; sub < 2; sub++) {
            const uint32_t stA = sb + s*STAGEB + sub*CHUNKB;
            const uint32_t stB = sb + s*STAGEB + BIGB + sub*CHUNKB;
            #pragma unroll
            for (int ks = 0; ks < 2; ks++) {
                uint32_t b[4][2];
                #pragma unroll
                for (int ng = 0; ng < 2; ng++) {
                    int row = wn*32 + ng*16 + brow;
                    int seg = ks*2 + bsel;
                    uint32_t r[4];
                    ldm4(r, stB + row*64 + ((seg ^ ((row >> 1) & 3)) << 4));
                    b[ng*2+0][0] = r[0]; b[ng*2+0][1] = r[1];
                    b[ng*2+1][0] = r[2]; b[ng*2+1][1] = r[3];
                }
                #pragma unroll
                for (int mf = 0; mf < 4; mf++) {
                    int row = wm*64 + mf*16 + arow;
                    int seg = ks*2 + asel;
                    uint32_t a[4];
                    ldm4(a, stA + row*64 + ((seg ^ ((row >> 1) & 3)) << 4));
                    #pragma unroll
                    for (int nf = 0; nf < 4; nf++)
                        mma16816(acc[mf][nf], a, b[nf]);
                }
            }
        }
        __syncthreads();
        if (tid == 0 && c + NSTAGE < NB) issue(c + NSTAGE, s);
    }

    // epilogue
    const int gr = lid >> 2, gc = lid & 3;
    uint8_t* hidb = reinterpret_cast<uint8_t*>(g_hid);
    #pragma unroll
    for (int mf = 0; mf < 4; mf++) {
        #pragma unroll
        for (int nf = 0; nf < 4; nf++) {
            const int col = bn * 128 + wn * 32 + nf * 8 + gc * 2;
            #pragma unroll
            for (int half = 0; half < 2; half++) {
                const int row = bm * 128 + wm * 64 + mf * 16 + gr + half * 8;
                float v0 = acc[mf][nf][half*2+0];
                float v1 = acc[mf][nf][half*2+1];
                if (EPI == 6) {
                    if (blockIdx.z == 0) {
                        float2 bv = *reinterpret_cast<const float2*>(bias + col);
                        v0 += bv.x; v1 += bv.y;
                    }
                    float* cp = Cout + (size_t)row * M + col;
                    atomicAdd(cp,     v0);
                    atomicAdd(cp + 1, v1);
                    continue;
                }
                if (EPI == 5) {
                    if (col < CC) {
                        float2 bv = *reinterpret_cast<const float2*>(bias + col);
                        *reinterpret_cast<uint32_t*>(&g_uh[(size_t)row * CC + col]) =
                            packh2(v0 + bv.x, v1 + bv.y);
                    } else {
                        int cg = col - CC;
                        float2 bv = *reinterpret_cast<const float2*>(extra + cg);
                        *reinterpret_cast<uint32_t*>(&g_gh[(size_t)row * CC + cg]) =
                            packh2(sigmoid_f(v0 + bv.x), sigmoid_f(v1 + bv.y));
                    }
                    continue;
                }
                {
                    float2 bv = *reinterpret_cast<const float2*>(bias + col);
                    v0 += bv.x; v1 += bv.y;
                }
                if (EPI == 2) {
                    v0 = gelu_f(v0); v1 = gelu_f(v1);
                    *reinterpret_cast<uint32_t*>(hidb + coff(row, col, HIDN)) = packh2(v0, v1);
                    continue;
                }
                if (EPI == 4) {
                    int p = row % (GRIDW*GRIDW);
                    float2 pv = *reinterpret_cast<const float2*>(extra + (size_t)p * CC + col);
                    v0 += pv.x; v1 += pv.y;
                }
                float* cp = Cout + (size_t)row * M + col;
                float2 o; o.x = v0; o.y = v1;
                *reinterpret_cast<float2*>(cp) = o;
            }
        }
    }
}

// ---------------- LayerNorm (2 rows per warp, deep MLP) ----------------
template<bool PAIR>
__global__ __launch_bounds__(256)
void ln_kernel(const float* __restrict__ gamma, const float* __restrict__ beta) {
    int w = threadIdx.x >> 5, lane = threadIdx.x & 31;
    int row0 = blockIdx.x * 16 + w * 2;
    const float* xr0 = g_h + (size_t)row0 * CC;
    const float* xr1 = xr0 + CC;
    float4 v0[3], v1[3];
    // issue all 6 independent loads up-front (MLP=6)
    #pragma unroll
    for (int i = 0; i < 3; i++) v0[i] = *reinterpret_cast<const float4*>(xr0 + lane*4 + i*128);
    #pragma unroll
    for (int i = 0; i < 3; i++) v1[i] = *reinterpret_cast<const float4*>(xr1 + lane*4 + i*128);

    float s0 = 0.f, q0 = 0.f, s1 = 0.f, q1 = 0.f;
    #pragma unroll
    for (int i = 0; i < 3; i++) {
        s0 += v0[i].x + v0[i].y + v0[i].z + v0[i].w;
        q0 += v0[i].x*v0[i].x + v0[i].y*v0[i].y + v0[i].z*v0[i].z + v0[i].w*v0[i].w;
        s1 += v1[i].x + v1[i].y + v1[i].z + v1[i].w;
        q1 += v1[i].x*v1[i].x + v1[i].y*v1[i].y + v1[i].z*v1[i].z + v1[i].w*v1[i].w;
    }
    #pragma unroll
    for (int o = 16; o; o >>= 1) {
        s0 += __shfl_xor_sync(0xffffffffu, s0, o);
        q0 += __shfl_xor_sync(0xffffffffu, q0, o);
        s1 += __shfl_xor_sync(0xffffffffu, s1, o);
        q1 += __shfl_xor_sync(0xffffffffu, q1, o);
    }
    float m0 = s0 * (1.0f / CC), r0 = rsqrtf(q0 * (1.0f / CC) - m0*m0 + 1e-6f);
    float m1 = s1 * (1.0f / CC), r1 = rsqrtf(q1 * (1.0f / CC) - m1*m1 + 1e-6f);
    uint8_t* za = reinterpret_cast<uint8_t*>(g_za);
    #pragma unroll
    for (int i = 0; i < 3; i++) {
        int k = lane*4 + i*128;
        float4 g4 = *reinterpret_cast<const float4*>(gamma + k);
        float4 b4 = *reinterpret_cast<const float4*>(beta + k);
        float a0 = (v0[i].x - m0) * r0 * g4.x + b4.x;
        float a1 = (v0[i].y - m0) * r0 * g4.y + b4.y;
        float a2 = (v0[i].z - m0) * r0 * g4.z + b4.z;
        float a3 = (v0[i].w - m0) * r0 * g4.w + b4.w;
        float c0 = (v1[i].x - m1) * r1 * g4.x + b4.x;
        float c1 = (v1[i].y - m1) * r1 * g4.y + b4.y;
        float c2 = (v1[i].z - m1) * r1 * g4.z + b4.z;
        float c3 = (v1[i].w - m1) * r1 * g4.w + b4.w;
        if (PAIR) {
            uint2 p0; p0.x = packh2(a0, a1); p0.y = packh2(a2, a3);
            uint2 p1; p1.x = packh2(c0, c1); p1.y = packh2(c2, c3);
            *reinterpret_cast<uint2*>(za + coff(row0,     k, CC)) = p0;
            *reinterpret_cast<uint2*>(za + coff(row0 + 1, k, CC)) = p1;
        } else {
            float4 o0; o0.x=a0; o0.y=a1; o0.z=a2; o0.w=a3;
            float4 o1; o1.x=c0; o1.y=c1; o1.z=c2; o1.w=c3;
            *reinterpret_cast<float4*>(g_z + (size_t)row0 * CC + k) = o0;
            *reinterpret_cast<float4*>(g_z + (size_t)(row0+1) * CC + k) = o1;
        }
    }
}

// ---------------- gated depthwise-conv recurrence (double-buffered state) ----------------
__global__ __launch_bounds__(196)
void recur_kernel(const float* __restrict__ KD) {
    __shared__ float4 sbuf[2][4][256];  // ping-pong state, 4 channel-groups x 16x16 halo
    __shared__ float4 kd4[9][4];

    int blk = blockIdx.x;
    int b   = blk / (CC / 16);
    int cg  = blk % (CC / 16);
    int tid = threadIdx.x;
    int y = tid / GRIDW, x = tid % GRIDW;
    const int base_ch = cg * 16;

    for (int i = tid; i < 2 * 4 * 256; i += 196) {
        float4 z; z.x = z.y = z.z = z.w = 0.0f;
        ((float4*)sbuf)[i] = z;
    }
    if (tid < 36) {
        int tap = tid >> 2, grp = tid & 3;
        kd4[tap][grp] = *reinterpret_cast<const float4*>(KD + tap*CC + base_ch + grp*4);
    }

    size_t gbase = ((size_t)(b * (GRIDW*GRIDW) + tid)) * CC + base_ch;
    float4 gg[4], u1[4], cur[4];
    #pragma unroll
    for (int g = 0; g < 4; g++) {
        float4 gv = h4_to_f4(*reinterpret_cast<const uint2*>(g_gh + gbase + g*4));
        float4 uv = h4_to_f4(*reinterpret_cast<const uint2*>(g_uh + gbase + g*4));
        gg[g] = gv;
        u1[g].x = (1.0f-gv.x)*uv.x; u1[g].y = (1.0f-gv.y)*uv.y;
        u1[g].z = (1.0f-gv.z)*uv.z; u1[g].w = (1.0f-gv.w)*uv.w;
        cur[g] = u1[g];
    }
    __syncthreads();

    const int ip = (y + 1) * 16 + (x + 1);
    #pragma unroll
    for (int g = 0; g < 4; g++) sbuf[0][g][ip] = cur[g];
    __syncthreads();

    int pb = 0;
    for (int step = 0; step < TT - 1; step++) {
        float4 ns[4];
        #pragma unroll
        for (int g = 0; g < 4; g++) {
            const float4* sg = sbuf[pb][g];
            float4 a;
            a.x = kd4[4][g].x * cur[g].x; a.y = kd4[4][g].y * cur[g].y;
            a.z = kd4[4][g].z * cur[g].z; a.w = kd4[4][g].w * cur[g].w;
            a = fma4(kd4[0][g], sg[ip-17], a);
            a = fma4(kd4[1][g], sg[ip-16], a);
            a = fma4(kd4[2][g], sg[ip-15], a);
            a = fma4(kd4[3][g], sg[ip-1],  a);
            a = fma4(kd4[5][g], sg[ip+1],  a);
            a = fma4(kd4[6][g], sg[ip+15], a);
            a = fma4(kd4[7][g], sg[ip+16], a);
            a = fma4(kd4[8][g], sg[ip+17], a);
            ns[g] = fma4(gg[g], a, u1[g]);
        }
        #pragma unroll
        for (int g = 0; g < 4; g++) { cur[g] = ns[g]; sbuf[1-pb][g][ip] = ns[g]; }
        __syncthreads();
        pb ^= 1;
    }

    #pragma unroll
    for (int g = 0; g < 4; g++) {
        float4 h = *reinterpret_cast<const float4*>(g_h + gbase + g*4);
        h.x += cur[g].x; h.y += cur[g].y; h.z += cur[g].z; h.w += cur[g].w;
        *reinterpret_cast<float4*>(g_h + gbase + g*4) = h;
    }
}

// ---------------- final max pool over spatial ----------------
__global__ void maxpool_kernel() {
    int b = blockIdx.x, c = threadIdx.x;
    const float* zb = g_z + (size_t)b * (GRIDW*GRIDW) * CC + c;
    float m = -INFINITY;
    #pragma unroll 4
    for (int p = 0; p < GRIDW*GRIDW; p++) m = fmaxf(m, zb[(size_t)p * CC]);
    g_pool[b * CC + c] = m;
}

// ---------------- classification head ----------------
__global__ void head_kernel(const float* __restrict__ HW, const float* __restrict__ HB,
                            float* __restrict__ out) {
    int idx = blockIdx.x * blockDim.x + threadIdx.x;
    if (idx >= BATCH * NCLS) return;
    int b = idx / NCLS, cls = idx % NCLS;
    const float* pb = g_pool + b * CC;
    float acc = HB[cls];
    #pragma unroll 4
    for (int k = 0; k < CC; k++) acc += pb[k] * HW[(size_t)k * NCLS + cls];
    out[idx] = acc;
}

// ---------------- host orchestration ----------------
extern "C" void kernel_launch(void* const* d_in, const int* in_sizes, int n_in,
                              void* d_out, int out_size) {
    const float* x       = (const float*)d_in[0];
    const float* patch_w = (const float*)d_in[1];
    const float* patch_b = (const float*)d_in[2];
    const float* pos     = (const float*)d_in[3];
    const float* ln1_s   = (const float*)d_in[4];
    const float* ln1_b   = (const float*)d_in[5];
    const float* w_in    = (const float*)d_in[6];
    const float* b_in    = (const float*)d_in[7];
    const float* w_g     = (const float*)d_in[8];
    const float* b_g     = (const float*)d_in[9];
    const float* k_dw    = (const float*)d_in[10];
    const float* ln2_s   = (const float*)d_in[11];
    const float* ln2_b   = (const float*)d_in[12];
    const float* w1      = (const float*)d_in[13];
    const float* b1      = (const float*)d_in[14];
    const float* w2      = (const float*)d_in[15];
    const float* b2      = (const float*)d_in[16];
    const float* lnf_s   = (const float*)d_in[17];
    const float* lnf_b   = (const float*)d_in[18];
    const float* head_w  = (const float*)d_in[19];
    const float* head_b  = (const float*)d_in[20];
    float* out = (float*)d_out;

    float *ph;
    uint8_t *za, *hid, *wt;
    cudaGetSymbolAddress((void**)&ph,  g_h);
    cudaGetSymbolAddress((void**)&za,  g_za);
    cudaGetSymbolAddress((void**)&hid, g_hid);
    cudaGetSymbolAddress((void**)&wt,  g_wt);

    cudaFuncSetAttribute(tgemm_kernel<2>, cudaFuncAttributeMaxDynamicSharedMemorySize, GEMM_SMEM);
    cudaFuncSetAttribute(tgemm_kernel<4>, cudaFuncAttributeMaxDynamicSharedMemorySize, GEMM_SMEM);
    cudaFuncSetAttribute(tgemm_kernel<5>, cudaFuncAttributeMaxDynamicSharedMemorySize, GEMM_SMEM);
    cudaFuncSetAttribute(tgemm_kernel<6>, cudaFuncAttributeMaxDynamicSharedMemorySize, GEMM_SMEM);

    const int NT = NTOK / 128;   // 49

    // weights -> chunked fp16
    convert_w_kernel<<<dim3(144, 1 + 4*DD), 256>>>(patch_w, w_in, w_g, w1, w2);

    // patch embed
    im2col_kernel<<<NTOK, 256>>>(x);
    tgemm_kernel<4><<<dim3(CC/128, NT), 256, GEMM_SMEM>>>(
        za, wt + (size_t)OFF_PATCH*2, patch_b, ph, KI2C, CC, pos);

    for (int d = 0; d < DD; d++) {
        size_t wb = ((size_t)OFF_BLK0 + (size_t)d * PER_BLK) * 2;
        ln_kernel<true><<<NTOK/16, 256>>>(ln1_s + d*CC, ln1_b + d*CC);
        tgemm_kernel<5><<<dim3((2*CC)/128, NT), 256, GEMM_SMEM>>>(
            za, wt + wb, b_in + d*CC, nullptr, CC, 2*CC, b_g + d*CC);
        recur_kernel<<<BATCH * (CC/16), 196>>>(k_dw + (size_t)d*9*CC);
        ln_kernel<true><<<NTOK/16, 256>>>(ln2_s + d*CC, ln2_b + d*CC);
        tgemm_kernel<2><<<dim3(HIDN/128, NT), 256, GEMM_SMEM>>>(
            za, wt + wb + (size_t)2*LEN_CXC*2, b1 + d*HIDN, nullptr, CC, HIDN, nullptr);
        tgemm_kernel<6><<<dim3(CC/128, NT, 2), 256, GEMM_SMEM>>>(
            hid, wt + wb + (size_t)(2*LEN_CXC + LEN_W1)*2, b2 + d*CC, ph, HIDN, CC, nullptr);
    }

    ln_kernel<false><<<NTOK/16, 256>>>(lnf_s, lnf_b);
    maxpool_kernel<<<BATCH, CC>>>();
    head_kernel<<<(BATCH*NCLS + 255) / 256, 256>>>(head_w, head_b, out);
}